// round 7
// baseline (speedup 1.0000x reference)
#include <cuda_runtime.h>
#include <cuda_bf16.h>
#include <math.h>
#include <stdint.h>

#define KST 3
#define NN 30000
#define NE 300000
#define FIN 256
#define FHID 256
#define FOUT 64
#define KP1 (FIN / 2)    // 128
#define KPH (FHID / 2)   // 128
#define KPO (FOUT / 2)   // 32

// ---------------- scratch (device globals) ------------------------------------
__device__ __align__(16) uint32_t g_XH[NN * KP1], g_XL[NN * KP1];
__device__ __align__(16) uint32_t g_H0H[KST * NN * KPH], g_H0L[KST * NN * KPH];
__device__ __align__(16) uint32_t g_H1H[KST * NN * KPH], g_H1L[KST * NN * KPH];
__device__ __align__(16) uint32_t g_R1H[KST * NN * KPH], g_R1L[KST * NN * KPH];
__device__ __align__(16) uint32_t g_HMH[NN * KPH], g_HML[NN * KPH];
__device__ __align__(16) uint32_t g_G0H[KST * NN * KPO], g_G0L[KST * NN * KPO];
__device__ __align__(16) uint32_t g_G1H[KST * NN * KPO], g_G1L[KST * NN * KPO];
__device__ __align__(16) uint32_t g_R2H[KST * NN * KPO], g_R2L[KST * NN * KPO];
__device__ __align__(16) uint32_t g_W1CH[KST * 512 * KP1], g_W1CL[KST * 512 * KP1];
__device__ __align__(16) uint32_t g_W1H[KST * 256 * KPH], g_W1L[KST * 256 * KPH];
__device__ __align__(16) uint32_t g_W2CH[KST * 128 * KPH], g_W2CL[KST * 128 * KPH];
__device__ __align__(16) uint32_t g_W2H[KST * 64 * KPO], g_W2L[KST * 64 * KPO];
__device__ float g_dis[NN];
__device__ int g_cnt[NN];
__device__ int g_rowptr[NN + 1];
__device__ int g_cursor[NN];
__device__ int g_src[NE];
__device__ float g_nrm[NE];
__device__ int g_is64;

// ---------------- helpers -----------------------------------------------------
__device__ __forceinline__ uint32_t split_pack(float v0, float v1, uint32_t& lo_out) {
    __nv_bfloat16 h0 = __float2bfloat16(v0);
    __nv_bfloat16 h1 = __float2bfloat16(v1);
    float r0 = v0 - __bfloat162float(h0);
    float r1 = v1 - __bfloat162float(h1);
    __nv_bfloat16 l0 = __float2bfloat16(r0);
    __nv_bfloat16 l1 = __float2bfloat16(r1);
    lo_out = ((uint32_t)__bfloat16_as_ushort(l1) << 16) | __bfloat16_as_ushort(l0);
    return ((uint32_t)__bfloat16_as_ushort(h1) << 16) | __bfloat16_as_ushort(h0);
}

__device__ __forceinline__ float2 bf2f(uint32_t u) {
    __nv_bfloat162 b = *reinterpret_cast<__nv_bfloat162*>(&u);
    return __bfloat1622float2(b);
}

__device__ __forceinline__ void mma_bf16(float* c, const uint32_t* a, const uint32_t* bb) {
    asm volatile(
        "mma.sync.aligned.m16n8k16.row.col.f32.bf16.bf16.f32 "
        "{%0,%1,%2,%3}, {%4,%5,%6,%7}, {%8,%9}, {%0,%1,%2,%3};\n"
        : "+f"(c[0]), "+f"(c[1]), "+f"(c[2]), "+f"(c[3])
        : "r"(a[0]), "r"(a[1]), "r"(a[2]), "r"(a[3]), "r"(bb[0]), "r"(bb[1]));
}

__device__ __forceinline__ void ldsm4(uint32_t* r, uint32_t addr) {
    asm volatile("ldmatrix.sync.aligned.m8n8.x4.shared.b16 {%0,%1,%2,%3}, [%4];"
                 : "=r"(r[0]), "=r"(r[1]), "=r"(r[2]), "=r"(r[3])
                 : "r"(addr));
}

// ---------------- input splitting ---------------------------------------------
__global__ void split_x_kernel(const float* __restrict__ x) {
    long i = blockIdx.x * 256L + threadIdx.x;
    if (i < (long)NN * KP1) {
        float2 v = *(const float2*)(x + 2 * i);
        uint32_t lo;
        uint32_t hi = split_pack(v.x, v.y, lo);
        g_XH[i] = hi;
        g_XL[i] = lo;
    }
}

__device__ __forceinline__ void wsplit(const float* __restrict__ W, uint32_t* oh,
                                       uint32_t* ol, int Kd, int N, int nOff,
                                       int outN, long idx) {
    int Kp = Kd / 2;
    int k = (int)(idx / ((long)N * Kp));
    int rem = (int)(idx % ((long)N * Kp));
    int n = rem / Kp;
    int kp = rem % Kp;
    const float* Wk = W + (long)k * Kd * N;
    float v0 = Wk[(long)(2 * kp) * N + n];
    float v1 = Wk[(long)(2 * kp + 1) * N + n];
    uint32_t lo;
    uint32_t hi = split_pack(v0, v1, lo);
    long o = ((long)k * outN + nOff + n) * Kp + kp;
    oh[o] = hi;
    ol[o] = lo;
}

#define CNT_A (KST * 256 * 128)
#define CNT_B (KST * 64 * 128)
#define CNT_C (KST * 64 * 32)

__global__ void split_weights_kernel(const float* iw1, const float* rw1,
                                     const float* w1, const float* iw2,
                                     const float* rw2, const float* w2) {
    long id = blockIdx.x * 256L + threadIdx.x;
    if (id < CNT_A) { wsplit(iw1, g_W1CH, g_W1CL, 256, 256, 0, 512, id); return; }
    id -= CNT_A;
    if (id < CNT_A) { wsplit(rw1, g_W1CH, g_W1CL, 256, 256, 256, 512, id); return; }
    id -= CNT_A;
    if (id < CNT_A) { wsplit(w1, g_W1H, g_W1L, 256, 256, 0, 256, id); return; }
    id -= CNT_A;
    if (id < CNT_B) { wsplit(iw2, g_W2CH, g_W2CL, 256, 64, 0, 128, id); return; }
    id -= CNT_B;
    if (id < CNT_B) { wsplit(rw2, g_W2CH, g_W2CL, 256, 64, 64, 128, id); return; }
    id -= CNT_B;
    if (id < CNT_C) { wsplit(w2, g_W2H, g_W2L, 64, 64, 0, 64, id); }
}

// ---------------- dtype sniff / CSR -------------------------------------------
__global__ void sniff_kernel(const int* __restrict__ ei_raw) {
    if (threadIdx.x == 0 && blockIdx.x == 0) {
        int all_zero = 1;
        for (int i = 0; i < 128; i++)
            if (ei_raw[2 * i + 1] != 0) { all_zero = 0; break; }
        g_is64 = all_zero;
    }
}

__device__ __forceinline__ int load_idx(const void* ei, long pos) {
    if (g_is64) return (int)((const long long*)ei)[pos];
    return ((const int*)ei)[pos];
}

__global__ void zero_cnt_kernel() {
    int i = blockIdx.x * blockDim.x + threadIdx.x;
    if (i < NN) g_cnt[i] = 0;
}

__global__ void count_deg_kernel(const void* __restrict__ ei) {
    int e = blockIdx.x * blockDim.x + threadIdx.x;
    if (e < NE) {
        int c = load_idx(ei, (long)NE + e);
        if (c >= 0 && c < NN) atomicAdd(&g_cnt[c], 1);
    }
}

__global__ void dis_kernel() {
    int i = blockIdx.x * blockDim.x + threadIdx.x;
    if (i < NN) {
        int c = g_cnt[i];
        g_dis[i] = (c > 0) ? rsqrtf((float)c) : 0.0f;
    }
}

__global__ void scan_kernel() {
    __shared__ int sh[1024];
    __shared__ int s_off;
    if (threadIdx.x == 0) s_off = 0;
    __syncthreads();
    for (int base = 0; base < NN; base += 1024) {
        int i = base + threadIdx.x;
        int v = (i < NN) ? g_cnt[i] : 0;
        sh[threadIdx.x] = v;
        __syncthreads();
        for (int d = 1; d < 1024; d <<= 1) {
            int t = (threadIdx.x >= (unsigned)d) ? sh[threadIdx.x - d] : 0;
            __syncthreads();
            sh[threadIdx.x] += t;
            __syncthreads();
        }
        int incl = sh[threadIdx.x];
        int off = s_off;
        __syncthreads();
        if (i < NN) {
            int ex = off + incl - v;
            g_rowptr[i] = ex;
            g_cursor[i] = ex;
        }
        if (threadIdx.x == 1023) s_off = off + incl;
        __syncthreads();
    }
    if (threadIdx.x == 0) g_rowptr[NN] = s_off;
}

__global__ void fill_csr_kernel(const void* __restrict__ ei) {
    int e = blockIdx.x * blockDim.x + threadIdx.x;
    if (e < NE) {
        int r = load_idx(ei, e);
        int c = load_idx(ei, (long)NE + e);
        if (r >= 0 && r < NN && c >= 0 && c < NN) {
            int pos = atomicAdd(&g_cursor[c], 1);
            if (pos >= 0 && pos < NE) {
                g_src[pos] = r;
                g_nrm[pos] = g_dis[r] * g_dis[c];
            }
        }
    }
}

// ---------------- pipelined split-bf16 tensor-core GEMM (BM=256) ---------------
// A: split-bf16 [M][Kp] u32 (hi/lo), B: pre-transposed split [Ntot][Kp] u32.
// Dual-output epilogue. BM=256, BN=64, BK=32 (16 pairs), 2-stage cp.async,
// ldmatrix.x4 fragment loads. 4x2 warps, warp tile 64x32.
#define APITCH 20
#define A_PLANE_B (256 * APITCH * 4)   // 20480 B
#define B_PLANE_B (64 * APITCH * 4)    // 5120 B
#define B_OFF_B (2 * 2 * A_PLANE_B)    // 81920
#define GSMEM (2 * 2 * (A_PLANE_B + B_PLANE_B))  // 102400

__global__ __launch_bounds__(256, 2)
void bgemm2(const uint32_t* __restrict__ Ah, const uint32_t* __restrict__ Al, long sA,
            const uint32_t* __restrict__ Bh, const uint32_t* __restrict__ Bl, long sB,
            const float* __restrict__ bias, long sBias,
            uint32_t* __restrict__ C0h, uint32_t* __restrict__ C0l, long sC0,
            uint32_t* __restrict__ C1h, uint32_t* __restrict__ C1l, long sC1,
            int M, int Ntot, int N1, int Kd) {
    extern __shared__ uint32_t smem[];
    uint32_t smem_u = (uint32_t)__cvta_generic_to_shared(smem);
    int Kp = Kd >> 1;
    int b = blockIdx.z;
    const uint32_t* Abh = Ah + (long)b * sA;
    const uint32_t* Abl = Al + (long)b * sA;
    const uint32_t* Bbh = Bh + (long)b * sB;
    const uint32_t* Bbl = Bl + (long)b * sB;
    int bm = blockIdx.y * 256, bn = blockIdx.x * 64;
    int tid = threadIdx.x, warp = tid >> 5, lane = tid & 31;
    int g = lane >> 2, t = lane & 3;
    int wm = warp >> 1, wn = warp & 1;  // wm 0..3 (64 rows), wn 0..1 (32 cols)

    int rowA = ((lane >> 3) & 1) * 8 + (lane & 7);
    int segA = (lane >> 4) * 4;
    int rowB = ((lane >> 4) & 1) * 8 + (lane & 7);
    int segB = ((lane >> 3) & 1) * 4;

    auto issue = [&](int kt, int buf) {
        int kp0 = kt * 16;
#pragma unroll
        for (int i = 0; i < 8; i++) {  // A: 2048 16B chunks (256 rows x 4 segs x 2 splits)
            int ch = tid + i * 256;
            int s = ch >> 10, rem = ch & 1023, row = rem >> 2, seg = rem & 3;
            int gm = bm + row;
            if (gm >= M) gm = M - 1;
            const uint32_t* src = (s ? Abl : Abh) + (long)gm * Kp + kp0 + seg * 4;
            uint32_t dst = smem_u + (buf * 2 + s) * A_PLANE_B + (row * APITCH + seg * 4) * 4;
            asm volatile("cp.async.cg.shared.global [%0], [%1], 16;" ::"r"(dst), "l"(src));
        }
#pragma unroll
        for (int i = 0; i < 2; i++) {  // B: 512 chunks
            int ch = tid + i * 256;
            int s = ch >> 8, rem = ch & 255, row = rem >> 2, seg = rem & 3;
            const uint32_t* src = (s ? Bbl : Bbh) + (long)(bn + row) * Kp + kp0 + seg * 4;
            uint32_t dst =
                smem_u + B_OFF_B + (buf * 2 + s) * B_PLANE_B + (row * APITCH + seg * 4) * 4;
            asm volatile("cp.async.cg.shared.global [%0], [%1], 16;" ::"r"(dst), "l"(src));
        }
        asm volatile("cp.async.commit_group;" ::: "memory");
    };

    float acc[4][4][4];
#pragma unroll
    for (int i = 0; i < 4; i++)
#pragma unroll
        for (int j = 0; j < 4; j++)
#pragma unroll
            for (int k = 0; k < 4; k++) acc[i][j][k] = 0.f;

    int NT = Kd / 32;
    issue(0, 0);
    for (int kt = 0; kt < NT; kt++) {
        int buf = kt & 1;
        if (kt + 1 < NT) {
            issue(kt + 1, (kt + 1) & 1);
            asm volatile("cp.async.wait_group 1;" ::: "memory");
        } else {
            asm volatile("cp.async.wait_group 0;" ::: "memory");
        }
        __syncthreads();
#pragma unroll
        for (int ks = 0; ks < 2; ks++) {
            int kp0 = ks * 8;
            uint32_t bf[2][4][2];
#pragma unroll
            for (int s = 0; s < 2; s++) {
                uint32_t bBase = smem_u + B_OFF_B + (buf * 2 + s) * B_PLANE_B;
#pragma unroll
                for (int np = 0; np < 2; np++) {
                    uint32_t addr =
                        bBase + ((wn * 32 + np * 16 + rowB) * APITCH + kp0 + segB) * 4;
                    ldsm4(&bf[s][np * 2][0], addr);
                }
            }
#pragma unroll
            for (int mt = 0; mt < 4; mt++) {
                uint32_t afh[4], afl[4];
                {
                    uint32_t aBaseH = smem_u + (buf * 2 + 0) * A_PLANE_B;
                    uint32_t aBaseL = smem_u + (buf * 2 + 1) * A_PLANE_B;
                    int mrow = wm * 64 + mt * 16 + rowA;
                    ldsm4(afh, aBaseH + (mrow * APITCH + kp0 + segA) * 4);
                    ldsm4(afl, aBaseL + (mrow * APITCH + kp0 + segA) * 4);
                }
#pragma unroll
                for (int nt = 0; nt < 4; nt++) {
                    mma_bf16(acc[mt][nt], afh, bf[0][nt]);  // hi*hi
                    mma_bf16(acc[mt][nt], afh, bf[1][nt]);  // hi*lo
                    mma_bf16(acc[mt][nt], afl, bf[0][nt]);  // lo*hi
                }
            }
        }
        __syncthreads();
    }

    // ---- epilogue: split-pack + dual-target store ----
    int row0 = bm + wm * 64;
    int col0 = bn + wn * 32;
#pragma unroll
    for (int nt = 0; nt < 4; nt++) {
        int c = col0 + nt * 8 + 2 * t;
        bool out1 = (c >= N1);
        float bx = 0.f, by = 0.f;
        uint32_t *Oh, *Ol;
        long pitch;
        int cc;
        if (out1) {
            if (bias) {
                bx = bias[b * sBias + (c - N1)];
                by = bias[b * sBias + (c - N1) + 1];
            }
            Oh = C1h + (long)b * sC1;
            Ol = C1l + (long)b * sC1;
            pitch = (Ntot - N1) >> 1;
            cc = (c - N1) >> 1;
        } else {
            Oh = C0h + (long)b * sC0;
            Ol = C0l + (long)b * sC0;
            pitch = N1 >> 1;
            cc = c >> 1;
        }
#pragma unroll
        for (int mt = 0; mt < 4; mt++) {
            int r = row0 + mt * 16 + g;
            if (r < M) {
                uint32_t lo, hi = split_pack(acc[mt][nt][0] + bx, acc[mt][nt][1] + by, lo);
                Oh[(long)r * pitch + cc] = hi;
                Ol[(long)r * pitch + cc] = lo;
            }
            if (r + 8 < M) {
                uint32_t lo, hi = split_pack(acc[mt][nt][2] + bx, acc[mt][nt][3] + by, lo);
                Oh[(long)(r + 8) * pitch + cc] = hi;
                Ol[(long)(r + 8) * pitch + cc] = lo;
            }
        }
    }
}

// ---------------- propagation (CSR gather on split-bf16) ------------------------
template <int F, bool RELU>
__global__ void prop_kernel(const uint32_t* __restrict__ Hh,
                            const uint32_t* __restrict__ Hl,
                            const uint32_t* __restrict__ Rh,
                            const uint32_t* __restrict__ Rl,
                            uint32_t* __restrict__ Oh, uint32_t* __restrict__ Ol) {
    constexpr int LANES = F / 4;
    constexpr int NPB = 256 / LANES;
    constexpr int PITCH = F / 2;
    int lane = threadIdx.x % LANES;
    int local = threadIdx.x / LANES;
    int n = blockIdx.x * NPB + local;
    int k = blockIdx.y;
    if (n >= NN) return;
    long base = (long)k * NN * PITCH;
    const uint32_t* Hkh = Hh + base;
    const uint32_t* Hkl = Hl + base;
    int e0 = g_rowptr[n], e1 = g_rowptr[n + 1];
    float4 acc = make_float4(0.f, 0.f, 0.f, 0.f);
    for (int e = e0; e < e1; e++) {
        int s = g_src[e];
        float w = g_nrm[e];
        uint2 hh = *(const uint2*)(Hkh + (long)s * PITCH + lane * 2);
        uint2 hl = *(const uint2*)(Hkl + (long)s * PITCH + lane * 2);
        float2 v0 = bf2f(hh.x), l0 = bf2f(hl.x);
        float2 v1 = bf2f(hh.y), l1 = bf2f(hl.y);
        acc.x += w * (v0.x + l0.x);
        acc.y += w * (v0.y + l0.y);
        acc.z += w * (v1.x + l1.x);
        acc.w += w * (v1.y + l1.y);
    }
    long off = base + (long)n * PITCH + lane * 2;
    uint2 rh = *(const uint2*)(Rh + off);
    uint2 rl = *(const uint2*)(Rl + off);
    float2 r0 = bf2f(rh.x), q0 = bf2f(rl.x);
    float2 r1 = bf2f(rh.y), q1 = bf2f(rl.y);
    acc.x += r0.x + q0.x;
    acc.y += r0.y + q0.y;
    acc.z += r1.x + q1.x;
    acc.w += r1.y + q1.y;
    if (RELU) {
        acc.x = fmaxf(acc.x, 0.f);
        acc.y = fmaxf(acc.y, 0.f);
        acc.z = fmaxf(acc.z, 0.f);
        acc.w = fmaxf(acc.w, 0.f);
    }
    uint32_t lo0, hi0 = split_pack(acc.x, acc.y, lo0);
    uint32_t lo1, hi1 = split_pack(acc.z, acc.w, lo1);
    *(uint2*)(Oh + off) = make_uint2(hi0, hi1);
    *(uint2*)(Ol + off) = make_uint2(lo0, lo1);
}

// ---------------- mean over stacks ---------------------------------------------
__global__ void mean_kernel() {
    long i = blockIdx.x * 256L + threadIdx.x;
    const long st = (long)NN * KPH;
    if (i < st) {
        float2 s = make_float2(0.f, 0.f);
#pragma unroll
        for (int k = 0; k < KST; k++) {
            float2 h = bf2f(g_H1H[i + k * st]);
            float2 l = bf2f(g_H1L[i + k * st]);
            s.x += h.x + l.x;
            s.y += h.y + l.y;
        }
        s.x *= (1.0f / 3.0f);
        s.y *= (1.0f / 3.0f);
        uint32_t lo, hi = split_pack(s.x, s.y, lo);
        g_HMH[i] = hi;
        g_HML[i] = lo;
    }
}

// ---------------- final: mean over stacks + log_softmax -------------------------
__global__ void final_kernel(float* __restrict__ out) {
    int n = blockIdx.x;
    int f = threadIdx.x;  // 64 threads
    const long st = (long)NN * KPO;
    long p = (long)n * KPO + (f >> 1);
    float v = 0.f;
#pragma unroll
    for (int k = 0; k < KST; k++) {
        float2 h = bf2f(g_G1H[p + k * st]);
        float2 l = bf2f(g_G1L[p + k * st]);
        v += (f & 1) ? (h.y + l.y) : (h.x + l.x);
    }
    v *= (1.0f / 3.0f);
    float m = v;
#pragma unroll
    for (int d = 16; d; d >>= 1) m = fmaxf(m, __shfl_xor_sync(0xffffffffu, m, d));
    __shared__ float sm[2], ss[2];
    int w = threadIdx.x >> 5;
    if ((threadIdx.x & 31) == 0) sm[w] = m;
    __syncthreads();
    m = fmaxf(sm[0], sm[1]);
    float e = expf(v - m);
    float s = e;
#pragma unroll
    for (int d = 16; d; d >>= 1) s += __shfl_xor_sync(0xffffffffu, s, d);
    if ((threadIdx.x & 31) == 0) ss[w] = s;
    __syncthreads();
    s = ss[0] + ss[1];
    out[(long)n * FOUT + f] = v - m - logf(s);
}

// ---------------- launch ---------------------------------------------------------
extern "C" void kernel_launch(void* const* d_in, const int* in_sizes, int n_in,
                              void* d_out, int out_size) {
    const float* x = (const float*)d_in[0];
    const void* ei = d_in[1];
    const float* init_w1 = (const float*)d_in[2];
    const float* w1 = (const float*)d_in[3];
    const float* root_w1 = (const float*)d_in[4];
    const float* bias1 = (const float*)d_in[5];
    const float* init_w2 = (const float*)d_in[6];
    const float* w2 = (const float*)d_in[7];
    const float* root_w2 = (const float*)d_in[8];
    const float* bias2 = (const float*)d_in[9];
    float* out = (float*)d_out;

    static bool attr_set = false;
    if (!attr_set) {
        cudaFuncSetAttribute(bgemm2, cudaFuncAttributeMaxDynamicSharedMemorySize, GSMEM);
        attr_set = true;
    }

    uint32_t *XH, *XL, *H0H, *H0L, *H1H, *H1L, *R1H, *R1L, *HMH, *HML;
    uint32_t *G0H, *G0L, *G1H, *G1L, *R2H, *R2L;
    uint32_t *W1CH, *W1CL, *W1H, *W1L, *W2CH, *W2CL, *W2H, *W2L;
    cudaGetSymbolAddress((void**)&XH, g_XH);
    cudaGetSymbolAddress((void**)&XL, g_XL);
    cudaGetSymbolAddress((void**)&H0H, g_H0H);
    cudaGetSymbolAddress((void**)&H0L, g_H0L);
    cudaGetSymbolAddress((void**)&H1H, g_H1H);
    cudaGetSymbolAddress((void**)&H1L, g_H1L);
    cudaGetSymbolAddress((void**)&R1H, g_R1H);
    cudaGetSymbolAddress((void**)&R1L, g_R1L);
    cudaGetSymbolAddress((void**)&HMH, g_HMH);
    cudaGetSymbolAddress((void**)&HML, g_HML);
    cudaGetSymbolAddress((void**)&G0H, g_G0H);
    cudaGetSymbolAddress((void**)&G0L, g_G0L);
    cudaGetSymbolAddress((void**)&G1H, g_G1H);
    cudaGetSymbolAddress((void**)&G1L, g_G1L);
    cudaGetSymbolAddress((void**)&R2H, g_R2H);
    cudaGetSymbolAddress((void**)&R2L, g_R2L);
    cudaGetSymbolAddress((void**)&W1CH, g_W1CH);
    cudaGetSymbolAddress((void**)&W1CL, g_W1CL);
    cudaGetSymbolAddress((void**)&W1H, g_W1H);
    cudaGetSymbolAddress((void**)&W1L, g_W1L);
    cudaGetSymbolAddress((void**)&W2CH, g_W2CH);
    cudaGetSymbolAddress((void**)&W2CL, g_W2CL);
    cudaGetSymbolAddress((void**)&W2H, g_W2H);
    cudaGetSymbolAddress((void**)&W2L, g_W2L);

    const int MY = (NN + 255) / 256;  // 118

    // 0-2: prep
    split_x_kernel<<<(NN * KP1 + 255) / 256, 256>>>(x);
    split_weights_kernel<<<(3 * CNT_A + 2 * CNT_B + CNT_C + 255) / 256, 256>>>(
        init_w1, root_w1, w1, init_w2, root_w2, w2);
    zero_cnt_kernel<<<(NN + 255) / 256, 256>>>();
    // 3: fused conv1 GEMM — ncu capture slot
    dim3 gc1(512 / 64, MY, KST);
    bgemm2<<<gc1, 256, GSMEM>>>(XH, XL, 0, W1CH, W1CL, (long)512 * KP1, bias1, FHID,
                                H0H, H0L, (long)NN * KPH, R1H, R1L, (long)NN * KPH,
                                NN, 512, 256, FIN);
    // 4-8: CSR build
    sniff_kernel<<<1, 32>>>((const int*)ei);
    count_deg_kernel<<<(NE + 255) / 256, 256>>>(ei);
    dis_kernel<<<(NN + 255) / 256, 256>>>();
    scan_kernel<<<1, 1024>>>();
    fill_csr_kernel<<<(NE + 255) / 256, 256>>>(ei);

    // conv1 body
    dim3 gp1((NN + 3) / 4, KST);
    prop_kernel<FHID, true><<<gp1, 256>>>(H0H, H0L, R1H, R1L, H1H, H1L);
    dim3 gw1(256 / 64, MY, KST);
    bgemm2<<<gw1, 256, GSMEM>>>(H1H, H1L, (long)NN * KPH, W1H, W1L, (long)256 * KPH,
                                nullptr, 0, H0H, H0L, (long)NN * KPH, nullptr, nullptr,
                                0, NN, 256, 256, FHID);
    prop_kernel<FHID, true><<<gp1, 256>>>(H0H, H0L, R1H, R1L, H1H, H1L);
    mean_kernel<<<(NN * KPH + 255) / 256, 256>>>();

    // conv2
    dim3 gc2(128 / 64, MY, KST);
    bgemm2<<<gc2, 256, GSMEM>>>(HMH, HML, 0, W2CH, W2CL, (long)128 * KPH, bias2, FOUT,
                                G0H, G0L, (long)NN * KPO, R2H, R2L, (long)NN * KPO,
                                NN, 128, 64, FHID);
    dim3 gp2((NN + 15) / 16, KST);
    prop_kernel<FOUT, false><<<gp2, 256>>>(G0H, G0L, R2H, R2L, G1H, G1L);
    dim3 gw2(1, MY, KST);
    bgemm2<<<gw2, 256, GSMEM>>>(G1H, G1L, (long)NN * KPO, W2H, W2L, (long)64 * KPO,
                                nullptr, 0, G0H, G0L, (long)NN * KPO, nullptr, nullptr,
                                0, NN, 64, 64, FOUT);
    prop_kernel<FOUT, false><<<gp2, 256>>>(G0H, G0L, R2H, R2L, G1H, G1L);

    final_kernel<<<NN, FOUT>>>(out);
}

// round 8
// speedup vs baseline: 1.0012x; 1.0012x over previous
#include <cuda_runtime.h>
#include <cuda_bf16.h>
#include <math.h>
#include <stdint.h>

#define KST 3
#define NN 30000
#define NE 300000
#define FIN 256
#define FHID 256
#define FOUT 64
#define KP1 (FIN / 2)    // 128
#define KPH (FHID / 2)   // 128
#define KPO (FOUT / 2)   // 32

// ---------------- scratch (device globals) ------------------------------------
__device__ __align__(16) uint32_t g_XH[NN * KP1], g_XL[NN * KP1];
__device__ __align__(16) uint32_t g_H0H[KST * NN * KPH], g_H0L[KST * NN * KPH];
__device__ __align__(16) uint32_t g_H1H[KST * NN * KPH], g_H1L[KST * NN * KPH];
__device__ __align__(16) uint32_t g_R1H[KST * NN * KPH], g_R1L[KST * NN * KPH];
__device__ __align__(16) uint32_t g_HMH[NN * KPH], g_HML[NN * KPH];
__device__ __align__(16) uint32_t g_G0H[KST * NN * KPO], g_G0L[KST * NN * KPO];
__device__ __align__(16) uint32_t g_G1H[KST * NN * KPO], g_G1L[KST * NN * KPO];
__device__ __align__(16) uint32_t g_R2H[KST * NN * KPO], g_R2L[KST * NN * KPO];
__device__ __align__(16) uint32_t g_W1CH[KST * 512 * KP1], g_W1CL[KST * 512 * KP1];
__device__ __align__(16) uint32_t g_W1H[KST * 256 * KPH], g_W1L[KST * 256 * KPH];
__device__ __align__(16) uint32_t g_W2CH[KST * 128 * KPH], g_W2CL[KST * 128 * KPH];
__device__ __align__(16) uint32_t g_W2H[KST * 64 * KPO], g_W2L[KST * 64 * KPO];
__device__ float g_dis[NN];
__device__ int g_cnt[NN];
__device__ int g_rowptr[NN + 1];
__device__ int g_cursor[NN];
__device__ int g_src[NE];
__device__ float g_nrm[NE];
__device__ int g_is64;

// ---------------- helpers -----------------------------------------------------
__device__ __forceinline__ uint32_t split_pack(float v0, float v1, uint32_t& lo_out) {
    __nv_bfloat16 h0 = __float2bfloat16(v0);
    __nv_bfloat16 h1 = __float2bfloat16(v1);
    float r0 = v0 - __bfloat162float(h0);
    float r1 = v1 - __bfloat162float(h1);
    __nv_bfloat16 l0 = __float2bfloat16(r0);
    __nv_bfloat16 l1 = __float2bfloat16(r1);
    lo_out = ((uint32_t)__bfloat16_as_ushort(l1) << 16) | __bfloat16_as_ushort(l0);
    return ((uint32_t)__bfloat16_as_ushort(h1) << 16) | __bfloat16_as_ushort(h0);
}

__device__ __forceinline__ float2 bf2f(uint32_t u) {
    __nv_bfloat162 b = *reinterpret_cast<__nv_bfloat162*>(&u);
    return __bfloat1622float2(b);
}

__device__ __forceinline__ void mma_bf16(float* c, const uint32_t* a, const uint32_t* bb) {
    asm volatile(
        "mma.sync.aligned.m16n8k16.row.col.f32.bf16.bf16.f32 "
        "{%0,%1,%2,%3}, {%4,%5,%6,%7}, {%8,%9}, {%0,%1,%2,%3};\n"
        : "+f"(c[0]), "+f"(c[1]), "+f"(c[2]), "+f"(c[3])
        : "r"(a[0]), "r"(a[1]), "r"(a[2]), "r"(a[3]), "r"(bb[0]), "r"(bb[1]));
}

__device__ __forceinline__ void ldsm4(uint32_t* r, uint32_t addr) {
    asm volatile("ldmatrix.sync.aligned.m8n8.x4.shared.b16 {%0,%1,%2,%3}, [%4];"
                 : "=r"(r[0]), "=r"(r[1]), "=r"(r[2]), "=r"(r[3])
                 : "r"(addr));
}

// ---------------- input splitting ---------------------------------------------
__global__ void split_x_kernel(const float* __restrict__ x) {
    long i = blockIdx.x * 256L + threadIdx.x;
    if (i < (long)NN * KP1) {
        float2 v = *(const float2*)(x + 2 * i);
        uint32_t lo;
        uint32_t hi = split_pack(v.x, v.y, lo);
        g_XH[i] = hi;
        g_XL[i] = lo;
    }
}

__device__ __forceinline__ void wsplit(const float* __restrict__ W, uint32_t* oh,
                                       uint32_t* ol, int Kd, int N, int nOff,
                                       int outN, long idx) {
    int Kp = Kd / 2;
    int k = (int)(idx / ((long)N * Kp));
    int rem = (int)(idx % ((long)N * Kp));
    int n = rem / Kp;
    int kp = rem % Kp;
    const float* Wk = W + (long)k * Kd * N;
    float v0 = Wk[(long)(2 * kp) * N + n];
    float v1 = Wk[(long)(2 * kp + 1) * N + n];
    uint32_t lo;
    uint32_t hi = split_pack(v0, v1, lo);
    long o = ((long)k * outN + nOff + n) * Kp + kp;
    oh[o] = hi;
    ol[o] = lo;
}

#define CNT_A (KST * 256 * 128)
#define CNT_B (KST * 64 * 128)
#define CNT_C (KST * 64 * 32)

__global__ void split_weights_kernel(const float* iw1, const float* rw1,
                                     const float* w1, const float* iw2,
                                     const float* rw2, const float* w2) {
    long id = blockIdx.x * 256L + threadIdx.x;
    if (id < CNT_A) { wsplit(iw1, g_W1CH, g_W1CL, 256, 256, 0, 512, id); return; }
    id -= CNT_A;
    if (id < CNT_A) { wsplit(rw1, g_W1CH, g_W1CL, 256, 256, 256, 512, id); return; }
    id -= CNT_A;
    if (id < CNT_A) { wsplit(w1, g_W1H, g_W1L, 256, 256, 0, 256, id); return; }
    id -= CNT_A;
    if (id < CNT_B) { wsplit(iw2, g_W2CH, g_W2CL, 256, 64, 0, 128, id); return; }
    id -= CNT_B;
    if (id < CNT_B) { wsplit(rw2, g_W2CH, g_W2CL, 256, 64, 64, 128, id); return; }
    id -= CNT_B;
    if (id < CNT_C) { wsplit(w2, g_W2H, g_W2L, 64, 64, 0, 64, id); }
}

// ---------------- dtype sniff / CSR -------------------------------------------
__global__ void sniff_kernel(const int* __restrict__ ei_raw) {
    if (threadIdx.x == 0 && blockIdx.x == 0) {
        int all_zero = 1;
        for (int i = 0; i < 128; i++)
            if (ei_raw[2 * i + 1] != 0) { all_zero = 0; break; }
        g_is64 = all_zero;
    }
}

__device__ __forceinline__ int load_idx(const void* ei, long pos) {
    if (g_is64) return (int)((const long long*)ei)[pos];
    return ((const int*)ei)[pos];
}

__global__ void zero_cnt_kernel() {
    int i = blockIdx.x * blockDim.x + threadIdx.x;
    if (i < NN) g_cnt[i] = 0;
}

__global__ void count_deg_kernel(const void* __restrict__ ei) {
    int e = blockIdx.x * blockDim.x + threadIdx.x;
    if (e < NE) {
        int c = load_idx(ei, (long)NE + e);
        if (c >= 0 && c < NN) atomicAdd(&g_cnt[c], 1);
    }
}

__global__ void dis_kernel() {
    int i = blockIdx.x * blockDim.x + threadIdx.x;
    if (i < NN) {
        int c = g_cnt[i];
        g_dis[i] = (c > 0) ? rsqrtf((float)c) : 0.0f;
    }
}

__global__ void scan_kernel() {
    __shared__ int sh[1024];
    __shared__ int s_off;
    if (threadIdx.x == 0) s_off = 0;
    __syncthreads();
    for (int base = 0; base < NN; base += 1024) {
        int i = base + threadIdx.x;
        int v = (i < NN) ? g_cnt[i] : 0;
        sh[threadIdx.x] = v;
        __syncthreads();
        for (int d = 1; d < 1024; d <<= 1) {
            int t = (threadIdx.x >= (unsigned)d) ? sh[threadIdx.x - d] : 0;
            __syncthreads();
            sh[threadIdx.x] += t;
            __syncthreads();
        }
        int incl = sh[threadIdx.x];
        int off = s_off;
        __syncthreads();
        if (i < NN) {
            int ex = off + incl - v;
            g_rowptr[i] = ex;
            g_cursor[i] = ex;
        }
        if (threadIdx.x == 1023) s_off = off + incl;
        __syncthreads();
    }
    if (threadIdx.x == 0) g_rowptr[NN] = s_off;
}

__global__ void fill_csr_kernel(const void* __restrict__ ei) {
    int e = blockIdx.x * blockDim.x + threadIdx.x;
    if (e < NE) {
        int r = load_idx(ei, e);
        int c = load_idx(ei, (long)NE + e);
        if (r >= 0 && r < NN && c >= 0 && c < NN) {
            int pos = atomicAdd(&g_cursor[c], 1);
            if (pos >= 0 && pos < NE) {
                g_src[pos] = r;
                g_nrm[pos] = g_dis[r] * g_dis[c];
            }
        }
    }
}

// ---------------- pipelined split-bf16 tensor-core GEMM (3-stage) --------------
// A: split-bf16 [M][Kp] u32 (hi/lo), B: pre-transposed split [Ntot][Kp] u32.
// Dual-output epilogue. BM=128, BN=64, BK=32 (16 pairs), 3-stage cp.async,
// single __syncthreads per k-tile, ldmatrix.x4 fragment loads (pitch 80B).
#define APITCH 20
#define A_PLANE_B (128 * APITCH * 4)   // 10240 B
#define B_PLANE_B (64 * APITCH * 4)    // 5120 B
#define NSTAGE 3
#define B_OFF_B (NSTAGE * 2 * A_PLANE_B)  // 61440
#define GSMEM (NSTAGE * 2 * (A_PLANE_B + B_PLANE_B))  // 92160

__global__ __launch_bounds__(256, 2)
void bgemm2(const uint32_t* __restrict__ Ah, const uint32_t* __restrict__ Al, long sA,
            const uint32_t* __restrict__ Bh, const uint32_t* __restrict__ Bl, long sB,
            const float* __restrict__ bias, long sBias,
            uint32_t* __restrict__ C0h, uint32_t* __restrict__ C0l, long sC0,
            uint32_t* __restrict__ C1h, uint32_t* __restrict__ C1l, long sC1,
            int M, int Ntot, int N1, int Kd) {
    extern __shared__ uint32_t smem[];
    uint32_t smem_u = (uint32_t)__cvta_generic_to_shared(smem);
    int Kp = Kd >> 1;
    int b = blockIdx.z;
    const uint32_t* Abh = Ah + (long)b * sA;
    const uint32_t* Abl = Al + (long)b * sA;
    const uint32_t* Bbh = Bh + (long)b * sB;
    const uint32_t* Bbl = Bl + (long)b * sB;
    int bm = blockIdx.y * 128, bn = blockIdx.x * 64;
    int tid = threadIdx.x, warp = tid >> 5, lane = tid & 31;
    int g = lane >> 2, t = lane & 3;
    int wm = warp >> 1, wn = warp & 1;

    int rowA = ((lane >> 3) & 1) * 8 + (lane & 7);
    int segA = (lane >> 4) * 4;
    int rowB = ((lane >> 4) & 1) * 8 + (lane & 7);
    int segB = ((lane >> 3) & 1) * 4;

    auto issue = [&](int kt) {
        int buf = kt % NSTAGE;
        int kp0 = kt * 16;
#pragma unroll
        for (int i = 0; i < 4; i++) {  // A: 1024 16B chunks
            int ch = tid + i * 256;
            int s = ch >> 9, rem = ch & 511, row = rem >> 2, seg = rem & 3;
            int gm = bm + row;
            if (gm >= M) gm = M - 1;
            const uint32_t* src = (s ? Abl : Abh) + (long)gm * Kp + kp0 + seg * 4;
            uint32_t dst = smem_u + (buf * 2 + s) * A_PLANE_B + (row * APITCH + seg * 4) * 4;
            asm volatile("cp.async.cg.shared.global [%0], [%1], 16;" ::"r"(dst), "l"(src));
        }
#pragma unroll
        for (int i = 0; i < 2; i++) {  // B: 512 chunks
            int ch = tid + i * 256;
            int s = ch >> 8, rem = ch & 255, row = rem >> 2, seg = rem & 3;
            const uint32_t* src = (s ? Bbl : Bbh) + (long)(bn + row) * Kp + kp0 + seg * 4;
            uint32_t dst =
                smem_u + B_OFF_B + (buf * 2 + s) * B_PLANE_B + (row * APITCH + seg * 4) * 4;
            asm volatile("cp.async.cg.shared.global [%0], [%1], 16;" ::"r"(dst), "l"(src));
        }
        asm volatile("cp.async.commit_group;" ::: "memory");
    };

    float acc[2][4][4];
#pragma unroll
    for (int i = 0; i < 2; i++)
#pragma unroll
        for (int j = 0; j < 4; j++)
#pragma unroll
            for (int k = 0; k < 4; k++) acc[i][j][k] = 0.f;

    int NT = Kd / 32;
    issue(0);
    if (NT > 1) issue(1);
    for (int kt = 0; kt < NT; kt++) {
        int buf = kt % NSTAGE;
        if (kt + 1 < NT) {
            asm volatile("cp.async.wait_group 1;" ::: "memory");
        } else {
            asm volatile("cp.async.wait_group 0;" ::: "memory");
        }
        __syncthreads();
        // stage (kt+2)%3 == (kt-1)%3 is free: every warp past this sync has
        // finished compute(kt-1) in program order.
        if (kt + 2 < NT) issue(kt + 2);
#pragma unroll
        for (int ks = 0; ks < 2; ks++) {
            int kp0 = ks * 8;
            uint32_t af[2][2][4], bf[2][4][2];
#pragma unroll
            for (int s = 0; s < 2; s++) {
                uint32_t aBase = smem_u + (buf * 2 + s) * A_PLANE_B;
#pragma unroll
                for (int mt = 0; mt < 2; mt++) {
                    uint32_t addr =
                        aBase + ((wm * 32 + mt * 16 + rowA) * APITCH + kp0 + segA) * 4;
                    ldsm4(af[s][mt], addr);
                }
            }
#pragma unroll
            for (int s = 0; s < 2; s++) {
                uint32_t bBase = smem_u + B_OFF_B + (buf * 2 + s) * B_PLANE_B;
#pragma unroll
                for (int np = 0; np < 2; np++) {
                    uint32_t addr =
                        bBase + ((wn * 32 + np * 16 + rowB) * APITCH + kp0 + segB) * 4;
                    ldsm4(&bf[s][np * 2][0], addr);
                }
            }
#pragma unroll
            for (int mt = 0; mt < 2; mt++)
#pragma unroll
                for (int nt = 0; nt < 4; nt++) {
                    mma_bf16(acc[mt][nt], af[0][mt], bf[0][nt]);  // hi*hi
                    mma_bf16(acc[mt][nt], af[0][mt], bf[1][nt]);  // hi*lo
                    mma_bf16(acc[mt][nt], af[1][mt], bf[0][nt]);  // lo*hi
                }
        }
    }

    // ---- epilogue: split-pack + dual-target store ----
    int row0 = bm + wm * 32;
    int col0 = bn + wn * 32;
#pragma unroll
    for (int nt = 0; nt < 4; nt++) {
        int c = col0 + nt * 8 + 2 * t;
        bool out1 = (c >= N1);
        float bx = 0.f, by = 0.f;
        uint32_t *Oh, *Ol;
        long pitch;
        int cc;
        if (out1) {
            if (bias) {
                bx = bias[b * sBias + (c - N1)];
                by = bias[b * sBias + (c - N1) + 1];
            }
            Oh = C1h + (long)b * sC1;
            Ol = C1l + (long)b * sC1;
            pitch = (Ntot - N1) >> 1;
            cc = (c - N1) >> 1;
        } else {
            Oh = C0h + (long)b * sC0;
            Ol = C0l + (long)b * sC0;
            pitch = N1 >> 1;
            cc = c >> 1;
        }
#pragma unroll
        for (int mt = 0; mt < 2; mt++) {
            int r = row0 + mt * 16 + g;
            if (r < M) {
                uint32_t lo, hi = split_pack(acc[mt][nt][0] + bx, acc[mt][nt][1] + by, lo);
                Oh[(long)r * pitch + cc] = hi;
                Ol[(long)r * pitch + cc] = lo;
            }
            if (r + 8 < M) {
                uint32_t lo, hi = split_pack(acc[mt][nt][2] + bx, acc[mt][nt][3] + by, lo);
                Oh[(long)(r + 8) * pitch + cc] = hi;
                Ol[(long)(r + 8) * pitch + cc] = lo;
            }
        }
    }
}

// ---------------- propagation (CSR gather on split-bf16) ------------------------
template <int F, bool RELU>
__global__ void prop_kernel(const uint32_t* __restrict__ Hh,
                            const uint32_t* __restrict__ Hl,
                            const uint32_t* __restrict__ Rh,
                            const uint32_t* __restrict__ Rl,
                            uint32_t* __restrict__ Oh, uint32_t* __restrict__ Ol) {
    constexpr int LANES = F / 4;
    constexpr int NPB = 256 / LANES;
    constexpr int PITCH = F / 2;
    int lane = threadIdx.x % LANES;
    int local = threadIdx.x / LANES;
    int n = blockIdx.x * NPB + local;
    int k = blockIdx.y;
    if (n >= NN) return;
    long base = (long)k * NN * PITCH;
    const uint32_t* Hkh = Hh + base;
    const uint32_t* Hkl = Hl + base;
    int e0 = g_rowptr[n], e1 = g_rowptr[n + 1];
    float4 acc = make_float4(0.f, 0.f, 0.f, 0.f);
    for (int e = e0; e < e1; e++) {
        int s = g_src[e];
        float w = g_nrm[e];
        uint2 hh = *(const uint2*)(Hkh + (long)s * PITCH + lane * 2);
        uint2 hl = *(const uint2*)(Hkl + (long)s * PITCH + lane * 2);
        float2 v0 = bf2f(hh.x), l0 = bf2f(hl.x);
        float2 v1 = bf2f(hh.y), l1 = bf2f(hl.y);
        acc.x += w * (v0.x + l0.x);
        acc.y += w * (v0.y + l0.y);
        acc.z += w * (v1.x + l1.x);
        acc.w += w * (v1.y + l1.y);
    }
    long off = base + (long)n * PITCH + lane * 2;
    uint2 rh = *(const uint2*)(Rh + off);
    uint2 rl = *(const uint2*)(Rl + off);
    float2 r0 = bf2f(rh.x), q0 = bf2f(rl.x);
    float2 r1 = bf2f(rh.y), q1 = bf2f(rl.y);
    acc.x += r0.x + q0.x;
    acc.y += r0.y + q0.y;
    acc.z += r1.x + q1.x;
    acc.w += r1.y + q1.y;
    if (RELU) {
        acc.x = fmaxf(acc.x, 0.f);
        acc.y = fmaxf(acc.y, 0.f);
        acc.z = fmaxf(acc.z, 0.f);
        acc.w = fmaxf(acc.w, 0.f);
    }
    uint32_t lo0, hi0 = split_pack(acc.x, acc.y, lo0);
    uint32_t lo1, hi1 = split_pack(acc.z, acc.w, lo1);
    *(uint2*)(Oh + off) = make_uint2(hi0, hi1);
    *(uint2*)(Ol + off) = make_uint2(lo0, lo1);
}

// ---------------- mean over stacks ---------------------------------------------
__global__ void mean_kernel() {
    long i = blockIdx.x * 256L + threadIdx.x;
    const long st = (long)NN * KPH;
    if (i < st) {
        float2 s = make_float2(0.f, 0.f);
#pragma unroll
        for (int k = 0; k < KST; k++) {
            float2 h = bf2f(g_H1H[i + k * st]);
            float2 l = bf2f(g_H1L[i + k * st]);
            s.x += h.x + l.x;
            s.y += h.y + l.y;
        }
        s.x *= (1.0f / 3.0f);
        s.y *= (1.0f / 3.0f);
        uint32_t lo, hi = split_pack(s.x, s.y, lo);
        g_HMH[i] = hi;
        g_HML[i] = lo;
    }
}

// ---------------- final: mean over stacks + log_softmax -------------------------
__global__ void final_kernel(float* __restrict__ out) {
    int n = blockIdx.x;
    int f = threadIdx.x;  // 64 threads
    const long st = (long)NN * KPO;
    long p = (long)n * KPO + (f >> 1);
    float v = 0.f;
#pragma unroll
    for (int k = 0; k < KST; k++) {
        float2 h = bf2f(g_G1H[p + k * st]);
        float2 l = bf2f(g_G1L[p + k * st]);
        v += (f & 1) ? (h.y + l.y) : (h.x + l.x);
    }
    v *= (1.0f / 3.0f);
    float m = v;
#pragma unroll
    for (int d = 16; d; d >>= 1) m = fmaxf(m, __shfl_xor_sync(0xffffffffu, m, d));
    __shared__ float sm[2], ss[2];
    int w = threadIdx.x >> 5;
    if ((threadIdx.x & 31) == 0) sm[w] = m;
    __syncthreads();
    m = fmaxf(sm[0], sm[1]);
    float e = expf(v - m);
    float s = e;
#pragma unroll
    for (int d = 16; d; d >>= 1) s += __shfl_xor_sync(0xffffffffu, s, d);
    if ((threadIdx.x & 31) == 0) ss[w] = s;
    __syncthreads();
    s = ss[0] + ss[1];
    out[(long)n * FOUT + f] = v - m - logf(s);
}

// ---------------- launch ---------------------------------------------------------
extern "C" void kernel_launch(void* const* d_in, const int* in_sizes, int n_in,
                              void* d_out, int out_size) {
    const float* x = (const float*)d_in[0];
    const void* ei = d_in[1];
    const float* init_w1 = (const float*)d_in[2];
    const float* w1 = (const float*)d_in[3];
    const float* root_w1 = (const float*)d_in[4];
    const float* bias1 = (const float*)d_in[5];
    const float* init_w2 = (const float*)d_in[6];
    const float* w2 = (const float*)d_in[7];
    const float* root_w2 = (const float*)d_in[8];
    const float* bias2 = (const float*)d_in[9];
    float* out = (float*)d_out;

    static bool attr_set = false;
    if (!attr_set) {
        cudaFuncSetAttribute(bgemm2, cudaFuncAttributeMaxDynamicSharedMemorySize, GSMEM);
        attr_set = true;
    }

    uint32_t *XH, *XL, *H0H, *H0L, *H1H, *H1L, *R1H, *R1L, *HMH, *HML;
    uint32_t *G0H, *G0L, *G1H, *G1L, *R2H, *R2L;
    uint32_t *W1CH, *W1CL, *W1H, *W1L, *W2CH, *W2CL, *W2H, *W2L;
    cudaGetSymbolAddress((void**)&XH, g_XH);
    cudaGetSymbolAddress((void**)&XL, g_XL);
    cudaGetSymbolAddress((void**)&H0H, g_H0H);
    cudaGetSymbolAddress((void**)&H0L, g_H0L);
    cudaGetSymbolAddress((void**)&H1H, g_H1H);
    cudaGetSymbolAddress((void**)&H1L, g_H1L);
    cudaGetSymbolAddress((void**)&R1H, g_R1H);
    cudaGetSymbolAddress((void**)&R1L, g_R1L);
    cudaGetSymbolAddress((void**)&HMH, g_HMH);
    cudaGetSymbolAddress((void**)&HML, g_HML);
    cudaGetSymbolAddress((void**)&G0H, g_G0H);
    cudaGetSymbolAddress((void**)&G0L, g_G0L);
    cudaGetSymbolAddress((void**)&G1H, g_G1H);
    cudaGetSymbolAddress((void**)&G1L, g_G1L);
    cudaGetSymbolAddress((void**)&R2H, g_R2H);
    cudaGetSymbolAddress((void**)&R2L, g_R2L);
    cudaGetSymbolAddress((void**)&W1CH, g_W1CH);
    cudaGetSymbolAddress((void**)&W1CL, g_W1CL);
    cudaGetSymbolAddress((void**)&W1H, g_W1H);
    cudaGetSymbolAddress((void**)&W1L, g_W1L);
    cudaGetSymbolAddress((void**)&W2CH, g_W2CH);
    cudaGetSymbolAddress((void**)&W2CL, g_W2CL);
    cudaGetSymbolAddress((void**)&W2H, g_W2H);
    cudaGetSymbolAddress((void**)&W2L, g_W2L);

    const int MY = (NN + 127) / 128;  // 235

    // 0-2: prep
    split_x_kernel<<<(NN * KP1 + 255) / 256, 256>>>(x);
    split_weights_kernel<<<(3 * CNT_A + 2 * CNT_B + CNT_C + 255) / 256, 256>>>(
        init_w1, root_w1, w1, init_w2, root_w2, w2);
    zero_cnt_kernel<<<(NN + 255) / 256, 256>>>();
    // 3: fused conv1 GEMM — ncu capture slot
    dim3 gc1(512 / 64, MY, KST);
    bgemm2<<<gc1, 256, GSMEM>>>(XH, XL, 0, W1CH, W1CL, (long)512 * KP1, bias1, FHID,
                                H0H, H0L, (long)NN * KPH, R1H, R1L, (long)NN * KPH,
                                NN, 512, 256, FIN);
    // 4-8: CSR build
    sniff_kernel<<<1, 32>>>((const int*)ei);
    count_deg_kernel<<<(NE + 255) / 256, 256>>>(ei);
    dis_kernel<<<(NN + 255) / 256, 256>>>();
    scan_kernel<<<1, 1024>>>();
    fill_csr_kernel<<<(NE + 255) / 256, 256>>>(ei);

    // conv1 body
    dim3 gp1((NN + 3) / 4, KST);
    prop_kernel<FHID, true><<<gp1, 256>>>(H0H, H0L, R1H, R1L, H1H, H1L);
    dim3 gw1(256 / 64, MY, KST);
    bgemm2<<<gw1, 256, GSMEM>>>(H1H, H1L, (long)NN * KPH, W1H, W1L, (long)256 * KPH,
                                nullptr, 0, H0H, H0L, (long)NN * KPH, nullptr, nullptr,
                                0, NN, 256, 256, FHID);
    prop_kernel<FHID, true><<<gp1, 256>>>(H0H, H0L, R1H, R1L, H1H, H1L);
    mean_kernel<<<(NN * KPH + 255) / 256, 256>>>();

    // conv2
    dim3 gc2(128 / 64, MY, KST);
    bgemm2<<<gc2, 256, GSMEM>>>(HMH, HML, 0, W2CH, W2CL, (long)128 * KPH, bias2, FOUT,
                                G0H, G0L, (long)NN * KPO, R2H, R2L, (long)NN * KPO,
                                NN, 128, 64, FHID);
    dim3 gp2((NN + 15) / 16, KST);
    prop_kernel<FOUT, false><<<gp2, 256>>>(G0H, G0L, R2H, R2L, G1H, G1L);
    dim3 gw2(1, MY, KST);
    bgemm2<<<gw2, 256, GSMEM>>>(G1H, G1L, (long)NN * KPO, W2H, W2L, (long)64 * KPO,
                                nullptr, 0, G0H, G0L, (long)NN * KPO, nullptr, nullptr,
                                0, NN, 64, 64, FOUT);
    prop_kernel<FOUT, false><<<gp2, 256>>>(G0H, G0L, R2H, R2L, G1H, G1L);

    final_kernel<<<NN, FOUT>>>(out);
}

// round 9
// speedup vs baseline: 1.5582x; 1.5563x over previous
#include <cuda_runtime.h>
#include <cuda_fp16.h>
#include <math.h>
#include <stdint.h>

#define KST 3
#define NN 30000
#define NE 300000
#define FIN 256
#define FHID 256
#define FOUT 64
#define KP1 (FIN / 2)    // 128
#define KPH (FHID / 2)   // 128
#define KPO (FOUT / 2)   // 32

// ---------------- scratch (device globals) ------------------------------------
// activations: single fp16x2-packed plane. weights: fp16 hi+lo planes.
__device__ __align__(16) uint32_t g_X[NN * KP1];
__device__ __align__(16) uint32_t g_H0[KST * NN * KPH];
__device__ __align__(16) uint32_t g_H1[KST * NN * KPH];
__device__ __align__(16) uint32_t g_R1[KST * NN * KPH];
__device__ __align__(16) uint32_t g_HM[NN * KPH];
__device__ __align__(16) uint32_t g_G0[KST * NN * KPO];
__device__ __align__(16) uint32_t g_G1[KST * NN * KPO];
__device__ __align__(16) uint32_t g_R2[KST * NN * KPO];
__device__ __align__(16) uint32_t g_W1CH[KST * 512 * KP1], g_W1CL[KST * 512 * KP1];
__device__ __align__(16) uint32_t g_W1H[KST * 256 * KPH], g_W1L[KST * 256 * KPH];
__device__ __align__(16) uint32_t g_W2CH[KST * 128 * KPH], g_W2CL[KST * 128 * KPH];
__device__ __align__(16) uint32_t g_W2H[KST * 64 * KPO], g_W2L[KST * 64 * KPO];
__device__ float g_dis[NN];
__device__ int g_cnt[NN];
__device__ int g_rowptr[NN + 1];
__device__ int g_cursor[NN];
__device__ int g_src[NE];
__device__ float g_nrm[NE];
__device__ int g_is64;

// ---------------- helpers -----------------------------------------------------
__device__ __forceinline__ uint32_t pack_f16(float a, float b) {
    __half2 h = __floats2half2_rn(a, b);
    return *reinterpret_cast<uint32_t*>(&h);
}

__device__ __forceinline__ float2 h2f2(uint32_t u) {
    __half2 h = *reinterpret_cast<__half2*>(&u);
    return __half22float2(h);
}

__device__ __forceinline__ void mma_f16(float* c, const uint32_t* a, const uint32_t* bb) {
    asm volatile(
        "mma.sync.aligned.m16n8k16.row.col.f32.f16.f16.f32 "
        "{%0,%1,%2,%3}, {%4,%5,%6,%7}, {%8,%9}, {%0,%1,%2,%3};\n"
        : "+f"(c[0]), "+f"(c[1]), "+f"(c[2]), "+f"(c[3])
        : "r"(a[0]), "r"(a[1]), "r"(a[2]), "r"(a[3]), "r"(bb[0]), "r"(bb[1]));
}

__device__ __forceinline__ void ldsm4(uint32_t* r, uint32_t addr) {
    asm volatile("ldmatrix.sync.aligned.m8n8.x4.shared.b16 {%0,%1,%2,%3}, [%4];"
                 : "=r"(r[0]), "=r"(r[1]), "=r"(r[2]), "=r"(r[3])
                 : "r"(addr));
}

// ---------------- input conversion ---------------------------------------------
__global__ void split_x_kernel(const float* __restrict__ x) {
    long i = blockIdx.x * 256L + threadIdx.x;
    if (i < (long)NN * KP1) {
        float2 v = *(const float2*)(x + 2 * i);
        g_X[i] = pack_f16(v.x, v.y);
    }
}

// weights: hi = fp16(v), lo = fp16(v - hi); pre-transposed [n][kp]
__device__ __forceinline__ void wsplit(const float* __restrict__ W, uint32_t* oh,
                                       uint32_t* ol, int Kd, int N, int nOff,
                                       int outN, long idx) {
    int Kp = Kd / 2;
    int k = (int)(idx / ((long)N * Kp));
    int rem = (int)(idx % ((long)N * Kp));
    int n = rem / Kp;
    int kp = rem % Kp;
    const float* Wk = W + (long)k * Kd * N;
    float v0 = Wk[(long)(2 * kp) * N + n];
    float v1 = Wk[(long)(2 * kp + 1) * N + n];
    __half h0 = __float2half_rn(v0);
    __half h1 = __float2half_rn(v1);
    float r0 = v0 - __half2float(h0);
    float r1 = v1 - __half2float(h1);
    long o = ((long)k * outN + nOff + n) * Kp + kp;
    __half2 hp = __halves2half2(h0, h1);
    oh[o] = *reinterpret_cast<uint32_t*>(&hp);
    ol[o] = pack_f16(r0, r1);
}

#define CNT_A (KST * 256 * 128)
#define CNT_B (KST * 64 * 128)
#define CNT_C (KST * 64 * 32)

__global__ void split_weights_kernel(const float* iw1, const float* rw1,
                                     const float* w1, const float* iw2,
                                     const float* rw2, const float* w2) {
    long id = blockIdx.x * 256L + threadIdx.x;
    if (id < CNT_A) { wsplit(iw1, g_W1CH, g_W1CL, 256, 256, 0, 512, id); return; }
    id -= CNT_A;
    if (id < CNT_A) { wsplit(rw1, g_W1CH, g_W1CL, 256, 256, 256, 512, id); return; }
    id -= CNT_A;
    if (id < CNT_A) { wsplit(w1, g_W1H, g_W1L, 256, 256, 0, 256, id); return; }
    id -= CNT_A;
    if (id < CNT_B) { wsplit(iw2, g_W2CH, g_W2CL, 256, 64, 0, 128, id); return; }
    id -= CNT_B;
    if (id < CNT_B) { wsplit(rw2, g_W2CH, g_W2CL, 256, 64, 64, 128, id); return; }
    id -= CNT_B;
    if (id < CNT_C) { wsplit(w2, g_W2H, g_W2L, 64, 64, 0, 64, id); }
}

// ---------------- dtype sniff / CSR -------------------------------------------
__global__ void sniff_kernel(const int* __restrict__ ei_raw) {
    if (threadIdx.x == 0 && blockIdx.x == 0) {
        int all_zero = 1;
        for (int i = 0; i < 128; i++)
            if (ei_raw[2 * i + 1] != 0) { all_zero = 0; break; }
        g_is64 = all_zero;
    }
}

__device__ __forceinline__ int load_idx(const void* ei, long pos) {
    if (g_is64) return (int)((const long long*)ei)[pos];
    return ((const int*)ei)[pos];
}

__global__ void zero_cnt_kernel() {
    int i = blockIdx.x * blockDim.x + threadIdx.x;
    if (i < NN) g_cnt[i] = 0;
}

__global__ void count_deg_kernel(const void* __restrict__ ei) {
    int e = blockIdx.x * blockDim.x + threadIdx.x;
    if (e < NE) {
        int c = load_idx(ei, (long)NE + e);
        if (c >= 0 && c < NN) atomicAdd(&g_cnt[c], 1);
    }
}

__global__ void dis_kernel() {
    int i = blockIdx.x * blockDim.x + threadIdx.x;
    if (i < NN) {
        int c = g_cnt[i];
        g_dis[i] = (c > 0) ? rsqrtf((float)c) : 0.0f;
    }
}

__global__ void scan_kernel() {
    __shared__ int sh[1024];
    __shared__ int s_off;
    if (threadIdx.x == 0) s_off = 0;
    __syncthreads();
    for (int base = 0; base < NN; base += 1024) {
        int i = base + threadIdx.x;
        int v = (i < NN) ? g_cnt[i] : 0;
        sh[threadIdx.x] = v;
        __syncthreads();
        for (int d = 1; d < 1024; d <<= 1) {
            int t = (threadIdx.x >= (unsigned)d) ? sh[threadIdx.x - d] : 0;
            __syncthreads();
            sh[threadIdx.x] += t;
            __syncthreads();
        }
        int incl = sh[threadIdx.x];
        int off = s_off;
        __syncthreads();
        if (i < NN) {
            int ex = off + incl - v;
            g_rowptr[i] = ex;
            g_cursor[i] = ex;
        }
        if (threadIdx.x == 1023) s_off = off + incl;
        __syncthreads();
    }
    if (threadIdx.x == 0) g_rowptr[NN] = s_off;
}

__global__ void fill_csr_kernel(const void* __restrict__ ei) {
    int e = blockIdx.x * blockDim.x + threadIdx.x;
    if (e < NE) {
        int r = load_idx(ei, e);
        int c = load_idx(ei, (long)NE + e);
        if (r >= 0 && r < NN && c >= 0 && c < NN) {
            int pos = atomicAdd(&g_cursor[c], 1);
            if (pos >= 0 && pos < NE) {
                g_src[pos] = r;
                g_nrm[pos] = g_dis[r] * g_dis[c];
            }
        }
    }
}

// ---------------- fp16 tensor-core GEMM (A single, W split) --------------------
// C[b] = A[b] @ (Wh[b] + Wl[b]): 2 MMAs per fragment pair. A fp16x2-packed
// [M][Kp]; W pre-transposed split [Ntot][Kp]. Dual-output epilogue.
// BM=128, BN=64, BK=32 (16 pairs), 2-stage cp.async, ldmatrix.x4 (pitch 80B).
#define APITCH 20
#define A_PLANE_B (128 * APITCH * 4)   // 10240 B
#define B_PLANE_B (64 * APITCH * 4)    // 5120 B
#define B_OFF_B (2 * A_PLANE_B)        // 20480 (2 stages of A)
#define GSMEM (2 * (A_PLANE_B + 2 * B_PLANE_B))  // 40960

__global__ __launch_bounds__(256, 3)
void bgemm2(const uint32_t* __restrict__ A, long sA,
            const uint32_t* __restrict__ Bh, const uint32_t* __restrict__ Bl, long sB,
            const float* __restrict__ bias, long sBias,
            uint32_t* __restrict__ C0, long sC0,
            uint32_t* __restrict__ C1, long sC1,
            int M, int Ntot, int N1, int Kd) {
    extern __shared__ uint32_t smem[];
    uint32_t smem_u = (uint32_t)__cvta_generic_to_shared(smem);
    int Kp = Kd >> 1;
    int b = blockIdx.z;
    const uint32_t* Ab = A + (long)b * sA;
    const uint32_t* Bbh = Bh + (long)b * sB;
    const uint32_t* Bbl = Bl + (long)b * sB;
    int bm = blockIdx.y * 128, bn = blockIdx.x * 64;
    int tid = threadIdx.x, warp = tid >> 5, lane = tid & 31;
    int g = lane >> 2, t = lane & 3;
    int wm = warp >> 1, wn = warp & 1;

    int rowA = ((lane >> 3) & 1) * 8 + (lane & 7);
    int segA = (lane >> 4) * 4;
    int rowB = ((lane >> 4) & 1) * 8 + (lane & 7);
    int segB = ((lane >> 3) & 1) * 4;

    auto issue = [&](int kt, int buf) {
        int kp0 = kt * 16;
#pragma unroll
        for (int i = 0; i < 2; i++) {  // A: 512 16B chunks
            int ch = tid + i * 256;
            int row = ch >> 2, seg = ch & 3;
            int gm = bm + row;
            if (gm >= M) gm = M - 1;
            const uint32_t* src = Ab + (long)gm * Kp + kp0 + seg * 4;
            uint32_t dst = smem_u + buf * A_PLANE_B + (row * APITCH + seg * 4) * 4;
            asm volatile("cp.async.cg.shared.global [%0], [%1], 16;" ::"r"(dst), "l"(src));
        }
#pragma unroll
        for (int i = 0; i < 2; i++) {  // B: 512 chunks (2 splits x 64 rows x 4 segs)
            int ch = tid + i * 256;
            int s = ch >> 8, rem = ch & 255, row = rem >> 2, seg = rem & 3;
            const uint32_t* src = (s ? Bbl : Bbh) + (long)(bn + row) * Kp + kp0 + seg * 4;
            uint32_t dst =
                smem_u + B_OFF_B + (buf * 2 + s) * B_PLANE_B + (row * APITCH + seg * 4) * 4;
            asm volatile("cp.async.cg.shared.global [%0], [%1], 16;" ::"r"(dst), "l"(src));
        }
        asm volatile("cp.async.commit_group;" ::: "memory");
    };

    float acc[2][4][4];
#pragma unroll
    for (int i = 0; i < 2; i++)
#pragma unroll
        for (int j = 0; j < 4; j++)
#pragma unroll
            for (int k = 0; k < 4; k++) acc[i][j][k] = 0.f;

    int NT = Kd / 32;
    issue(0, 0);
    for (int kt = 0; kt < NT; kt++) {
        int buf = kt & 1;
        if (kt + 1 < NT) {
            issue(kt + 1, (kt + 1) & 1);
            asm volatile("cp.async.wait_group 1;" ::: "memory");
        } else {
            asm volatile("cp.async.wait_group 0;" ::: "memory");
        }
        __syncthreads();
#pragma unroll
        for (int ks = 0; ks < 2; ks++) {
            int kp0 = ks * 8;
            uint32_t af[2][4], bf[2][4][2];
            {
                uint32_t aBase = smem_u + buf * A_PLANE_B;
#pragma unroll
                for (int mt = 0; mt < 2; mt++) {
                    uint32_t addr =
                        aBase + ((wm * 32 + mt * 16 + rowA) * APITCH + kp0 + segA) * 4;
                    ldsm4(af[mt], addr);
                }
            }
#pragma unroll
            for (int s = 0; s < 2; s++) {
                uint32_t bBase = smem_u + B_OFF_B + (buf * 2 + s) * B_PLANE_B;
#pragma unroll
                for (int np = 0; np < 2; np++) {
                    uint32_t addr =
                        bBase + ((wn * 32 + np * 16 + rowB) * APITCH + kp0 + segB) * 4;
                    ldsm4(&bf[s][np * 2][0], addr);
                }
            }
#pragma unroll
            for (int mt = 0; mt < 2; mt++)
#pragma unroll
                for (int nt = 0; nt < 4; nt++) {
                    mma_f16(acc[mt][nt], af[mt], bf[0][nt]);  // A * Whi
                    mma_f16(acc[mt][nt], af[mt], bf[1][nt]);  // A * Wlo
                }
        }
        __syncthreads();
    }

    // ---- epilogue: fp16-pack + dual-target store ----
    int row0 = bm + wm * 32;
    int col0 = bn + wn * 32;
#pragma unroll
    for (int nt = 0; nt < 4; nt++) {
        int c = col0 + nt * 8 + 2 * t;
        bool out1 = (c >= N1);
        float bx = 0.f, by = 0.f;
        uint32_t* O;
        long pitch;
        int cc;
        if (out1) {
            if (bias) {
                bx = bias[b * sBias + (c - N1)];
                by = bias[b * sBias + (c - N1) + 1];
            }
            O = C1 + (long)b * sC1;
            pitch = (Ntot - N1) >> 1;
            cc = (c - N1) >> 1;
        } else {
            O = C0 + (long)b * sC0;
            pitch = N1 >> 1;
            cc = c >> 1;
        }
#pragma unroll
        for (int mt = 0; mt < 2; mt++) {
            int r = row0 + mt * 16 + g;
            if (r < M)
                O[(long)r * pitch + cc] = pack_f16(acc[mt][nt][0] + bx, acc[mt][nt][1] + by);
            if (r + 8 < M)
                O[(long)(r + 8) * pitch + cc] =
                    pack_f16(acc[mt][nt][2] + bx, acc[mt][nt][3] + by);
        }
    }
}

// ---------------- propagation (CSR gather on fp16) ------------------------------
template <int F, bool RELU>
__global__ void prop_kernel(const uint32_t* __restrict__ H,
                            const uint32_t* __restrict__ R,
                            uint32_t* __restrict__ O) {
    constexpr int LANES = F / 4;
    constexpr int NPB = 256 / LANES;
    constexpr int PITCH = F / 2;
    int lane = threadIdx.x % LANES;
    int local = threadIdx.x / LANES;
    int n = blockIdx.x * NPB + local;
    int k = blockIdx.y;
    if (n >= NN) return;
    long base = (long)k * NN * PITCH;
    const uint32_t* Hk = H + base;
    int e0 = g_rowptr[n], e1 = g_rowptr[n + 1];
    float4 acc = make_float4(0.f, 0.f, 0.f, 0.f);
    for (int e = e0; e < e1; e++) {
        int s = g_src[e];
        float w = g_nrm[e];
        uint2 hh = *(const uint2*)(Hk + (long)s * PITCH + lane * 2);
        float2 v0 = h2f2(hh.x);
        float2 v1 = h2f2(hh.y);
        acc.x += w * v0.x;
        acc.y += w * v0.y;
        acc.z += w * v1.x;
        acc.w += w * v1.y;
    }
    long off = base + (long)n * PITCH + lane * 2;
    uint2 rr = *(const uint2*)(R + off);
    float2 r0 = h2f2(rr.x), r1 = h2f2(rr.y);
    acc.x += r0.x;
    acc.y += r0.y;
    acc.z += r1.x;
    acc.w += r1.y;
    if (RELU) {
        acc.x = fmaxf(acc.x, 0.f);
        acc.y = fmaxf(acc.y, 0.f);
        acc.z = fmaxf(acc.z, 0.f);
        acc.w = fmaxf(acc.w, 0.f);
    }
    *(uint2*)(O + off) = make_uint2(pack_f16(acc.x, acc.y), pack_f16(acc.z, acc.w));
}

// ---------------- mean over stacks ---------------------------------------------
__global__ void mean_kernel() {
    long i = blockIdx.x * 256L + threadIdx.x;
    const long st = (long)NN * KPH;
    if (i < st) {
        float2 s = make_float2(0.f, 0.f);
#pragma unroll
        for (int k = 0; k < KST; k++) {
            float2 h = h2f2(g_H1[i + k * st]);
            s.x += h.x;
            s.y += h.y;
        }
        g_HM[i] = pack_f16(s.x * (1.0f / 3.0f), s.y * (1.0f / 3.0f));
    }
}

// ---------------- final: mean over stacks + log_softmax -------------------------
__global__ void final_kernel(float* __restrict__ out) {
    int n = blockIdx.x;
    int f = threadIdx.x;  // 64 threads
    const long st = (long)NN * KPO;
    long p = (long)n * KPO + (f >> 1);
    float v = 0.f;
#pragma unroll
    for (int k = 0; k < KST; k++) {
        float2 h = h2f2(g_G1[p + k * st]);
        v += (f & 1) ? h.y : h.x;
    }
    v *= (1.0f / 3.0f);
    float m = v;
#pragma unroll
    for (int d = 16; d; d >>= 1) m = fmaxf(m, __shfl_xor_sync(0xffffffffu, m, d));
    __shared__ float sm[2], ss[2];
    int w = threadIdx.x >> 5;
    if ((threadIdx.x & 31) == 0) sm[w] = m;
    __syncthreads();
    m = fmaxf(sm[0], sm[1]);
    float e = expf(v - m);
    float s = e;
#pragma unroll
    for (int d = 16; d; d >>= 1) s += __shfl_xor_sync(0xffffffffu, s, d);
    if ((threadIdx.x & 31) == 0) ss[w] = s;
    __syncthreads();
    s = ss[0] + ss[1];
    out[(long)n * FOUT + f] = v - m - logf(s);
}

// ---------------- launch ---------------------------------------------------------
extern "C" void kernel_launch(void* const* d_in, const int* in_sizes, int n_in,
                              void* d_out, int out_size) {
    const float* x = (const float*)d_in[0];
    const void* ei = d_in[1];
    const float* init_w1 = (const float*)d_in[2];
    const float* w1 = (const float*)d_in[3];
    const float* root_w1 = (const float*)d_in[4];
    const float* bias1 = (const float*)d_in[5];
    const float* init_w2 = (const float*)d_in[6];
    const float* w2 = (const float*)d_in[7];
    const float* root_w2 = (const float*)d_in[8];
    const float* bias2 = (const float*)d_in[9];
    float* out = (float*)d_out;

    static bool attr_set = false;
    if (!attr_set) {
        cudaFuncSetAttribute(bgemm2, cudaFuncAttributeMaxDynamicSharedMemorySize, GSMEM);
        attr_set = true;
    }

    uint32_t *X, *H0, *H1, *R1, *HM, *G0, *G1, *R2;
    uint32_t *W1CH, *W1CL, *W1H, *W1L, *W2CH, *W2CL, *W2H, *W2L;
    cudaGetSymbolAddress((void**)&X, g_X);
    cudaGetSymbolAddress((void**)&H0, g_H0);
    cudaGetSymbolAddress((void**)&H1, g_H1);
    cudaGetSymbolAddress((void**)&R1, g_R1);
    cudaGetSymbolAddress((void**)&HM, g_HM);
    cudaGetSymbolAddress((void**)&G0, g_G0);
    cudaGetSymbolAddress((void**)&G1, g_G1);
    cudaGetSymbolAddress((void**)&R2, g_R2);
    cudaGetSymbolAddress((void**)&W1CH, g_W1CH);
    cudaGetSymbolAddress((void**)&W1CL, g_W1CL);
    cudaGetSymbolAddress((void**)&W1H, g_W1H);
    cudaGetSymbolAddress((void**)&W1L, g_W1L);
    cudaGetSymbolAddress((void**)&W2CH, g_W2CH);
    cudaGetSymbolAddress((void**)&W2CL, g_W2CL);
    cudaGetSymbolAddress((void**)&W2H, g_W2H);
    cudaGetSymbolAddress((void**)&W2L, g_W2L);

    const int MY = (NN + 127) / 128;  // 235

    // 0-2: prep
    split_x_kernel<<<(NN * KP1 + 255) / 256, 256>>>(x);
    split_weights_kernel<<<(3 * CNT_A + 2 * CNT_B + CNT_C + 255) / 256, 256>>>(
        init_w1, root_w1, w1, init_w2, root_w2, w2);
    zero_cnt_kernel<<<(NN + 255) / 256, 256>>>();
    // 3: fused conv1 GEMM — ncu capture slot
    dim3 gc1(512 / 64, MY, KST);
    bgemm2<<<gc1, 256, GSMEM>>>(X, 0, W1CH, W1CL, (long)512 * KP1, bias1, FHID,
                                H0, (long)NN * KPH, R1, (long)NN * KPH,
                                NN, 512, 256, FIN);
    // 4-8: CSR build
    sniff_kernel<<<1, 32>>>((const int*)ei);
    count_deg_kernel<<<(NE + 255) / 256, 256>>>(ei);
    dis_kernel<<<(NN + 255) / 256, 256>>>();
    scan_kernel<<<1, 1024>>>();
    fill_csr_kernel<<<(NE + 255) / 256, 256>>>(ei);

    // conv1 body
    dim3 gp1((NN + 3) / 4, KST);
    prop_kernel<FHID, true><<<gp1, 256>>>(H0, R1, H1);
    dim3 gw1(256 / 64, MY, KST);
    bgemm2<<<gw1, 256, GSMEM>>>(H1, (long)NN * KPH, W1H, W1L, (long)256 * KPH,
                                nullptr, 0, H0, (long)NN * KPH, nullptr, 0,
                                NN, 256, 256, FHID);
    prop_kernel<FHID, true><<<gp1, 256>>>(H0, R1, H1);
    mean_kernel<<<(NN * KPH + 255) / 256, 256>>>();

    // conv2
    dim3 gc2(128 / 64, MY, KST);
    bgemm2<<<gc2, 256, GSMEM>>>(HM, 0, W2CH, W2CL, (long)128 * KPH, bias2, FOUT,
                                G0, (long)NN * KPO, R2, (long)NN * KPO,
                                NN, 128, 64, FHID);
    dim3 gp2((NN + 15) / 16, KST);
    prop_kernel<FOUT, false><<<gp2, 256>>>(G0, R2, G1);
    dim3 gw2(1, MY, KST);
    bgemm2<<<gw2, 256, GSMEM>>>(G1, (long)NN * KPO, W2H, W2L, (long)64 * KPO,
                                nullptr, 0, G0, (long)NN * KPO, nullptr, 0,
                                NN, 64, 64, FOUT);
    prop_kernel<FOUT, false><<<gp2, 256>>>(G0, R2, G1);

    final_kernel<<<NN, FOUT>>>(out);
}

// round 10
// speedup vs baseline: 1.8224x; 1.1695x over previous
#include <cuda_runtime.h>
#include <cuda_fp16.h>
#include <math.h>
#include <stdint.h>

#define KST 3
#define NN 30000
#define NE 300000
#define FIN 256
#define FHID 256
#define FOUT 64
#define KP1 (FIN / 2)    // 128
#define KPH (FHID / 2)   // 128
#define KPO (FOUT / 2)   // 32

// ---------------- scratch (device globals) ------------------------------------
// activations + weights: single fp16x2-packed plane each.
__device__ __align__(16) uint32_t g_X[NN * KP1];
__device__ __align__(16) uint32_t g_H0[KST * NN * KPH];
__device__ __align__(16) uint32_t g_H1[KST * NN * KPH];
__device__ __align__(16) uint32_t g_R1[KST * NN * KPH];
__device__ __align__(16) uint32_t g_HM[NN * KPH];
__device__ __align__(16) uint32_t g_G0[KST * NN * KPO];
__device__ __align__(16) uint32_t g_G1[KST * NN * KPO];
__device__ __align__(16) uint32_t g_R2[KST * NN * KPO];
__device__ __align__(16) uint32_t g_W1C[KST * 512 * KP1];
__device__ __align__(16) uint32_t g_W1[KST * 256 * KPH];
__device__ __align__(16) uint32_t g_W2C[KST * 128 * KPH];
__device__ __align__(16) uint32_t g_W2[KST * 64 * KPO];
__device__ float g_dis[NN];
__device__ int g_cnt[NN];
__device__ int g_rowptr[NN + 1];
__device__ int g_cursor[NN];
__device__ int g_src[NE];
__device__ float g_nrm[NE];
__device__ int g_is64;

// ---------------- helpers -----------------------------------------------------
__device__ __forceinline__ uint32_t pack_f16(float a, float b) {
    __half2 h = __floats2half2_rn(a, b);
    return *reinterpret_cast<uint32_t*>(&h);
}

__device__ __forceinline__ float2 h2f2(uint32_t u) {
    __half2 h = *reinterpret_cast<__half2*>(&u);
    return __half22float2(h);
}

__device__ __forceinline__ void mma_f16(float* c, const uint32_t* a, const uint32_t* bb) {
    asm volatile(
        "mma.sync.aligned.m16n8k16.row.col.f32.f16.f16.f32 "
        "{%0,%1,%2,%3}, {%4,%5,%6,%7}, {%8,%9}, {%0,%1,%2,%3};\n"
        : "+f"(c[0]), "+f"(c[1]), "+f"(c[2]), "+f"(c[3])
        : "r"(a[0]), "r"(a[1]), "r"(a[2]), "r"(a[3]), "r"(bb[0]), "r"(bb[1]));
}

__device__ __forceinline__ void ldsm4(uint32_t* r, uint32_t addr) {
    asm volatile("ldmatrix.sync.aligned.m8n8.x4.shared.b16 {%0,%1,%2,%3}, [%4];"
                 : "=r"(r[0]), "=r"(r[1]), "=r"(r[2]), "=r"(r[3])
                 : "r"(addr));
}

// ---------------- input conversion ---------------------------------------------
__global__ void split_x_kernel(const float* __restrict__ x) {
    long i = blockIdx.x * 256L + threadIdx.x;
    if (i < (long)NN * KP1) {
        float2 v = *(const float2*)(x + 2 * i);
        g_X[i] = pack_f16(v.x, v.y);
    }
}

// weights: fp16 convert, pre-transposed [n][kp]
__device__ __forceinline__ void wconv(const float* __restrict__ W, uint32_t* oh,
                                      int Kd, int N, int nOff, int outN, long idx) {
    int Kp = Kd / 2;
    int k = (int)(idx / ((long)N * Kp));
    int rem = (int)(idx % ((long)N * Kp));
    int n = rem / Kp;
    int kp = rem % Kp;
    const float* Wk = W + (long)k * Kd * N;
    float v0 = Wk[(long)(2 * kp) * N + n];
    float v1 = Wk[(long)(2 * kp + 1) * N + n];
    oh[((long)k * outN + nOff + n) * Kp + kp] = pack_f16(v0, v1);
}

#define CNT_A (KST * 256 * 128)
#define CNT_B (KST * 64 * 128)
#define CNT_C (KST * 64 * 32)

__global__ void split_weights_kernel(const float* iw1, const float* rw1,
                                     const float* w1, const float* iw2,
                                     const float* rw2, const float* w2) {
    long id = blockIdx.x * 256L + threadIdx.x;
    if (id < CNT_A) { wconv(iw1, g_W1C, 256, 256, 0, 512, id); return; }
    id -= CNT_A;
    if (id < CNT_A) { wconv(rw1, g_W1C, 256, 256, 256, 512, id); return; }
    id -= CNT_A;
    if (id < CNT_A) { wconv(w1, g_W1, 256, 256, 0, 256, id); return; }
    id -= CNT_A;
    if (id < CNT_B) { wconv(iw2, g_W2C, 256, 64, 0, 128, id); return; }
    id -= CNT_B;
    if (id < CNT_B) { wconv(rw2, g_W2C, 256, 64, 64, 128, id); return; }
    id -= CNT_B;
    if (id < CNT_C) { wconv(w2, g_W2, 64, 64, 0, 64, id); }
}

// ---------------- dtype sniff / CSR -------------------------------------------
__global__ void sniff_kernel(const int* __restrict__ ei_raw) {
    if (threadIdx.x == 0 && blockIdx.x == 0) {
        int all_zero = 1;
        for (int i = 0; i < 128; i++)
            if (ei_raw[2 * i + 1] != 0) { all_zero = 0; break; }
        g_is64 = all_zero;
    }
}

__device__ __forceinline__ int load_idx(const void* ei, long pos) {
    if (g_is64) return (int)((const long long*)ei)[pos];
    return ((const int*)ei)[pos];
}

__global__ void zero_cnt_kernel() {
    int i = blockIdx.x * blockDim.x + threadIdx.x;
    if (i < NN) g_cnt[i] = 0;
}

__global__ void count_deg_kernel(const void* __restrict__ ei) {
    int e = blockIdx.x * blockDim.x + threadIdx.x;
    if (e < NE) {
        int c = load_idx(ei, (long)NE + e);
        if (c >= 0 && c < NN) atomicAdd(&g_cnt[c], 1);
    }
}

__global__ void dis_kernel() {
    int i = blockIdx.x * blockDim.x + threadIdx.x;
    if (i < NN) {
        int c = g_cnt[i];
        g_dis[i] = (c > 0) ? rsqrtf((float)c) : 0.0f;
    }
}

__global__ void scan_kernel() {
    __shared__ int sh[1024];
    __shared__ int s_off;
    if (threadIdx.x == 0) s_off = 0;
    __syncthreads();
    for (int base = 0; base < NN; base += 1024) {
        int i = base + threadIdx.x;
        int v = (i < NN) ? g_cnt[i] : 0;
        sh[threadIdx.x] = v;
        __syncthreads();
        for (int d = 1; d < 1024; d <<= 1) {
            int t = (threadIdx.x >= (unsigned)d) ? sh[threadIdx.x - d] : 0;
            __syncthreads();
            sh[threadIdx.x] += t;
            __syncthreads();
        }
        int incl = sh[threadIdx.x];
        int off = s_off;
        __syncthreads();
        if (i < NN) {
            int ex = off + incl - v;
            g_rowptr[i] = ex;
            g_cursor[i] = ex;
        }
        if (threadIdx.x == 1023) s_off = off + incl;
        __syncthreads();
    }
    if (threadIdx.x == 0) g_rowptr[NN] = s_off;
}

__global__ void fill_csr_kernel(const void* __restrict__ ei) {
    int e = blockIdx.x * blockDim.x + threadIdx.x;
    if (e < NE) {
        int r = load_idx(ei, e);
        int c = load_idx(ei, (long)NE + e);
        if (r >= 0 && r < NN && c >= 0 && c < NN) {
            int pos = atomicAdd(&g_cursor[c], 1);
            if (pos >= 0 && pos < NE) {
                g_src[pos] = r;
                g_nrm[pos] = g_dis[r] * g_dis[c];
            }
        }
    }
}

// ---------------- fp16 tensor-core GEMM ----------------------------------------
// C[b] = A[b] @ W[b]: plain fp16 MMA, fp32 accum. A fp16x2-packed [M][Kp];
// W pre-transposed [Ntot][Kp]. Dual-output epilogue.
// BM=128, BN=64, BK=32 (16 pairs), 2-stage cp.async, ldmatrix.x4 (pitch 80B).
#define APITCH 20
#define A_PLANE_B (128 * APITCH * 4)   // 10240 B
#define B_PLANE_B (64 * APITCH * 4)    // 5120 B
#define B_OFF_B (2 * A_PLANE_B)        // 20480 (2 stages of A)
#define GSMEM (2 * (A_PLANE_B + B_PLANE_B))  // 30720

__global__ __launch_bounds__(256, 3)
void bgemm2(const uint32_t* __restrict__ A, long sA,
            const uint32_t* __restrict__ B, long sB,
            const float* __restrict__ bias, long sBias,
            uint32_t* __restrict__ C0, long sC0,
            uint32_t* __restrict__ C1, long sC1,
            int M, int Ntot, int N1, int Kd) {
    extern __shared__ uint32_t smem[];
    uint32_t smem_u = (uint32_t)__cvta_generic_to_shared(smem);
    int Kp = Kd >> 1;
    int b = blockIdx.z;
    const uint32_t* Ab = A + (long)b * sA;
    const uint32_t* Bb = B + (long)b * sB;
    int bm = blockIdx.y * 128, bn = blockIdx.x * 64;
    int tid = threadIdx.x, warp = tid >> 5, lane = tid & 31;
    int g = lane >> 2, t = lane & 3;
    int wm = warp >> 1, wn = warp & 1;

    int rowA = ((lane >> 3) & 1) * 8 + (lane & 7);
    int segA = (lane >> 4) * 4;
    int rowB = ((lane >> 4) & 1) * 8 + (lane & 7);
    int segB = ((lane >> 3) & 1) * 4;

    auto issue = [&](int kt, int buf) {
        int kp0 = kt * 16;
#pragma unroll
        for (int i = 0; i < 2; i++) {  // A: 512 16B chunks
            int ch = tid + i * 256;
            int row = ch >> 2, seg = ch & 3;
            int gm = bm + row;
            if (gm >= M) gm = M - 1;
            const uint32_t* src = Ab + (long)gm * Kp + kp0 + seg * 4;
            uint32_t dst = smem_u + buf * A_PLANE_B + (row * APITCH + seg * 4) * 4;
            asm volatile("cp.async.cg.shared.global [%0], [%1], 16;" ::"r"(dst), "l"(src));
        }
        {  // B: 256 chunks
            int ch = tid;
            int row = ch >> 2, seg = ch & 3;
            const uint32_t* src = Bb + (long)(bn + row) * Kp + kp0 + seg * 4;
            uint32_t dst = smem_u + B_OFF_B + buf * B_PLANE_B + (row * APITCH + seg * 4) * 4;
            asm volatile("cp.async.cg.shared.global [%0], [%1], 16;" ::"r"(dst), "l"(src));
        }
        asm volatile("cp.async.commit_group;" ::: "memory");
    };

    float acc[2][4][4];
#pragma unroll
    for (int i = 0; i < 2; i++)
#pragma unroll
        for (int j = 0; j < 4; j++)
#pragma unroll
            for (int k = 0; k < 4; k++) acc[i][j][k] = 0.f;

    int NT = Kd / 32;
    issue(0, 0);
    for (int kt = 0; kt < NT; kt++) {
        int buf = kt & 1;
        if (kt + 1 < NT) {
            issue(kt + 1, (kt + 1) & 1);
            asm volatile("cp.async.wait_group 1;" ::: "memory");
        } else {
            asm volatile("cp.async.wait_group 0;" ::: "memory");
        }
        __syncthreads();
#pragma unroll
        for (int ks = 0; ks < 2; ks++) {
            int kp0 = ks * 8;
            uint32_t af[2][4], bf[4][2];
            {
                uint32_t aBase = smem_u + buf * A_PLANE_B;
#pragma unroll
                for (int mt = 0; mt < 2; mt++) {
                    uint32_t addr =
                        aBase + ((wm * 32 + mt * 16 + rowA) * APITCH + kp0 + segA) * 4;
                    ldsm4(af[mt], addr);
                }
            }
            {
                uint32_t bBase = smem_u + B_OFF_B + buf * B_PLANE_B;
#pragma unroll
                for (int np = 0; np < 2; np++) {
                    uint32_t addr =
                        bBase + ((wn * 32 + np * 16 + rowB) * APITCH + kp0 + segB) * 4;
                    ldsm4(&bf[np * 2][0], addr);
                }
            }
#pragma unroll
            for (int mt = 0; mt < 2; mt++)
#pragma unroll
                for (int nt = 0; nt < 4; nt++) mma_f16(acc[mt][nt], af[mt], bf[nt]);
        }
        __syncthreads();
    }

    // ---- epilogue: fp16-pack + dual-target store ----
    int row0 = bm + wm * 32;
    int col0 = bn + wn * 32;
#pragma unroll
    for (int nt = 0; nt < 4; nt++) {
        int c = col0 + nt * 8 + 2 * t;
        bool out1 = (c >= N1);
        float bx = 0.f, by = 0.f;
        uint32_t* O;
        long pitch;
        int cc;
        if (out1) {
            if (bias) {
                bx = bias[b * sBias + (c - N1)];
                by = bias[b * sBias + (c - N1) + 1];
            }
            O = C1 + (long)b * sC1;
            pitch = (Ntot - N1) >> 1;
            cc = (c - N1) >> 1;
        } else {
            O = C0 + (long)b * sC0;
            pitch = N1 >> 1;
            cc = c >> 1;
        }
#pragma unroll
        for (int mt = 0; mt < 2; mt++) {
            int r = row0 + mt * 16 + g;
            if (r < M)
                O[(long)r * pitch + cc] = pack_f16(acc[mt][nt][0] + bx, acc[mt][nt][1] + by);
            if (r + 8 < M)
                O[(long)(r + 8) * pitch + cc] =
                    pack_f16(acc[mt][nt][2] + bx, acc[mt][nt][3] + by);
        }
    }
}

// ---------------- propagation (CSR gather on fp16) ------------------------------
template <int F, bool RELU>
__global__ void prop_kernel(const uint32_t* __restrict__ H,
                            const uint32_t* __restrict__ R,
                            uint32_t* __restrict__ O) {
    constexpr int LANES = F / 4;
    constexpr int NPB = 256 / LANES;
    constexpr int PITCH = F / 2;
    int lane = threadIdx.x % LANES;
    int local = threadIdx.x / LANES;
    int n = blockIdx.x * NPB + local;
    int k = blockIdx.y;
    if (n >= NN) return;
    long base = (long)k * NN * PITCH;
    const uint32_t* Hk = H + base;
    int e0 = g_rowptr[n], e1 = g_rowptr[n + 1];
    float4 acc = make_float4(0.f, 0.f, 0.f, 0.f);
    for (int e = e0; e < e1; e++) {
        int s = g_src[e];
        float w = g_nrm[e];
        uint2 hh = *(const uint2*)(Hk + (long)s * PITCH + lane * 2);
        float2 v0 = h2f2(hh.x);
        float2 v1 = h2f2(hh.y);
        acc.x += w * v0.x;
        acc.y += w * v0.y;
        acc.z += w * v1.x;
        acc.w += w * v1.y;
    }
    long off = base + (long)n * PITCH + lane * 2;
    uint2 rr = *(const uint2*)(R + off);
    float2 r0 = h2f2(rr.x), r1 = h2f2(rr.y);
    acc.x += r0.x;
    acc.y += r0.y;
    acc.z += r1.x;
    acc.w += r1.y;
    if (RELU) {
        acc.x = fmaxf(acc.x, 0.f);
        acc.y = fmaxf(acc.y, 0.f);
        acc.z = fmaxf(acc.z, 0.f);
        acc.w = fmaxf(acc.w, 0.f);
    }
    *(uint2*)(O + off) = make_uint2(pack_f16(acc.x, acc.y), pack_f16(acc.z, acc.w));
}

// ---------------- mean over stacks ---------------------------------------------
__global__ void mean_kernel() {
    long i = blockIdx.x * 256L + threadIdx.x;
    const long st = (long)NN * KPH;
    if (i < st) {
        float2 s = make_float2(0.f, 0.f);
#pragma unroll
        for (int k = 0; k < KST; k++) {
            float2 h = h2f2(g_H1[i + k * st]);
            s.x += h.x;
            s.y += h.y;
        }
        g_HM[i] = pack_f16(s.x * (1.0f / 3.0f), s.y * (1.0f / 3.0f));
    }
}

// ---------------- final: mean over stacks + log_softmax -------------------------
__global__ void final_kernel(float* __restrict__ out) {
    int n = blockIdx.x;
    int f = threadIdx.x;  // 64 threads
    const long st = (long)NN * KPO;
    long p = (long)n * KPO + (f >> 1);
    float v = 0.f;
#pragma unroll
    for (int k = 0; k < KST; k++) {
        float2 h = h2f2(g_G1[p + k * st]);
        v += (f & 1) ? h.y : h.x;
    }
    v *= (1.0f / 3.0f);
    float m = v;
#pragma unroll
    for (int d = 16; d; d >>= 1) m = fmaxf(m, __shfl_xor_sync(0xffffffffu, m, d));
    __shared__ float sm[2], ss[2];
    int w = threadIdx.x >> 5;
    if ((threadIdx.x & 31) == 0) sm[w] = m;
    __syncthreads();
    m = fmaxf(sm[0], sm[1]);
    float e = expf(v - m);
    float s = e;
#pragma unroll
    for (int d = 16; d; d >>= 1) s += __shfl_xor_sync(0xffffffffu, s, d);
    if ((threadIdx.x & 31) == 0) ss[w] = s;
    __syncthreads();
    s = ss[0] + ss[1];
    out[(long)n * FOUT + f] = v - m - logf(s);
}

// ---------------- launch ---------------------------------------------------------
extern "C" void kernel_launch(void* const* d_in, const int* in_sizes, int n_in,
                              void* d_out, int out_size) {
    const float* x = (const float*)d_in[0];
    const void* ei = d_in[1];
    const float* init_w1 = (const float*)d_in[2];
    const float* w1 = (const float*)d_in[3];
    const float* root_w1 = (const float*)d_in[4];
    const float* bias1 = (const float*)d_in[5];
    const float* init_w2 = (const float*)d_in[6];
    const float* w2 = (const float*)d_in[7];
    const float* root_w2 = (const float*)d_in[8];
    const float* bias2 = (const float*)d_in[9];
    float* out = (float*)d_out;

    static bool attr_set = false;
    if (!attr_set) {
        cudaFuncSetAttribute(bgemm2, cudaFuncAttributeMaxDynamicSharedMemorySize, GSMEM);
        attr_set = true;
    }

    uint32_t *X, *H0, *H1, *R1, *HM, *G0, *G1, *R2;
    uint32_t *W1C, *W1, *W2C, *W2;
    cudaGetSymbolAddress((void**)&X, g_X);
    cudaGetSymbolAddress((void**)&H0, g_H0);
    cudaGetSymbolAddress((void**)&H1, g_H1);
    cudaGetSymbolAddress((void**)&R1, g_R1);
    cudaGetSymbolAddress((void**)&HM, g_HM);
    cudaGetSymbolAddress((void**)&G0, g_G0);
    cudaGetSymbolAddress((void**)&G1, g_G1);
    cudaGetSymbolAddress((void**)&R2, g_R2);
    cudaGetSymbolAddress((void**)&W1C, g_W1C);
    cudaGetSymbolAddress((void**)&W1, g_W1);
    cudaGetSymbolAddress((void**)&W2C, g_W2C);
    cudaGetSymbolAddress((void**)&W2, g_W2);

    const int MY = (NN + 127) / 128;  // 235

    // 0-2: prep
    split_x_kernel<<<(NN * KP1 + 255) / 256, 256>>>(x);
    split_weights_kernel<<<(3 * CNT_A + 2 * CNT_B + CNT_C + 255) / 256, 256>>>(
        init_w1, root_w1, w1, init_w2, root_w2, w2);
    zero_cnt_kernel<<<(NN + 255) / 256, 256>>>();
    // 3: fused conv1 GEMM — ncu capture slot
    dim3 gc1(512 / 64, MY, KST);
    bgemm2<<<gc1, 256, GSMEM>>>(X, 0, W1C, (long)512 * KP1, bias1, FHID,
                                H0, (long)NN * KPH, R1, (long)NN * KPH,
                                NN, 512, 256, FIN);
    // 4-8: CSR build
    sniff_kernel<<<1, 32>>>((const int*)ei);
    count_deg_kernel<<<(NE + 255) / 256, 256>>>(ei);
    dis_kernel<<<(NN + 255) / 256, 256>>>();
    scan_kernel<<<1, 1024>>>();
    fill_csr_kernel<<<(NE + 255) / 256, 256>>>(ei);

    // conv1 body
    dim3 gp1((NN + 3) / 4, KST);
    prop_kernel<FHID, true><<<gp1, 256>>>(H0, R1, H1);
    dim3 gw1(256 / 64, MY, KST);
    bgemm2<<<gw1, 256, GSMEM>>>(H1, (long)NN * KPH, W1, (long)256 * KPH,
                                nullptr, 0, H0, (long)NN * KPH, nullptr, 0,
                                NN, 256, 256, FHID);
    prop_kernel<FHID, true><<<gp1, 256>>>(H0, R1, H1);
    mean_kernel<<<(NN * KPH + 255) / 256, 256>>>();

    // conv2
    dim3 gc2(128 / 64, MY, KST);
    bgemm2<<<gc2, 256, GSMEM>>>(HM, 0, W2C, (long)128 * KPH, bias2, FOUT,
                                G0, (long)NN * KPO, R2, (long)NN * KPO,
                                NN, 128, 64, FHID);
    dim3 gp2((NN + 15) / 16, KST);
    prop_kernel<FOUT, false><<<gp2, 256>>>(G0, R2, G1);
    dim3 gw2(1, MY, KST);
    bgemm2<<<gw2, 256, GSMEM>>>(G1, (long)NN * KPO, W2, (long)64 * KPO,
                                nullptr, 0, G0, (long)NN * KPO, nullptr, 0,
                                NN, 64, 64, FOUT);
    prop_kernel<FOUT, false><<<gp2, 256>>>(G0, R2, G1);

    final_kernel<<<NN, FOUT>>>(out);
}

// round 11
// speedup vs baseline: 1.9322x; 1.0603x over previous
#include <cuda_runtime.h>
#include <cuda_fp16.h>
#include <math.h>
#include <stdint.h>

#define KST 3
#define NN 30000
#define NE 300000
#define FIN 256
#define FHID 256
#define FOUT 64
#define KP1 (FIN / 2)    // 128
#define KPH (FHID / 2)   // 128
#define KPO (FOUT / 2)   // 32

// ---------------- scratch (device globals) ------------------------------------
__device__ __align__(16) uint32_t g_X[NN * KP1];
__device__ __align__(16) uint32_t g_H0[KST * NN * KPH];
__device__ __align__(16) uint32_t g_H1[KST * NN * KPH];
__device__ __align__(16) uint32_t g_R1[KST * NN * KPH];
__device__ __align__(16) uint32_t g_HM[NN * KPH];
__device__ __align__(16) uint32_t g_G0[KST * NN * KPO];
__device__ __align__(16) uint32_t g_G1[KST * NN * KPO];
__device__ __align__(16) uint32_t g_R2[KST * NN * KPO];
__device__ __align__(16) uint32_t g_W1C[KST * 512 * KP1];
__device__ __align__(16) uint32_t g_W1[KST * 256 * KPH];
__device__ __align__(16) uint32_t g_W2C[KST * 128 * KPH];
__device__ __align__(16) uint32_t g_W2[KST * 64 * KPO];
__device__ float g_dis[NN];
__device__ int g_cnt[NN];
__device__ int g_rowptr[NN + 1];
__device__ int g_cursor[NN];
__device__ int g_src[NE];
__device__ float g_nrm[NE];
__device__ int g_is64;
#define SCAN_NBLK 118  // ceil(30000/256)
__device__ int g_bsum[SCAN_NBLK + 1];

// ---------------- helpers -----------------------------------------------------
__device__ __forceinline__ uint32_t pack_f16(float a, float b) {
    __half2 h = __floats2half2_rn(a, b);
    return *reinterpret_cast<uint32_t*>(&h);
}

__device__ __forceinline__ float2 h2f2(uint32_t u) {
    __half2 h = *reinterpret_cast<__half2*>(&u);
    return __half22float2(h);
}

__device__ __forceinline__ void mma_f16(float* c, const uint32_t* a, const uint32_t* bb) {
    asm volatile(
        "mma.sync.aligned.m16n8k16.row.col.f32.f16.f16.f32 "
        "{%0,%1,%2,%3}, {%4,%5,%6,%7}, {%8,%9}, {%0,%1,%2,%3};\n"
        : "+f"(c[0]), "+f"(c[1]), "+f"(c[2]), "+f"(c[3])
        : "r"(a[0]), "r"(a[1]), "r"(a[2]), "r"(a[3]), "r"(bb[0]), "r"(bb[1]));
}

__device__ __forceinline__ void ldsm4(uint32_t* r, uint32_t addr) {
    asm volatile("ldmatrix.sync.aligned.m8n8.x4.shared.b16 {%0,%1,%2,%3}, [%4];"
                 : "=r"(r[0]), "=r"(r[1]), "=r"(r[2]), "=r"(r[3])
                 : "r"(addr));
}

// ---------------- input conversion ---------------------------------------------
__global__ void split_x_kernel(const float* __restrict__ x) {
    long i = blockIdx.x * 256L + threadIdx.x;
    if (i < (long)NN * KP1) {
        float2 v = *(const float2*)(x + 2 * i);
        g_X[i] = pack_f16(v.x, v.y);
    }
}

__device__ __forceinline__ void wconv(const float* __restrict__ W, uint32_t* oh,
                                      int Kd, int N, int nOff, int outN, long idx) {
    int Kp = Kd / 2;
    int k = (int)(idx / ((long)N * Kp));
    int rem = (int)(idx % ((long)N * Kp));
    int n = rem / Kp;
    int kp = rem % Kp;
    const float* Wk = W + (long)k * Kd * N;
    float v0 = Wk[(long)(2 * kp) * N + n];
    float v1 = Wk[(long)(2 * kp + 1) * N + n];
    oh[((long)k * outN + nOff + n) * Kp + kp] = pack_f16(v0, v1);
}

#define CNT_A (KST * 256 * 128)
#define CNT_B (KST * 64 * 128)
#define CNT_C (KST * 64 * 32)

__global__ void split_weights_kernel(const float* iw1, const float* rw1,
                                     const float* w1, const float* iw2,
                                     const float* rw2, const float* w2) {
    long id = blockIdx.x * 256L + threadIdx.x;
    if (id < CNT_A) { wconv(iw1, g_W1C, 256, 256, 0, 512, id); return; }
    id -= CNT_A;
    if (id < CNT_A) { wconv(rw1, g_W1C, 256, 256, 256, 512, id); return; }
    id -= CNT_A;
    if (id < CNT_A) { wconv(w1, g_W1, 256, 256, 0, 256, id); return; }
    id -= CNT_A;
    if (id < CNT_B) { wconv(iw2, g_W2C, 256, 64, 0, 128, id); return; }
    id -= CNT_B;
    if (id < CNT_B) { wconv(rw2, g_W2C, 256, 64, 64, 128, id); return; }
    id -= CNT_B;
    if (id < CNT_C) { wconv(w2, g_W2, 64, 64, 0, 64, id); }
}

// ---------------- dtype sniff / CSR -------------------------------------------
__global__ void sniff_kernel(const int* __restrict__ ei_raw) {
    if (threadIdx.x == 0 && blockIdx.x == 0) {
        int all_zero = 1;
        for (int i = 0; i < 128; i++)
            if (ei_raw[2 * i + 1] != 0) { all_zero = 0; break; }
        g_is64 = all_zero;
    }
}

__device__ __forceinline__ int load_idx(const void* ei, long pos) {
    if (g_is64) return (int)((const long long*)ei)[pos];
    return ((const int*)ei)[pos];
}

__global__ void zero_cnt_kernel() {
    int i = blockIdx.x * blockDim.x + threadIdx.x;
    if (i < NN) g_cnt[i] = 0;
}

__global__ void count_deg_kernel(const void* __restrict__ ei) {
    int e = blockIdx.x * blockDim.x + threadIdx.x;
    if (e < NE) {
        int c = load_idx(ei, (long)NE + e);
        if (c >= 0 && c < NN) atomicAdd(&g_cnt[c], 1);
    }
}

__global__ void dis_kernel() {
    int i = blockIdx.x * blockDim.x + threadIdx.x;
    if (i < NN) {
        int c = g_cnt[i];
        g_dis[i] = (c > 0) ? rsqrtf((float)c) : 0.0f;
    }
}

// multi-block exclusive scan: per-block scan + block sums
__global__ void scan1_kernel() {
    __shared__ int sh[256];
    int blk = blockIdx.x;
    int i = blk * 256 + threadIdx.x;
    int v = (i < NN) ? g_cnt[i] : 0;
    sh[threadIdx.x] = v;
    __syncthreads();
    for (int d = 1; d < 256; d <<= 1) {
        int t = (threadIdx.x >= (unsigned)d) ? sh[threadIdx.x - d] : 0;
        __syncthreads();
        sh[threadIdx.x] += t;
        __syncthreads();
    }
    int incl = sh[threadIdx.x];
    if (i < NN) g_rowptr[i] = incl - v;  // local exclusive
    if (threadIdx.x == 255) g_bsum[blk] = incl;
}

__global__ void scan2_kernel() {  // scan 118 block sums (128 threads)
    __shared__ int sh[128];
    int v = (threadIdx.x < SCAN_NBLK) ? g_bsum[threadIdx.x] : 0;
    sh[threadIdx.x] = v;
    __syncthreads();
    for (int d = 1; d < 128; d <<= 1) {
        int t = (threadIdx.x >= (unsigned)d) ? sh[threadIdx.x - d] : 0;
        __syncthreads();
        sh[threadIdx.x] += t;
        __syncthreads();
    }
    int incl = sh[threadIdx.x];
    if (threadIdx.x < SCAN_NBLK) g_bsum[threadIdx.x] = incl - v;  // exclusive
    if (threadIdx.x == 127) g_bsum[SCAN_NBLK] = incl;             // total
}

__global__ void scan3_kernel() {
    int i = blockIdx.x * 256 + threadIdx.x;
    if (i < NN) {
        int ex = g_rowptr[i] + g_bsum[blockIdx.x];
        g_rowptr[i] = ex;
        g_cursor[i] = ex;
    }
    if (i == 0) g_rowptr[NN] = g_bsum[SCAN_NBLK];
}

__global__ void fill_csr_kernel(const void* __restrict__ ei) {
    int e = blockIdx.x * blockDim.x + threadIdx.x;
    if (e < NE) {
        int r = load_idx(ei, e);
        int c = load_idx(ei, (long)NE + e);
        if (r >= 0 && r < NN && c >= 0 && c < NN) {
            int pos = atomicAdd(&g_cursor[c], 1);
            if (pos >= 0 && pos < NE) {
                g_src[pos] = r;
                g_nrm[pos] = g_dis[r] * g_dis[c];
            }
        }
    }
}

// ---------------- fp16 tensor-core GEMM (4-stage, single sync/ktile) -----------
// C[b] = A[b] @ W[b]: fp16 MMA, fp32 accum. A fp16x2-packed [M][Kp];
// W pre-transposed [Ntot][Kp]. Dual-output epilogue.
// BM=128, BN=64, BK=32 (16 pairs), 4-stage cp.async, ldmatrix.x4 (pitch 80B).
#define APITCH 20
#define A_PLANE_B (128 * APITCH * 4)   // 10240 B
#define B_PLANE_B (64 * APITCH * 4)    // 5120 B
#define NSTAGE 4
#define B_OFF_B (NSTAGE * A_PLANE_B)   // 40960
#define GSMEM (NSTAGE * (A_PLANE_B + B_PLANE_B))  // 61440 -> 3 CTAs/SM

__global__ __launch_bounds__(256, 3)
void bgemm2(const uint32_t* __restrict__ A, long sA,
            const uint32_t* __restrict__ B, long sB,
            const float* __restrict__ bias, long sBias,
            uint32_t* __restrict__ C0, long sC0,
            uint32_t* __restrict__ C1, long sC1,
            int M, int Ntot, int N1, int Kd) {
    extern __shared__ uint32_t smem[];
    uint32_t smem_u = (uint32_t)__cvta_generic_to_shared(smem);
    int Kp = Kd >> 1;
    int b = blockIdx.z;
    const uint32_t* Ab = A + (long)b * sA;
    const uint32_t* Bb = B + (long)b * sB;
    int bm = blockIdx.y * 128, bn = blockIdx.x * 64;
    int tid = threadIdx.x, warp = tid >> 5, lane = tid & 31;
    int g = lane >> 2, t = lane & 3;
    int wm = warp >> 1, wn = warp & 1;

    int rowA = ((lane >> 3) & 1) * 8 + (lane & 7);
    int segA = (lane >> 4) * 4;
    int rowB = ((lane >> 4) & 1) * 8 + (lane & 7);
    int segB = ((lane >> 3) & 1) * 4;

    auto issue = [&](int kt) {
        int buf = kt & 3;
        int kp0 = kt * 16;
#pragma unroll
        for (int i = 0; i < 2; i++) {  // A: 512 16B chunks
            int ch = tid + i * 256;
            int row = ch >> 2, seg = ch & 3;
            int gm = bm + row;
            if (gm >= M) gm = M - 1;
            const uint32_t* src = Ab + (long)gm * Kp + kp0 + seg * 4;
            uint32_t dst = smem_u + buf * A_PLANE_B + (row * APITCH + seg * 4) * 4;
            asm volatile("cp.async.cg.shared.global [%0], [%1], 16;" ::"r"(dst), "l"(src));
        }
        {  // B: 256 chunks
            int row = tid >> 2, seg = tid & 3;
            const uint32_t* src = Bb + (long)(bn + row) * Kp + kp0 + seg * 4;
            uint32_t dst = smem_u + B_OFF_B + buf * B_PLANE_B + (row * APITCH + seg * 4) * 4;
            asm volatile("cp.async.cg.shared.global [%0], [%1], 16;" ::"r"(dst), "l"(src));
        }
        asm volatile("cp.async.commit_group;" ::: "memory");
    };

    float acc[2][4][4];
#pragma unroll
    for (int i = 0; i < 2; i++)
#pragma unroll
        for (int j = 0; j < 4; j++)
#pragma unroll
            for (int k = 0; k < 4; k++) acc[i][j][k] = 0.f;

    int NT = Kd / 32;
    for (int s = 0; s < 3 && s < NT; s++) issue(s);
    for (int kt = 0; kt < NT; kt++) {
        int buf = kt & 3;
        int rem = NT - kt;
        if (rem >= 3) {
            asm volatile("cp.async.wait_group 2;" ::: "memory");
        } else if (rem == 2) {
            asm volatile("cp.async.wait_group 1;" ::: "memory");
        } else {
            asm volatile("cp.async.wait_group 0;" ::: "memory");
        }
        __syncthreads();
        // buffer (kt+3)%4 == (kt-1)%4 is free: every warp past this sync has
        // finished compute(kt-1) in program order.
        if (kt + 3 < NT) issue(kt + 3);
#pragma unroll
        for (int ks = 0; ks < 2; ks++) {
            int kp0 = ks * 8;
            uint32_t af[2][4], bf[4][2];
            {
                uint32_t aBase = smem_u + buf * A_PLANE_B;
#pragma unroll
                for (int mt = 0; mt < 2; mt++) {
                    uint32_t addr =
                        aBase + ((wm * 32 + mt * 16 + rowA) * APITCH + kp0 + segA) * 4;
                    ldsm4(af[mt], addr);
                }
            }
            {
                uint32_t bBase = smem_u + B_OFF_B + buf * B_PLANE_B;
#pragma unroll
                for (int np = 0; np < 2; np++) {
                    uint32_t addr =
                        bBase + ((wn * 32 + np * 16 + rowB) * APITCH + kp0 + segB) * 4;
                    ldsm4(&bf[np * 2][0], addr);
                }
            }
#pragma unroll
            for (int mt = 0; mt < 2; mt++)
#pragma unroll
                for (int nt = 0; nt < 4; nt++) mma_f16(acc[mt][nt], af[mt], bf[nt]);
        }
    }

    // ---- epilogue: fp16-pack + dual-target store ----
    int row0 = bm + wm * 32;
    int col0 = bn + wn * 32;
#pragma unroll
    for (int nt = 0; nt < 4; nt++) {
        int c = col0 + nt * 8 + 2 * t;
        bool out1 = (c >= N1);
        float bx = 0.f, by = 0.f;
        uint32_t* O;
        long pitch;
        int cc;
        if (out1) {
            if (bias) {
                bx = bias[b * sBias + (c - N1)];
                by = bias[b * sBias + (c - N1) + 1];
            }
            O = C1 + (long)b * sC1;
            pitch = (Ntot - N1) >> 1;
            cc = (c - N1) >> 1;
        } else {
            O = C0 + (long)b * sC0;
            pitch = N1 >> 1;
            cc = c >> 1;
        }
#pragma unroll
        for (int mt = 0; mt < 2; mt++) {
            int r = row0 + mt * 16 + g;
            if (r < M)
                O[(long)r * pitch + cc] = pack_f16(acc[mt][nt][0] + bx, acc[mt][nt][1] + by);
            if (r + 8 < M)
                O[(long)(r + 8) * pitch + cc] =
                    pack_f16(acc[mt][nt][2] + bx, acc[mt][nt][3] + by);
        }
    }
}

// ---------------- propagation (CSR gather on fp16) ------------------------------
template <int F, bool RELU>
__global__ void prop_kernel(const uint32_t* __restrict__ H,
                            const uint32_t* __restrict__ R,
                            uint32_t* __restrict__ O) {
    constexpr int LANES = F / 4;
    constexpr int NPB = 256 / LANES;
    constexpr int PITCH = F / 2;
    int lane = threadIdx.x % LANES;
    int local = threadIdx.x / LANES;
    int n = blockIdx.x * NPB + local;
    int k = blockIdx.y;
    if (n >= NN) return;
    long base = (long)k * NN * PITCH;
    const uint32_t* Hk = H + base;
    int e0 = g_rowptr[n], e1 = g_rowptr[n + 1];
    float4 acc = make_float4(0.f, 0.f, 0.f, 0.f);
#pragma unroll 2
    for (int e = e0; e < e1; e++) {
        int s = g_src[e];
        float w = g_nrm[e];
        uint2 hh = *(const uint2*)(Hk + (long)s * PITCH + lane * 2);
        float2 v0 = h2f2(hh.x);
        float2 v1 = h2f2(hh.y);
        acc.x += w * v0.x;
        acc.y += w * v0.y;
        acc.z += w * v1.x;
        acc.w += w * v1.y;
    }
    long off = base + (long)n * PITCH + lane * 2;
    uint2 rr = *(const uint2*)(R + off);
    float2 r0 = h2f2(rr.x), r1 = h2f2(rr.y);
    acc.x += r0.x;
    acc.y += r0.y;
    acc.z += r1.x;
    acc.w += r1.y;
    if (RELU) {
        acc.x = fmaxf(acc.x, 0.f);
        acc.y = fmaxf(acc.y, 0.f);
        acc.z = fmaxf(acc.z, 0.f);
        acc.w = fmaxf(acc.w, 0.f);
    }
    *(uint2*)(O + off) = make_uint2(pack_f16(acc.x, acc.y), pack_f16(acc.z, acc.w));
}

// ---------------- mean over stacks ---------------------------------------------
__global__ void mean_kernel() {
    long i = blockIdx.x * 256L + threadIdx.x;
    const long st = (long)NN * KPH;
    if (i < st) {
        float2 s = make_float2(0.f, 0.f);
#pragma unroll
        for (int k = 0; k < KST; k++) {
            float2 h = h2f2(g_H1[i + k * st]);
            s.x += h.x;
            s.y += h.y;
        }
        g_HM[i] = pack_f16(s.x * (1.0f / 3.0f), s.y * (1.0f / 3.0f));
    }
}

// ---------------- final: mean over stacks + log_softmax -------------------------
__global__ void final_kernel(float* __restrict__ out) {
    int n = blockIdx.x;
    int f = threadIdx.x;  // 64 threads
    const long st = (long)NN * KPO;
    long p = (long)n * KPO + (f >> 1);
    float v = 0.f;
#pragma unroll
    for (int k = 0; k < KST; k++) {
        float2 h = h2f2(g_G1[p + k * st]);
        v += (f & 1) ? h.y : h.x;
    }
    v *= (1.0f / 3.0f);
    float m = v;
#pragma unroll
    for (int d = 16; d; d >>= 1) m = fmaxf(m, __shfl_xor_sync(0xffffffffu, m, d));
    __shared__ float sm[2], ss[2];
    int w = threadIdx.x >> 5;
    if ((threadIdx.x & 31) == 0) sm[w] = m;
    __syncthreads();
    m = fmaxf(sm[0], sm[1]);
    float e = expf(v - m);
    float s = e;
#pragma unroll
    for (int d = 16; d; d >>= 1) s += __shfl_xor_sync(0xffffffffu, s, d);
    if ((threadIdx.x & 31) == 0) ss[w] = s;
    __syncthreads();
    s = ss[0] + ss[1];
    out[(long)n * FOUT + f] = v - m - logf(s);
}

// ---------------- launch ---------------------------------------------------------
extern "C" void kernel_launch(void* const* d_in, const int* in_sizes, int n_in,
                              void* d_out, int out_size) {
    const float* x = (const float*)d_in[0];
    const void* ei = d_in[1];
    const float* init_w1 = (const float*)d_in[2];
    const float* w1 = (const float*)d_in[3];
    const float* root_w1 = (const float*)d_in[4];
    const float* bias1 = (const float*)d_in[5];
    const float* init_w2 = (const float*)d_in[6];
    const float* w2 = (const float*)d_in[7];
    const float* root_w2 = (const float*)d_in[8];
    const float* bias2 = (const float*)d_in[9];
    float* out = (float*)d_out;

    static bool attr_set = false;
    if (!attr_set) {
        cudaFuncSetAttribute(bgemm2, cudaFuncAttributeMaxDynamicSharedMemorySize, GSMEM);
        attr_set = true;
    }

    uint32_t *X, *H0, *H1, *R1, *HM, *G0, *G1, *R2;
    uint32_t *W1C, *W1, *W2C, *W2;
    cudaGetSymbolAddress((void**)&X, g_X);
    cudaGetSymbolAddress((void**)&H0, g_H0);
    cudaGetSymbolAddress((void**)&H1, g_H1);
    cudaGetSymbolAddress((void**)&R1, g_R1);
    cudaGetSymbolAddress((void**)&HM, g_HM);
    cudaGetSymbolAddress((void**)&G0, g_G0);
    cudaGetSymbolAddress((void**)&G1, g_G1);
    cudaGetSymbolAddress((void**)&R2, g_R2);
    cudaGetSymbolAddress((void**)&W1C, g_W1C);
    cudaGetSymbolAddress((void**)&W1, g_W1);
    cudaGetSymbolAddress((void**)&W2C, g_W2C);
    cudaGetSymbolAddress((void**)&W2, g_W2);

    const int MY = (NN + 127) / 128;  // 235

    // 0-2: prep
    split_x_kernel<<<(NN * KP1 + 255) / 256, 256>>>(x);
    split_weights_kernel<<<(3 * CNT_A + 2 * CNT_B + CNT_C + 255) / 256, 256>>>(
        init_w1, root_w1, w1, init_w2, root_w2, w2);
    zero_cnt_kernel<<<(NN + 255) / 256, 256>>>();
    // 3: fused conv1 GEMM — ncu capture slot
    dim3 gc1(512 / 64, MY, KST);
    bgemm2<<<gc1, 256, GSMEM>>>(X, 0, W1C, (long)512 * KP1, bias1, FHID,
                                H0, (long)NN * KPH, R1, (long)NN * KPH,
                                NN, 512, 256, FIN);
    // CSR build
    sniff_kernel<<<1, 32>>>((const int*)ei);
    count_deg_kernel<<<(NE + 255) / 256, 256>>>(ei);
    dis_kernel<<<(NN + 255) / 256, 256>>>();
    scan1_kernel<<<SCAN_NBLK, 256>>>();
    scan2_kernel<<<1, 128>>>();
    scan3_kernel<<<SCAN_NBLK, 256>>>();
    fill_csr_kernel<<<(NE + 255) / 256, 256>>>(ei);

    // conv1 body
    dim3 gp1((NN + 3) / 4, KST);
    prop_kernel<FHID, true><<<gp1, 256>>>(H0, R1, H1);
    dim3 gw1(256 / 64, MY, KST);
    bgemm2<<<gw1, 256, GSMEM>>>(H1, (long)NN * KPH, W1, (long)256 * KPH,
                                nullptr, 0, H0, (long)NN * KPH, nullptr, 0,
                                NN, 256, 256, FHID);
    prop_kernel<FHID, true><<<gp1, 256>>>(H0, R1, H1);
    mean_kernel<<<(NN * KPH + 255) / 256, 256>>>();

    // conv2
    dim3 gc2(128 / 64, MY, KST);
    bgemm2<<<gc2, 256, GSMEM>>>(HM, 0, W2C, (long)128 * KPH, bias2, FOUT,
                                G0, (long)NN * KPO, R2, (long)NN * KPO,
                                NN, 128, 64, FHID);
    dim3 gp2((NN + 15) / 16, KST);
    prop_kernel<FOUT, false><<<gp2, 256>>>(G0, R2, G1);
    dim3 gw2(1, MY, KST);
    bgemm2<<<gw2, 256, GSMEM>>>(G1, (long)NN * KPO, W2, (long)64 * KPO,
                                nullptr, 0, G0, (long)NN * KPO, nullptr, 0,
                                NN, 64, 64, FOUT);
    prop_kernel<FOUT, false><<<gp2, 256>>>(G0, R2, G1);

    final_kernel<<<NN, FOUT>>>(out);
}

// round 12
// speedup vs baseline: 1.9698x; 1.0195x over previous
#include <cuda_runtime.h>
#include <cuda_fp16.h>
#include <math.h>
#include <stdint.h>

#define KST 3
#define NN 30000
#define NE 300000
#define FIN 256
#define FHID 256
#define FOUT 64
#define KP1 (FIN / 2)    // 128
#define KPH (FHID / 2)   // 128
#define KPO (FOUT / 2)   // 32

// ---------------- scratch (device globals) ------------------------------------
__device__ __align__(16) uint32_t g_X[NN * KP1];
__device__ __align__(16) uint32_t g_H0[KST * NN * KPH];
__device__ __align__(16) uint32_t g_H1[KST * NN * KPH];
__device__ __align__(16) uint32_t g_R1[KST * NN * KPH];
__device__ __align__(16) uint32_t g_HM[NN * KPH];
__device__ __align__(16) uint32_t g_G0[KST * NN * KPO];
__device__ __align__(16) uint32_t g_G1[KST * NN * KPO];
__device__ __align__(16) uint32_t g_R2[KST * NN * KPO];
__device__ __align__(16) uint32_t g_W1C[KST * 512 * KP1];
__device__ __align__(16) uint32_t g_W1[KST * 256 * KPH];
__device__ __align__(16) uint32_t g_W2C[KST * 128 * KPH];
__device__ __align__(16) uint32_t g_W2[KST * 64 * KPO];
__device__ float g_dis[NN];
__device__ int g_cnt[NN];
__device__ int g_rowptr[NN + 1];
__device__ int g_cursor[NN];
__device__ int g_src[NE];
__device__ float g_nrm[NE];
__device__ int g_is64;
#define SCAN_NBLK 118  // ceil(30000/256)
__device__ int g_bsum[SCAN_NBLK + 1];

// ---------------- helpers -----------------------------------------------------
__device__ __forceinline__ uint32_t pack_f16(float a, float b) {
    __half2 h = __floats2half2_rn(a, b);
    return *reinterpret_cast<uint32_t*>(&h);
}

__device__ __forceinline__ float2 h2f2(uint32_t u) {
    __half2 h = *reinterpret_cast<__half2*>(&u);
    return __half22float2(h);
}

__device__ __forceinline__ void mma_f16(float* c, const uint32_t* a, const uint32_t* bb) {
    asm volatile(
        "mma.sync.aligned.m16n8k16.row.col.f32.f16.f16.f32 "
        "{%0,%1,%2,%3}, {%4,%5,%6,%7}, {%8,%9}, {%0,%1,%2,%3};\n"
        : "+f"(c[0]), "+f"(c[1]), "+f"(c[2]), "+f"(c[3])
        : "r"(a[0]), "r"(a[1]), "r"(a[2]), "r"(a[3]), "r"(bb[0]), "r"(bb[1]));
}

__device__ __forceinline__ void ldsm4(uint32_t* r, uint32_t addr) {
    asm volatile("ldmatrix.sync.aligned.m8n8.x4.shared.b16 {%0,%1,%2,%3}, [%4];"
                 : "=r"(r[0]), "=r"(r[1]), "=r"(r[2]), "=r"(r[3])
                 : "r"(addr));
}

__device__ __forceinline__ void cpasync16(uint32_t dst, const uint32_t* src) {
    asm volatile("cp.async.cg.shared.global [%0], [%1], 16;" ::"r"(dst), "l"(src));
}

// ---------------- input conversion ---------------------------------------------
__global__ void split_x_kernel(const float* __restrict__ x) {
    long i = blockIdx.x * 256L + threadIdx.x;
    if (i < (long)NN * KP1) {
        float2 v = *(const float2*)(x + 2 * i);
        g_X[i] = pack_f16(v.x, v.y);
    }
}

__device__ __forceinline__ void wconv(const float* __restrict__ W, uint32_t* oh,
                                      int Kd, int N, int nOff, int outN, long idx) {
    int Kp = Kd / 2;
    int k = (int)(idx / ((long)N * Kp));
    int rem = (int)(idx % ((long)N * Kp));
    int n = rem / Kp;
    int kp = rem % Kp;
    const float* Wk = W + (long)k * Kd * N;
    float v0 = Wk[(long)(2 * kp) * N + n];
    float v1 = Wk[(long)(2 * kp + 1) * N + n];
    oh[((long)k * outN + nOff + n) * Kp + kp] = pack_f16(v0, v1);
}

#define CNT_A (KST * 256 * 128)
#define CNT_B (KST * 64 * 128)
#define CNT_C (KST * 64 * 32)

__global__ void split_weights_kernel(const float* iw1, const float* rw1,
                                     const float* w1, const float* iw2,
                                     const float* rw2, const float* w2) {
    long id = blockIdx.x * 256L + threadIdx.x;
    if (id < CNT_A) { wconv(iw1, g_W1C, 256, 256, 0, 512, id); return; }
    id -= CNT_A;
    if (id < CNT_A) { wconv(rw1, g_W1C, 256, 256, 256, 512, id); return; }
    id -= CNT_A;
    if (id < CNT_A) { wconv(w1, g_W1, 256, 256, 0, 256, id); return; }
    id -= CNT_A;
    if (id < CNT_B) { wconv(iw2, g_W2C, 256, 64, 0, 128, id); return; }
    id -= CNT_B;
    if (id < CNT_B) { wconv(rw2, g_W2C, 256, 64, 64, 128, id); return; }
    id -= CNT_C + CNT_B - CNT_C;
    if (id < CNT_C) { wconv(w2, g_W2, 64, 64, 0, 64, id); }
}

// ---------------- CSR ----------------------------------------------------------
// zero counts + dtype sniff in one launch
__global__ void zero_sniff_kernel(const int* __restrict__ ei_raw) {
    int i = blockIdx.x * blockDim.x + threadIdx.x;
    if (i < NN) g_cnt[i] = 0;
    if (i == 0) {
        int all_zero = 1;
        for (int j = 0; j < 128; j++)
            if (ei_raw[2 * j + 1] != 0) { all_zero = 0; break; }
        g_is64 = all_zero;
    }
}

__device__ __forceinline__ int load_idx(const void* ei, long pos) {
    if (g_is64) return (int)((const long long*)ei)[pos];
    return ((const int*)ei)[pos];
}

__global__ void count_deg_kernel(const void* __restrict__ ei) {
    int e = blockIdx.x * blockDim.x + threadIdx.x;
    if (e < NE) {
        int c = load_idx(ei, (long)NE + e);
        if (c >= 0 && c < NN) atomicAdd(&g_cnt[c], 1);
    }
}

// per-block scan + block sums + dis computation fused
__global__ void scan1_kernel() {
    __shared__ int sh[256];
    int blk = blockIdx.x;
    int i = blk * 256 + threadIdx.x;
    int v = (i < NN) ? g_cnt[i] : 0;
    if (i < NN) g_dis[i] = (v > 0) ? rsqrtf((float)v) : 0.0f;
    sh[threadIdx.x] = v;
    __syncthreads();
    for (int d = 1; d < 256; d <<= 1) {
        int t = (threadIdx.x >= (unsigned)d) ? sh[threadIdx.x - d] : 0;
        __syncthreads();
        sh[threadIdx.x] += t;
        __syncthreads();
    }
    int incl = sh[threadIdx.x];
    if (i < NN) g_rowptr[i] = incl - v;  // local exclusive
    if (threadIdx.x == 255) g_bsum[blk] = incl;
}

__global__ void scan2_kernel() {
    __shared__ int sh[128];
    int v = (threadIdx.x < SCAN_NBLK) ? g_bsum[threadIdx.x] : 0;
    sh[threadIdx.x] = v;
    __syncthreads();
    for (int d = 1; d < 128; d <<= 1) {
        int t = (threadIdx.x >= (unsigned)d) ? sh[threadIdx.x - d] : 0;
        __syncthreads();
        sh[threadIdx.x] += t;
        __syncthreads();
    }
    int incl = sh[threadIdx.x];
    if (threadIdx.x < SCAN_NBLK) g_bsum[threadIdx.x] = incl - v;
    if (threadIdx.x == 127) g_bsum[SCAN_NBLK] = incl;
}

__global__ void scan3_kernel() {
    int i = blockIdx.x * 256 + threadIdx.x;
    if (i < NN) {
        int ex = g_rowptr[i] + g_bsum[blockIdx.x];
        g_rowptr[i] = ex;
        g_cursor[i] = ex;
    }
    if (i == 0) g_rowptr[NN] = g_bsum[SCAN_NBLK];
}

__global__ void fill_csr_kernel(const void* __restrict__ ei) {
    int e = blockIdx.x * blockDim.x + threadIdx.x;
    if (e < NE) {
        int r = load_idx(ei, e);
        int c = load_idx(ei, (long)NE + e);
        if (r >= 0 && r < NN && c >= 0 && c < NN) {
            int pos = atomicAdd(&g_cursor[c], 1);
            if (pos >= 0 && pos < NE) {
                g_src[pos] = r;
                g_nrm[pos] = g_dis[r] * g_dis[c];
            }
        }
    }
}

// ---------------- fp16 tensor-core GEMM (4-stage, hoisted addressing) ----------
// C[b] = A[b] @ W[b]: fp16 MMA, fp32 accum. A fp16x2-packed [M][Kp];
// W pre-transposed [Ntot][Kp]. Dual-output epilogue.
// BM=128, BN=64, BK=32 (16 pairs), 4-stage cp.async, ldmatrix.x4 (pitch 80B).
#define APITCH 20
#define A_PLANE_B (128 * APITCH * 4)   // 10240 B
#define B_PLANE_B (64 * APITCH * 4)    // 5120 B
#define NSTAGE 4
#define B_OFF_B (NSTAGE * A_PLANE_B)   // 40960
#define GSMEM (NSTAGE * (A_PLANE_B + B_PLANE_B))  // 61440 -> 3 CTAs/SM

__global__ __launch_bounds__(256, 3)
void bgemm2(const uint32_t* __restrict__ A, long sA,
            const uint32_t* __restrict__ B, long sB,
            const float* __restrict__ bias, long sBias,
            uint32_t* __restrict__ C0, long sC0,
            uint32_t* __restrict__ C1, long sC1,
            int M, int Ntot, int N1, int Kd) {
    extern __shared__ uint32_t smem[];
    uint32_t smem_u = (uint32_t)__cvta_generic_to_shared(smem);
    int Kp = Kd >> 1;
    int b = blockIdx.z;
    int bm = blockIdx.y * 128, bn = blockIdx.x * 64;
    int tid = threadIdx.x, warp = tid >> 5, lane = tid & 31;
    int g = lane >> 2, t = lane & 3;
    int wm = warp >> 1, wn = warp & 1;

    // ---- hoisted per-thread cp.async addressing ----
    int rowL = tid >> 2, segL = tid & 3;  // load row/seg
    int gm0 = bm + rowL;       if (gm0 >= M) gm0 = M - 1;
    int gm1 = bm + rowL + 64;  if (gm1 >= M) gm1 = M - 1;
    const uint32_t* sA0 = A + (long)b * sA + (long)gm0 * Kp + segL * 4;
    const uint32_t* sA1 = A + (long)b * sA + (long)gm1 * Kp + segL * 4;
    const uint32_t* sB0 = B + (long)b * sB + (long)(bn + rowL) * Kp + segL * 4;
    uint32_t dA0 = smem_u + (rowL * APITCH + segL * 4) * 4;
    uint32_t dA1 = dA0 + 64 * APITCH * 4;
    uint32_t dB0 = smem_u + B_OFF_B + (rowL * APITCH + segL * 4) * 4;

    // ---- hoisted ldsm offsets ----
    int rowA = ((lane >> 3) & 1) * 8 + (lane & 7);
    int segA = (lane >> 4) * 4;
    int rowB = ((lane >> 4) & 1) * 8 + (lane & 7);
    int segB = ((lane >> 3) & 1) * 4;
    uint32_t aOff0 = smem_u + ((wm * 32 + rowA) * APITCH + segA) * 4;
    uint32_t aOff1 = aOff0 + 16 * APITCH * 4;
    uint32_t bOff0 = smem_u + B_OFF_B + ((wn * 32 + rowB) * APITCH + segB) * 4;
    uint32_t bOff1 = bOff0 + 16 * APITCH * 4;

    auto issue = [&](int kt) {
        uint32_t aD = kt * (int)A_PLANE_B;  // kt pre-masked by caller via &3
        uint32_t bD = kt * (int)B_PLANE_B;
        cpasync16(dA0 + aD, sA0);
        cpasync16(dA1 + aD, sA1);
        cpasync16(dB0 + bD, sB0);
        sA0 += 16;
        sA1 += 16;
        sB0 += 16;
        asm volatile("cp.async.commit_group;" ::: "memory");
    };

    float acc[2][4][4];
#pragma unroll
    for (int i = 0; i < 2; i++)
#pragma unroll
        for (int j = 0; j < 4; j++)
#pragma unroll
            for (int k = 0; k < 4; k++) acc[i][j][k] = 0.f;

    int NT = Kd / 32;
    for (int s = 0; s < 3 && s < NT; s++) issue(s & 3);
    for (int kt = 0; kt < NT; kt++) {
        int buf = kt & 3;
        int rem = NT - kt;
        if (rem >= 3) {
            asm volatile("cp.async.wait_group 2;" ::: "memory");
        } else if (rem == 2) {
            asm volatile("cp.async.wait_group 1;" ::: "memory");
        } else {
            asm volatile("cp.async.wait_group 0;" ::: "memory");
        }
        __syncthreads();
        if (kt + 3 < NT) issue((kt + 3) & 3);
        uint32_t aBase = buf * (uint32_t)A_PLANE_B;
        uint32_t bBase = buf * (uint32_t)B_PLANE_B;
#pragma unroll
        for (int ks = 0; ks < 2; ks++) {
            uint32_t ko = ks * 32;  // 8 u32 pairs = 32 bytes
            uint32_t af[2][4], bf[4][2];
            ldsm4(af[0], aOff0 + aBase + ko);
            ldsm4(af[1], aOff1 + aBase + ko);
            ldsm4(&bf[0][0], bOff0 + bBase + ko);
            ldsm4(&bf[2][0], bOff1 + bBase + ko);
#pragma unroll
            for (int mt = 0; mt < 2; mt++)
#pragma unroll
                for (int nt = 0; nt < 4; nt++) mma_f16(acc[mt][nt], af[mt], bf[nt]);
        }
    }

    // ---- epilogue: fp16-pack + dual-target store ----
    int row0 = bm + wm * 32;
    int col0 = bn + wn * 32;
#pragma unroll
    for (int nt = 0; nt < 4; nt++) {
        int c = col0 + nt * 8 + 2 * t;
        bool out1 = (c >= N1);
        float bx = 0.f, by = 0.f;
        uint32_t* O;
        long pitch;
        int cc;
        if (out1) {
            if (bias) {
                bx = bias[b * sBias + (c - N1)];
                by = bias[b * sBias + (c - N1) + 1];
            }
            O = C1 + (long)b * sC1;
            pitch = (Ntot - N1) >> 1;
            cc = (c - N1) >> 1;
        } else {
            O = C0 + (long)b * sC0;
            pitch = N1 >> 1;
            cc = c >> 1;
        }
#pragma unroll
        for (int mt = 0; mt < 2; mt++) {
            int r = row0 + mt * 16 + g;
            if (r < M)
                O[(long)r * pitch + cc] = pack_f16(acc[mt][nt][0] + bx, acc[mt][nt][1] + by);
            if (r + 8 < M)
                O[(long)(r + 8) * pitch + cc] =
                    pack_f16(acc[mt][nt][2] + bx, acc[mt][nt][3] + by);
        }
    }
}

// ---------------- propagation (CSR gather on fp16) ------------------------------
template <int F, bool RELU>
__global__ void prop_kernel(const uint32_t* __restrict__ H,
                            const uint32_t* __restrict__ R,
                            uint32_t* __restrict__ O) {
    constexpr int LANES = F / 4;
    constexpr int NPB = 256 / LANES;
    constexpr int PITCH = F / 2;
    int lane = threadIdx.x % LANES;
    int local = threadIdx.x / LANES;
    int n = blockIdx.x * NPB + local;
    int k = blockIdx.y;
    if (n >= NN) return;
    long base = (long)k * NN * PITCH;
    const uint32_t* Hk = H + base;
    int e0 = g_rowptr[n], e1 = g_rowptr[n + 1];
    float4 acc = make_float4(0.f, 0.f, 0.f, 0.f);
#pragma unroll 4
    for (int e = e0; e < e1; e++) {
        int s = g_src[e];
        float w = g_nrm[e];
        uint2 hh = *(const uint2*)(Hk + (long)s * PITCH + lane * 2);
        float2 v0 = h2f2(hh.x);
        float2 v1 = h2f2(hh.y);
        acc.x += w * v0.x;
        acc.y += w * v0.y;
        acc.z += w * v1.x;
        acc.w += w * v1.y;
    }
    long off = base + (long)n * PITCH + lane * 2;
    uint2 rr = *(const uint2*)(R + off);
    float2 r0 = h2f2(rr.x), r1 = h2f2(rr.y);
    acc.x += r0.x;
    acc.y += r0.y;
    acc.z += r1.x;
    acc.w += r1.y;
    if (RELU) {
        acc.x = fmaxf(acc.x, 0.f);
        acc.y = fmaxf(acc.y, 0.f);
        acc.z = fmaxf(acc.z, 0.f);
        acc.w = fmaxf(acc.w, 0.f);
    }
    *(uint2*)(O + off) = make_uint2(pack_f16(acc.x, acc.y), pack_f16(acc.z, acc.w));
}

// ---------------- mean over stacks ---------------------------------------------
__global__ void mean_kernel() {
    long i = blockIdx.x * 256L + threadIdx.x;
    const long st = (long)NN * KPH;
    if (i < st) {
        float2 s = make_float2(0.f, 0.f);
#pragma unroll
        for (int k = 0; k < KST; k++) {
            float2 h = h2f2(g_H1[i + k * st]);
            s.x += h.x;
            s.y += h.y;
        }
        g_HM[i] = pack_f16(s.x * (1.0f / 3.0f), s.y * (1.0f / 3.0f));
    }
}

// ---------------- final: mean over stacks + log_softmax -------------------------
__global__ void final_kernel(float* __restrict__ out) {
    int n = blockIdx.x;
    int f = threadIdx.x;  // 64 threads
    const long st = (long)NN * KPO;
    long p = (long)n * KPO + (f >> 1);
    float v = 0.f;
#pragma unroll
    for (int k = 0; k < KST; k++) {
        float2 h = h2f2(g_G1[p + k * st]);
        v += (f & 1) ? h.y : h.x;
    }
    v *= (1.0f / 3.0f);
    float m = v;
#pragma unroll
    for (int d = 16; d; d >>= 1) m = fmaxf(m, __shfl_xor_sync(0xffffffffu, m, d));
    __shared__ float sm[2], ss[2];
    int w = threadIdx.x >> 5;
    if ((threadIdx.x & 31) == 0) sm[w] = m;
    __syncthreads();
    m = fmaxf(sm[0], sm[1]);
    float e = expf(v - m);
    float s = e;
#pragma unroll
    for (int d = 16; d; d >>= 1) s += __shfl_xor_sync(0xffffffffu, s, d);
    if ((threadIdx.x & 31) == 0) ss[w] = s;
    __syncthreads();
    s = ss[0] + ss[1];
    out[(long)n * FOUT + f] = v - m - logf(s);
}

// ---------------- launch ---------------------------------------------------------
extern "C" void kernel_launch(void* const* d_in, const int* in_sizes, int n_in,
                              void* d_out, int out_size) {
    const float* x = (const float*)d_in[0];
    const void* ei = d_in[1];
    const float* init_w1 = (const float*)d_in[2];
    const float* w1 = (const float*)d_in[3];
    const float* root_w1 = (const float*)d_in[4];
    const float* bias1 = (const float*)d_in[5];
    const float* init_w2 = (const float*)d_in[6];
    const float* w2 = (const float*)d_in[7];
    const float* root_w2 = (const float*)d_in[8];
    const float* bias2 = (const float*)d_in[9];
    float* out = (float*)d_out;

    static bool attr_set = false;
    if (!attr_set) {
        cudaFuncSetAttribute(bgemm2, cudaFuncAttributeMaxDynamicSharedMemorySize, GSMEM);
        attr_set = true;
    }

    uint32_t *X, *H0, *H1, *R1, *HM, *G0, *G1, *R2;
    uint32_t *W1C, *W1, *W2C, *W2;
    cudaGetSymbolAddress((void**)&X, g_X);
    cudaGetSymbolAddress((void**)&H0, g_H0);
    cudaGetSymbolAddress((void**)&H1, g_H1);
    cudaGetSymbolAddress((void**)&R1, g_R1);
    cudaGetSymbolAddress((void**)&HM, g_HM);
    cudaGetSymbolAddress((void**)&G0, g_G0);
    cudaGetSymbolAddress((void**)&G1, g_G1);
    cudaGetSymbolAddress((void**)&R2, g_R2);
    cudaGetSymbolAddress((void**)&W1C, g_W1C);
    cudaGetSymbolAddress((void**)&W1, g_W1);
    cudaGetSymbolAddress((void**)&W2C, g_W2C);
    cudaGetSymbolAddress((void**)&W2, g_W2);

    const int MY = (NN + 127) / 128;  // 235

    // 0-2: prep
    split_x_kernel<<<(NN * KP1 + 255) / 256, 256>>>(x);
    split_weights_kernel<<<(3 * CNT_A + 2 * CNT_B + CNT_C + 255) / 256, 256>>>(
        init_w1, root_w1, w1, init_w2, root_w2, w2);
    zero_sniff_kernel<<<(NN + 255) / 256, 256>>>((const int*)ei);
    // 3: fused conv1 GEMM — ncu capture slot
    dim3 gc1(512 / 64, MY, KST);
    bgemm2<<<gc1, 256, GSMEM>>>(X, 0, W1C, (long)512 * KP1, bias1, FHID,
                                H0, (long)NN * KPH, R1, (long)NN * KPH,
                                NN, 512, 256, FIN);
    // CSR build
    count_deg_kernel<<<(NE + 255) / 256, 256>>>(ei);
    scan1_kernel<<<SCAN_NBLK, 256>>>();
    scan2_kernel<<<1, 128>>>();
    scan3_kernel<<<SCAN_NBLK, 256>>>();
    fill_csr_kernel<<<(NE + 255) / 256, 256>>>(ei);

    // conv1 body
    dim3 gp1((NN + 3) / 4, KST);
    prop_kernel<FHID, true><<<gp1, 256>>>(H0, R1, H1);
    dim3 gw1(256 / 64, MY, KST);
    bgemm2<<<gw1, 256, GSMEM>>>(H1, (long)NN * KPH, W1, (long)256 * KPH,
                                nullptr, 0, H0, (long)NN * KPH, nullptr, 0,
                                NN, 256, 256, FHID);
    prop_kernel<FHID, true><<<gp1, 256>>>(H0, R1, H1);
    mean_kernel<<<(NN * KPH + 255) / 256, 256>>>();

    // conv2
    dim3 gc2(128 / 64, MY, KST);
    bgemm2<<<gc2, 256, GSMEM>>>(HM, 0, W2C, (long)128 * KPH, bias2, FOUT,
                                G0, (long)NN * KPO, R2, (long)NN * KPO,
                                NN, 128, 64, FHID);
    dim3 gp2((NN + 15) / 16, KST);
    prop_kernel<FOUT, false><<<gp2, 256>>>(G0, R2, G1);
    dim3 gw2(1, MY, KST);
    bgemm2<<<gw2, 256, GSMEM>>>(G1, (long)NN * KPO, W2, (long)64 * KPO,
                                nullptr, 0, G0, (long)NN * KPO, nullptr, 0,
                                NN, 64, 64, FOUT);
    prop_kernel<FOUT, false><<<gp2, 256>>>(G0, R2, G1);

    final_kernel<<<NN, FOUT>>>(out);
}

// round 13
// speedup vs baseline: 2.1088x; 1.0705x over previous
#include <cuda_runtime.h>
#include <cuda_fp16.h>
#include <math.h>
#include <stdint.h>

#define KST 3
#define NN 30000
#define NE 300000
#define FIN 256
#define FHID 256
#define FOUT 64
#define KP1 (FIN / 2)    // 128
#define KPH (FHID / 2)   // 128
#define KPO (FOUT / 2)   // 32

// ---------------- scratch (device globals) ------------------------------------
__device__ __align__(16) uint32_t g_X[NN * KP1];
__device__ __align__(16) uint32_t g_H0[KST * NN * KPH];
__device__ __align__(16) uint32_t g_H1[KST * NN * KPH];
__device__ __align__(16) uint32_t g_R1[KST * NN * KPH];
__device__ __align__(16) uint32_t g_HM[NN * KPH];
__device__ __align__(16) uint32_t g_G0[KST * NN * KPO];
__device__ __align__(16) uint32_t g_G1[KST * NN * KPO];
__device__ __align__(16) uint32_t g_R2[KST * NN * KPO];
__device__ __align__(16) uint32_t g_W1C[KST * 512 * KP1];
__device__ __align__(16) uint32_t g_W1[KST * 256 * KPH];
__device__ __align__(16) uint32_t g_W2C[KST * 128 * KPH];
__device__ __align__(16) uint32_t g_W2[KST * 64 * KPO];
__device__ float g_dis[NN];
__device__ int g_cnt[NN];
__device__ int g_rowptr[NN + 1];
__device__ int g_cursor[NN];
__device__ int g_src[NE];
__device__ float g_nrm[NE];
__device__ int g_is64;
#define SCAN_NBLK 118
__device__ int g_bsum[SCAN_NBLK + 1];

// ---------------- helpers -----------------------------------------------------
__device__ __forceinline__ uint32_t pack_f16(float a, float b) {
    __half2 h = __floats2half2_rn(a, b);
    return *reinterpret_cast<uint32_t*>(&h);
}

__device__ __forceinline__ float2 h2f2(uint32_t u) {
    __half2 h = *reinterpret_cast<__half2*>(&u);
    return __half22float2(h);
}

__device__ __forceinline__ void mma_f16(float* c, const uint32_t* a, const uint32_t* bb) {
    asm volatile(
        "mma.sync.aligned.m16n8k16.row.col.f32.f16.f16.f32 "
        "{%0,%1,%2,%3}, {%4,%5,%6,%7}, {%8,%9}, {%0,%1,%2,%3};\n"
        : "+f"(c[0]), "+f"(c[1]), "+f"(c[2]), "+f"(c[3])
        : "r"(a[0]), "r"(a[1]), "r"(a[2]), "r"(a[3]), "r"(bb[0]), "r"(bb[1]));
}

__device__ __forceinline__ void ldsm4(uint32_t* r, uint32_t addr) {
    asm volatile("ldmatrix.sync.aligned.m8n8.x4.shared.b16 {%0,%1,%2,%3}, [%4];"
                 : "=r"(r[0]), "=r"(r[1]), "=r"(r[2]), "=r"(r[3])
                 : "r"(addr));
}

__device__ __forceinline__ void cpasync16(uint32_t dst, const uint32_t* src) {
    asm volatile("cp.async.cg.shared.global [%0], [%1], 16;" ::"r"(dst), "l"(src));
}

// ---------------- input conversion ---------------------------------------------
__global__ void split_x_kernel(const float* __restrict__ x) {
    long i = blockIdx.x * 256L + threadIdx.x;
    if (i < (long)NN * KP1) {
        float2 v = *(const float2*)(x + 2 * i);
        g_X[i] = pack_f16(v.x, v.y);
    }
}

__device__ __forceinline__ void wconv(const float* __restrict__ W, uint32_t* oh,
                                      int Kd, int N, int nOff, int outN, long idx) {
    int Kp = Kd / 2;
    int k = (int)(idx / ((long)N * Kp));
    int rem = (int)(idx % ((long)N * Kp));
    int n = rem / Kp;
    int kp = rem % Kp;
    const float* Wk = W + (long)k * Kd * N;
    float v0 = Wk[(long)(2 * kp) * N + n];
    float v1 = Wk[(long)(2 * kp + 1) * N + n];
    oh[((long)k * outN + nOff + n) * Kp + kp] = pack_f16(v0, v1);
}

#define CNT_A (KST * 256 * 128)
#define CNT_B (KST * 64 * 128)
#define CNT_C (KST * 64 * 32)

__global__ void split_weights_kernel(const float* iw1, const float* rw1,
                                     const float* w1, const float* iw2,
                                     const float* rw2, const float* w2) {
    long id = blockIdx.x * 256L + threadIdx.x;
    if (id < CNT_A) { wconv(iw1, g_W1C, 256, 256, 0, 512, id); return; }
    id -= CNT_A;
    if (id < CNT_A) { wconv(rw1, g_W1C, 256, 256, 256, 512, id); return; }
    id -= CNT_A;
    if (id < CNT_A) { wconv(w1, g_W1, 256, 256, 0, 256, id); return; }
    id -= CNT_A;
    if (id < CNT_B) { wconv(iw2, g_W2C, 256, 64, 0, 128, id); return; }
    id -= CNT_B;
    if (id < CNT_B) { wconv(rw2, g_W2C, 256, 64, 64, 128, id); return; }
    id -= CNT_B;
    if (id < CNT_C) { wconv(w2, g_W2, 64, 64, 0, 64, id); }
}

// ---------------- CSR ----------------------------------------------------------
__global__ void zero_sniff_kernel(const int* __restrict__ ei_raw) {
    int i = blockIdx.x * blockDim.x + threadIdx.x;
    if (i < NN) g_cnt[i] = 0;
    if (i == 0) {
        int all_zero = 1;
        for (int j = 0; j < 128; j++)
            if (ei_raw[2 * j + 1] != 0) { all_zero = 0; break; }
        g_is64 = all_zero;
    }
}

__device__ __forceinline__ int load_idx(const void* ei, long pos) {
    if (g_is64) return (int)((const long long*)ei)[pos];
    return ((const int*)ei)[pos];
}

__global__ void count_deg_kernel(const void* __restrict__ ei) {
    int e = blockIdx.x * blockDim.x + threadIdx.x;
    if (e < NE) {
        int c = load_idx(ei, (long)NE + e);
        if (c >= 0 && c < NN) atomicAdd(&g_cnt[c], 1);
    }
}

__global__ void scan1_kernel() {
    __shared__ int sh[256];
    int blk = blockIdx.x;
    int i = blk * 256 + threadIdx.x;
    int v = (i < NN) ? g_cnt[i] : 0;
    if (i < NN) g_dis[i] = (v > 0) ? rsqrtf((float)v) : 0.0f;
    sh[threadIdx.x] = v;
    __syncthreads();
    for (int d = 1; d < 256; d <<= 1) {
        int t = (threadIdx.x >= (unsigned)d) ? sh[threadIdx.x - d] : 0;
        __syncthreads();
        sh[threadIdx.x] += t;
        __syncthreads();
    }
    int incl = sh[threadIdx.x];
    if (i < NN) g_rowptr[i] = incl - v;
    if (threadIdx.x == 255) g_bsum[blk] = incl;
}

__global__ void scan2_kernel() {
    __shared__ int sh[128];
    int v = (threadIdx.x < SCAN_NBLK) ? g_bsum[threadIdx.x] : 0;
    sh[threadIdx.x] = v;
    __syncthreads();
    for (int d = 1; d < 128; d <<= 1) {
        int t = (threadIdx.x >= (unsigned)d) ? sh[threadIdx.x - d] : 0;
        __syncthreads();
        sh[threadIdx.x] += t;
        __syncthreads();
    }
    int incl = sh[threadIdx.x];
    if (threadIdx.x < SCAN_NBLK) g_bsum[threadIdx.x] = incl - v;
    if (threadIdx.x == 127) g_bsum[SCAN_NBLK] = incl;
}

__global__ void scan3_kernel() {
    int i = blockIdx.x * 256 + threadIdx.x;
    if (i < NN) {
        int ex = g_rowptr[i] + g_bsum[blockIdx.x];
        g_rowptr[i] = ex;
        g_cursor[i] = ex;
    }
    if (i == 0) g_rowptr[NN] = g_bsum[SCAN_NBLK];
}

__global__ void fill_csr_kernel(const void* __restrict__ ei) {
    int e = blockIdx.x * blockDim.x + threadIdx.x;
    if (e < NE) {
        int r = load_idx(ei, e);
        int c = load_idx(ei, (long)NE + e);
        if (r >= 0 && r < NN && c >= 0 && c < NN) {
            int pos = atomicAdd(&g_cursor[c], 1);
            if (pos >= 0 && pos < NE) {
                g_src[pos] = r;
                g_nrm[pos] = g_dis[r] * g_dis[c];
            }
        }
    }
}

// ---------------- fp16 tensor-core GEMM (templated BN, fat warp tiles) ---------
// C[b] = A[b] @ W[b]: fp16 MMA, fp32 accum. A fp16x2-packed [M][Kp];
// W pre-transposed [Ntot][Kp]. Dual-output epilogue.
// BM=128. BN=128: warp tile 64x32 (8 warps, 0.75x LDSM traffic/MAC), 2 CTAs/SM.
// BN=64: warp tile 32x32, 3 CTAs/SM. 4-stage cp.async, 1 sync/ktile, pitch 80B.
#define APITCH 20
#define NSTAGE 4
#define A_PLANE 10240              // 128*APITCH*4
#define B_OFF (NSTAGE * A_PLANE)   // 40960

template <int BN>
__global__ void __launch_bounds__(256, (BN == 128) ? 2 : 3)
bgemm2(const uint32_t* __restrict__ A, long sA,
       const uint32_t* __restrict__ B, long sB,
       const float* __restrict__ bias, long sBias,
       uint32_t* __restrict__ C0, long sC0,
       uint32_t* __restrict__ C1, long sC1,
       int M, int Ntot, int N1, int Kd) {
    constexpr int MT = (BN == 128) ? 4 : 2;          // m16 tiles per warp
    constexpr int B_PLANE = BN * APITCH * 4;
    extern __shared__ uint32_t smem[];
    uint32_t smem_u = (uint32_t)__cvta_generic_to_shared(smem);
    int Kp = Kd >> 1;
    int b = blockIdx.z;
    int bm = blockIdx.y * 128, bn = blockIdx.x * BN;
    int tid = threadIdx.x, warp = tid >> 5, lane = tid & 31;
    int g = lane >> 2, t = lane & 3;
    int wm, wn;
    if (BN == 128) { wm = warp >> 2; wn = warp & 3; }
    else           { wm = warp >> 1; wn = warp & 1; }

    // ---- hoisted per-thread cp.async addressing ----
    int rowL = tid >> 2, segL = tid & 3;
    int gm0 = bm + rowL;       if (gm0 >= M) gm0 = M - 1;
    int gm1 = bm + rowL + 64;  if (gm1 >= M) gm1 = M - 1;
    const uint32_t* sA0 = A + (long)b * sA + (long)gm0 * Kp + segL * 4;
    const uint32_t* sA1 = A + (long)b * sA + (long)gm1 * Kp + segL * 4;
    const uint32_t* sB0 = B + (long)b * sB + (long)(bn + rowL) * Kp + segL * 4;
    const uint32_t* sB1 = sB0 + (long)64 * Kp;  // used only if BN==128
    uint32_t dA0 = smem_u + (rowL * APITCH + segL * 4) * 4;
    uint32_t dA1 = dA0 + 64 * APITCH * 4;
    uint32_t dB0 = smem_u + B_OFF + (rowL * APITCH + segL * 4) * 4;
    uint32_t dB1 = dB0 + 64 * APITCH * 4;

    // ---- hoisted ldsm offsets ----
    int rowA = ((lane >> 3) & 1) * 8 + (lane & 7);
    int segA = (lane >> 4) * 4;
    int rowB = ((lane >> 4) & 1) * 8 + (lane & 7);
    int segB = ((lane >> 3) & 1) * 4;
    uint32_t aOff0 = smem_u + ((wm * (MT * 16) + rowA) * APITCH + segA) * 4;
    uint32_t bOff0 = smem_u + B_OFF + ((wn * 32 + rowB) * APITCH + segB) * 4;
    uint32_t bOff1 = bOff0 + 16 * APITCH * 4;

    auto issue = [&](int kt) {
        uint32_t aD = kt * (uint32_t)A_PLANE;
        uint32_t bD = kt * (uint32_t)B_PLANE;
        cpasync16(dA0 + aD, sA0);
        cpasync16(dA1 + aD, sA1);
        cpasync16(dB0 + bD, sB0);
        if (BN == 128) cpasync16(dB1 + bD, sB1);
        sA0 += 16;
        sA1 += 16;
        sB0 += 16;
        if (BN == 128) sB1 += 16;
        asm volatile("cp.async.commit_group;" ::: "memory");
    };

    float acc[MT][4][4];
#pragma unroll
    for (int i = 0; i < MT; i++)
#pragma unroll
        for (int j = 0; j < 4; j++)
#pragma unroll
            for (int k = 0; k < 4; k++) acc[i][j][k] = 0.f;

    int NT = Kd / 32;
    for (int s = 0; s < 3 && s < NT; s++) issue(s & 3);
    for (int kt = 0; kt < NT; kt++) {
        int buf = kt & 3;
        int rem = NT - kt;
        if (rem >= 3) {
            asm volatile("cp.async.wait_group 2;" ::: "memory");
        } else if (rem == 2) {
            asm volatile("cp.async.wait_group 1;" ::: "memory");
        } else {
            asm volatile("cp.async.wait_group 0;" ::: "memory");
        }
        __syncthreads();
        if (kt + 3 < NT) issue((kt + 3) & 3);
        uint32_t aBase = buf * (uint32_t)A_PLANE;
        uint32_t bBase = buf * (uint32_t)B_PLANE;
#pragma unroll
        for (int ks = 0; ks < 2; ks++) {
            uint32_t ko = ks * 32;
            uint32_t af[MT][4], bf[4][2];
#pragma unroll
            for (int mt = 0; mt < MT; mt++)
                ldsm4(af[mt], aOff0 + mt * (16 * APITCH * 4) + aBase + ko);
            ldsm4(&bf[0][0], bOff0 + bBase + ko);
            ldsm4(&bf[2][0], bOff1 + bBase + ko);
#pragma unroll
            for (int mt = 0; mt < MT; mt++)
#pragma unroll
                for (int nt = 0; nt < 4; nt++) mma_f16(acc[mt][nt], af[mt], bf[nt]);
        }
    }

    // ---- epilogue: fp16-pack + dual-target store ----
    int row0 = bm + wm * (MT * 16);
    int col0 = bn + wn * 32;
#pragma unroll
    for (int nt = 0; nt < 4; nt++) {
        int c = col0 + nt * 8 + 2 * t;
        bool out1 = (c >= N1);
        float bx = 0.f, by = 0.f;
        uint32_t* O;
        long pitch;
        int cc;
        if (out1) {
            if (bias) {
                bx = bias[b * sBias + (c - N1)];
                by = bias[b * sBias + (c - N1) + 1];
            }
            O = C1 + (long)b * sC1;
            pitch = (Ntot - N1) >> 1;
            cc = (c - N1) >> 1;
        } else {
            O = C0 + (long)b * sC0;
            pitch = N1 >> 1;
            cc = c >> 1;
        }
#pragma unroll
        for (int mt = 0; mt < MT; mt++) {
            int r = row0 + mt * 16 + g;
            if (r < M)
                O[(long)r * pitch + cc] = pack_f16(acc[mt][nt][0] + bx, acc[mt][nt][1] + by);
            if (r + 8 < M)
                O[(long)(r + 8) * pitch + cc] =
                    pack_f16(acc[mt][nt][2] + bx, acc[mt][nt][3] + by);
        }
    }
}

#define GSMEM128 (NSTAGE * (A_PLANE + 128 * APITCH * 4))  // 81920
#define GSMEM64 (NSTAGE * (A_PLANE + 64 * APITCH * 4))    // 61440

// ---------------- propagation (CSR gather on fp16) ------------------------------
template <int F, bool RELU>
__global__ void prop_kernel(const uint32_t* __restrict__ H,
                            const uint32_t* __restrict__ R,
                            uint32_t* __restrict__ O) {
    constexpr int LANES = F / 4;
    constexpr int NPB = 256 / LANES;
    constexpr int PITCH = F / 2;
    int lane = threadIdx.x % LANES;
    int local = threadIdx.x / LANES;
    int n = blockIdx.x * NPB + local;
    int k = blockIdx.y;
    if (n >= NN) return;
    long base = (long)k * NN * PITCH;
    const uint32_t* Hk = H + base;
    int e0 = g_rowptr[n], e1 = g_rowptr[n + 1];
    float4 acc = make_float4(0.f, 0.f, 0.f, 0.f);
#pragma unroll 4
    for (int e = e0; e < e1; e++) {
        int s = g_src[e];
        float w = g_nrm[e];
        uint2 hh = *(const uint2*)(Hk + (long)s * PITCH + lane * 2);
        float2 v0 = h2f2(hh.x);
        float2 v1 = h2f2(hh.y);
        acc.x += w * v0.x;
        acc.y += w * v0.y;
        acc.z += w * v1.x;
        acc.w += w * v1.y;
    }
    long off = base + (long)n * PITCH + lane * 2;
    uint2 rr = *(const uint2*)(R + off);
    float2 r0 = h2f2(rr.x), r1 = h2f2(rr.y);
    acc.x += r0.x;
    acc.y += r0.y;
    acc.z += r1.x;
    acc.w += r1.y;
    if (RELU) {
        acc.x = fmaxf(acc.x, 0.f);
        acc.y = fmaxf(acc.y, 0.f);
        acc.z = fmaxf(acc.z, 0.f);
        acc.w = fmaxf(acc.w, 0.f);
    }
    *(uint2*)(O + off) = make_uint2(pack_f16(acc.x, acc.y), pack_f16(acc.z, acc.w));
}

// ---------------- mean over stacks ---------------------------------------------
__global__ void mean_kernel() {
    long i = blockIdx.x * 256L + threadIdx.x;
    const long st = (long)NN * KPH;
    if (i < st) {
        float2 s = make_float2(0.f, 0.f);
#pragma unroll
        for (int k = 0; k < KST; k++) {
            float2 h = h2f2(g_H1[i + k * st]);
            s.x += h.x;
            s.y += h.y;
        }
        g_HM[i] = pack_f16(s.x * (1.0f / 3.0f), s.y * (1.0f / 3.0f));
    }
}

// ---------------- final: mean over stacks + log_softmax -------------------------
__global__ void final_kernel(float* __restrict__ out) {
    int n = blockIdx.x;
    int f = threadIdx.x;  // 64 threads
    const long st = (long)NN * KPO;
    long p = (long)n * KPO + (f >> 1);
    float v = 0.f;
#pragma unroll
    for (int k = 0; k < KST; k++) {
        float2 h = h2f2(g_G1[p + k * st]);
        v += (f & 1) ? h.y : h.x;
    }
    v *= (1.0f / 3.0f);
    float m = v;
#pragma unroll
    for (int d = 16; d; d >>= 1) m = fmaxf(m, __shfl_xor_sync(0xffffffffu, m, d));
    __shared__ float sm[2], ss[2];
    int w = threadIdx.x >> 5;
    if ((threadIdx.x & 31) == 0) sm[w] = m;
    __syncthreads();
    m = fmaxf(sm[0], sm[1]);
    float e = expf(v - m);
    float s = e;
#pragma unroll
    for (int d = 16; d; d >>= 1) s += __shfl_xor_sync(0xffffffffu, s, d);
    if ((threadIdx.x & 31) == 0) ss[w] = s;
    __syncthreads();
    s = ss[0] + ss[1];
    out[(long)n * FOUT + f] = v - m - logf(s);
}

// ---------------- launch ---------------------------------------------------------
extern "C" void kernel_launch(void* const* d_in, const int* in_sizes, int n_in,
                              void* d_out, int out_size) {
    const float* x = (const float*)d_in[0];
    const void* ei = d_in[1];
    const float* init_w1 = (const float*)d_in[2];
    const float* w1 = (const float*)d_in[3];
    const float* root_w1 = (const float*)d_in[4];
    const float* bias1 = (const float*)d_in[5];
    const float* init_w2 = (const float*)d_in[6];
    const float* w2 = (const float*)d_in[7];
    const float* root_w2 = (const float*)d_in[8];
    const float* bias2 = (const float*)d_in[9];
    float* out = (float*)d_out;

    static bool attr_set = false;
    if (!attr_set) {
        cudaFuncSetAttribute(bgemm2<128>, cudaFuncAttributeMaxDynamicSharedMemorySize,
                             GSMEM128);
        cudaFuncSetAttribute(bgemm2<64>, cudaFuncAttributeMaxDynamicSharedMemorySize,
                             GSMEM64);
        attr_set = true;
    }

    uint32_t *X, *H0, *H1, *R1, *HM, *G0, *G1, *R2;
    uint32_t *W1C, *W1, *W2C, *W2;
    cudaGetSymbolAddress((void**)&X, g_X);
    cudaGetSymbolAddress((void**)&H0, g_H0);
    cudaGetSymbolAddress((void**)&H1, g_H1);
    cudaGetSymbolAddress((void**)&R1, g_R1);
    cudaGetSymbolAddress((void**)&HM, g_HM);
    cudaGetSymbolAddress((void**)&G0, g_G0);
    cudaGetSymbolAddress((void**)&G1, g_G1);
    cudaGetSymbolAddress((void**)&R2, g_R2);
    cudaGetSymbolAddress((void**)&W1C, g_W1C);
    cudaGetSymbolAddress((void**)&W1, g_W1);
    cudaGetSymbolAddress((void**)&W2C, g_W2C);
    cudaGetSymbolAddress((void**)&W2, g_W2);

    const int MY = (NN + 127) / 128;  // 235

    // 0-2: prep
    split_x_kernel<<<(NN * KP1 + 255) / 256, 256>>>(x);
    split_weights_kernel<<<(3 * CNT_A + 2 * CNT_B + CNT_C + 255) / 256, 256>>>(
        init_w1, root_w1, w1, init_w2, root_w2, w2);
    zero_sniff_kernel<<<(NN + 255) / 256, 256>>>((const int*)ei);
    // 3: fused conv1 GEMM — ncu capture slot
    dim3 gc1(512 / 128, MY, KST);
    bgemm2<128><<<gc1, 256, GSMEM128>>>(X, 0, W1C, (long)512 * KP1, bias1, FHID,
                                        H0, (long)NN * KPH, R1, (long)NN * KPH,
                                        NN, 512, 256, FIN);
    // CSR build
    count_deg_kernel<<<(NE + 255) / 256, 256>>>(ei);
    scan1_kernel<<<SCAN_NBLK, 256>>>();
    scan2_kernel<<<1, 128>>>();
    scan3_kernel<<<SCAN_NBLK, 256>>>();
    fill_csr_kernel<<<(NE + 255) / 256, 256>>>(ei);

    // conv1 body
    dim3 gp1((NN + 3) / 4, KST);
    prop_kernel<FHID, true><<<gp1, 256>>>(H0, R1, H1);
    dim3 gw1(256 / 128, MY, KST);
    bgemm2<128><<<gw1, 256, GSMEM128>>>(H1, (long)NN * KPH, W1, (long)256 * KPH,
                                        nullptr, 0, H0, (long)NN * KPH, nullptr, 0,
                                        NN, 256, 256, FHID);
    prop_kernel<FHID, true><<<gp1, 256>>>(H0, R1, H1);
    mean_kernel<<<(NN * KPH + 255) / 256, 256>>>();

    // conv2
    dim3 gc2(1, MY, KST);
    bgemm2<128><<<gc2, 256, GSMEM128>>>(HM, 0, W2C, (long)128 * KPH, bias2, FOUT,
                                        G0, (long)NN * KPO, R2, (long)NN * KPO,
                                        NN, 128, 64, FHID);
    dim3 gp2((NN + 15) / 16, KST);
    prop_kernel<FOUT, false><<<gp2, 256>>>(G0, R2, G1);
    dim3 gw2(1, MY, KST);
    bgemm2<64><<<gw2, 256, GSMEM64>>>(G1, (long)NN * KPO, W2, (long)64 * KPO,
                                      nullptr, 0, G0, (long)NN * KPO, nullptr, 0,
                                      NN, 64, 64, FOUT);
    prop_kernel<FOUT, false><<<gp2, 256>>>(G0, R2, G1);

    final_kernel<<<NN, FOUT>>>(out);
}

// round 14
// speedup vs baseline: 2.4376x; 1.1559x over previous
#include <cuda_runtime.h>
#include <cuda_fp16.h>
#include <math.h>
#include <stdint.h>

#define KST 3
#define NN 30000
#define NE 300000
#define FIN 256
#define FHID 256
#define FOUT 64
#define KP1 (FIN / 2)    // 128
#define KPH (FHID / 2)   // 128
#define KPO (FOUT / 2)   // 32

// ---------------- scratch (device globals) ------------------------------------
__device__ __align__(16) uint32_t g_X[NN * KP1];
__device__ __align__(16) uint32_t g_H0[KST * NN * KPH];
__device__ __align__(16) uint32_t g_H1[KST * NN * KPH];
__device__ __align__(16) uint32_t g_R1[KST * NN * KPH];
__device__ __align__(16) uint32_t g_HM[NN * KPH];
__device__ __align__(16) uint32_t g_G0[KST * NN * KPO];
__device__ __align__(16) uint32_t g_G1[KST * NN * KPO];
__device__ __align__(16) uint32_t g_R2[KST * NN * KPO];
__device__ __align__(16) uint32_t g_W1C[KST * 512 * KP1];
__device__ __align__(16) uint32_t g_W1[KST * 256 * KPH];
__device__ __align__(16) uint32_t g_W2C[KST * 128 * KPH];
__device__ __align__(16) uint32_t g_W2[KST * 64 * KPO];
__device__ float g_dis[NN];
__device__ int g_cnt[NN];
__device__ int g_rowptr[NN + 1];
__device__ int g_cursor[NN];
__device__ int g_src[NE];
__device__ float g_nrm[NE];
__device__ int g_is64;
#define SCAN_NBLK 118
__device__ int g_bsum[SCAN_NBLK + 1];

// ---------------- helpers -----------------------------------------------------
__device__ __forceinline__ uint32_t pack_f16(float a, float b) {
    __half2 h = __floats2half2_rn(a, b);
    return *reinterpret_cast<uint32_t*>(&h);
}

__device__ __forceinline__ float2 h2f2(uint32_t u) {
    __half2 h = *reinterpret_cast<__half2*>(&u);
    return __half22float2(h);
}

__device__ __forceinline__ void mma_f16(float* c, const uint32_t* a, const uint32_t* bb) {
    asm volatile(
        "mma.sync.aligned.m16n8k16.row.col.f32.f16.f16.f32 "
        "{%0,%1,%2,%3}, {%4,%5,%6,%7}, {%8,%9}, {%0,%1,%2,%3};\n"
        : "+f"(c[0]), "+f"(c[1]), "+f"(c[2]), "+f"(c[3])
        : "r"(a[0]), "r"(a[1]), "r"(a[2]), "r"(a[3]), "r"(bb[0]), "r"(bb[1]));
}

__device__ __forceinline__ void ldsm4(uint32_t* r, uint32_t addr) {
    asm volatile("ldmatrix.sync.aligned.m8n8.x4.shared.b16 {%0,%1,%2,%3}, [%4];"
                 : "=r"(r[0]), "=r"(r[1]), "=r"(r[2]), "=r"(r[3])
                 : "r"(addr));
}

__device__ __forceinline__ void cpasync16(uint32_t dst, const uint32_t* src) {
    asm volatile("cp.async.cg.shared.global [%0], [%1], 16;" ::"r"(dst), "l"(src));
}

// accumulate 8 fp16 values (uint4) into float acc[8] with weight w
__device__ __forceinline__ void acc8(float* a, uint4 v, float w) {
    float2 f0 = h2f2(v.x), f1 = h2f2(v.y), f2 = h2f2(v.z), f3 = h2f2(v.w);
    a[0] += w * f0.x; a[1] += w * f0.y;
    a[2] += w * f1.x; a[3] += w * f1.y;
    a[4] += w * f2.x; a[5] += w * f2.y;
    a[6] += w * f3.x; a[7] += w * f3.y;
}

__device__ __forceinline__ void add8(float* a, uint4 v) {
    float2 f0 = h2f2(v.x), f1 = h2f2(v.y), f2 = h2f2(v.z), f3 = h2f2(v.w);
    a[0] += f0.x; a[1] += f0.y;
    a[2] += f1.x; a[3] += f1.y;
    a[4] += f2.x; a[5] += f2.y;
    a[6] += f3.x; a[7] += f3.y;
}

// ---------------- fused prep: split x + weights + zero counters + sniff --------
__device__ __forceinline__ void wconv(const float* __restrict__ W, uint32_t* oh,
                                      int Kd, int N, int nOff, int outN, long idx) {
    int Kp = Kd / 2;
    int k = (int)(idx / ((long)N * Kp));
    int rem = (int)(idx % ((long)N * Kp));
    int n = rem / Kp;
    int kp = rem % Kp;
    const float* Wk = W + (long)k * Kd * N;
    float v0 = Wk[(long)(2 * kp) * N + n];
    float v1 = Wk[(long)(2 * kp + 1) * N + n];
    oh[((long)k * outN + nOff + n) * Kp + kp] = pack_f16(v0, v1);
}

#define CNT_X ((long)NN * KP1)
#define CNT_A (KST * 256 * 128)
#define CNT_B (KST * 64 * 128)
#define CNT_C (KST * 64 * 32)
#define CNT_PREP (CNT_X + 3 * CNT_A + 2 * CNT_B + CNT_C + NN)

__global__ void prep_kernel(const float* x, const float* iw1, const float* rw1,
                            const float* w1, const float* iw2, const float* rw2,
                            const float* w2, const int* ei_raw) {
    long id = blockIdx.x * 256L + threadIdx.x;
    if (id == 0) {
        int all_zero = 1;
        for (int j = 0; j < 128; j++)
            if (ei_raw[2 * j + 1] != 0) { all_zero = 0; break; }
        g_is64 = all_zero;
    }
    if (id < CNT_X) {
        float2 v = *(const float2*)(x + 2 * id);
        g_X[id] = pack_f16(v.x, v.y);
        return;
    }
    id -= CNT_X;
    if (id < CNT_A) { wconv(iw1, g_W1C, 256, 256, 0, 512, id); return; }
    id -= CNT_A;
    if (id < CNT_A) { wconv(rw1, g_W1C, 256, 256, 256, 512, id); return; }
    id -= CNT_A;
    if (id < CNT_A) { wconv(w1, g_W1, 256, 256, 0, 256, id); return; }
    id -= CNT_A;
    if (id < CNT_B) { wconv(iw2, g_W2C, 256, 64, 0, 128, id); return; }
    id -= CNT_B;
    if (id < CNT_B) { wconv(rw2, g_W2C, 256, 64, 64, 128, id); return; }
    id -= CNT_B;
    if (id < CNT_C) { wconv(w2, g_W2, 64, 64, 0, 64, id); return; }
    id -= CNT_C;
    if (id < NN) g_cnt[id] = 0;
}

// ---------------- CSR ----------------------------------------------------------
__device__ __forceinline__ int load_idx(const void* ei, long pos) {
    if (g_is64) return (int)((const long long*)ei)[pos];
    return ((const int*)ei)[pos];
}

__global__ void count_deg_kernel(const void* __restrict__ ei) {
    int e = blockIdx.x * blockDim.x + threadIdx.x;
    if (e < NE) {
        int c = load_idx(ei, (long)NE + e);
        if (c >= 0 && c < NN) atomicAdd(&g_cnt[c], 1);
    }
}

__global__ void scan1_kernel() {
    __shared__ int sh[256];
    int blk = blockIdx.x;
    int i = blk * 256 + threadIdx.x;
    int v = (i < NN) ? g_cnt[i] : 0;
    if (i < NN) g_dis[i] = (v > 0) ? rsqrtf((float)v) : 0.0f;
    sh[threadIdx.x] = v;
    __syncthreads();
    for (int d = 1; d < 256; d <<= 1) {
        int t = (threadIdx.x >= (unsigned)d) ? sh[threadIdx.x - d] : 0;
        __syncthreads();
        sh[threadIdx.x] += t;
        __syncthreads();
    }
    int incl = sh[threadIdx.x];
    if (i < NN) g_rowptr[i] = incl - v;  // local exclusive
    if (threadIdx.x == 255) g_bsum[blk] = incl;
}

// fused: every block scans the 118 block sums in smem, then applies offset
__global__ void scan3_kernel() {
    __shared__ int sh[128];
    int tid = threadIdx.x;
    if (tid < 128) sh[tid] = (tid < SCAN_NBLK) ? g_bsum[tid] : 0;
    __syncthreads();
    for (int d = 1; d < 128; d <<= 1) {
        int t = (tid < 128 && tid >= d) ? sh[tid - d] : 0;
        __syncthreads();
        if (tid < 128) sh[tid] += t;
        __syncthreads();
    }
    // exclusive prefix for this block = inclusive - own
    int prefix = sh[blockIdx.x] - g_bsum[blockIdx.x];
    int i = blockIdx.x * 256 + tid;
    if (i < NN) {
        int ex = g_rowptr[i] + prefix;
        g_rowptr[i] = ex;
        g_cursor[i] = ex;
    }
    if (blockIdx.x == 0 && tid == 0) g_rowptr[NN] = sh[SCAN_NBLK - 1];
}

__global__ void fill_csr_kernel(const void* __restrict__ ei) {
    int e = blockIdx.x * blockDim.x + threadIdx.x;
    if (e < NE) {
        int r = load_idx(ei, e);
        int c = load_idx(ei, (long)NE + e);
        if (r >= 0 && r < NN && c >= 0 && c < NN) {
            int pos = atomicAdd(&g_cursor[c], 1);
            if (pos >= 0 && pos < NE) {
                g_src[pos] = r;
                g_nrm[pos] = g_dis[r] * g_dis[c];
            }
        }
    }
}

// ---------------- fp16 tensor-core GEMM (templated BN, fat warp tiles) ---------
#define APITCH 20
#define NSTAGE 4
#define A_PLANE 10240              // 128*APITCH*4
#define B_OFF (NSTAGE * A_PLANE)   // 40960

template <int BN>
__global__ void __launch_bounds__(256, (BN == 128) ? 2 : 3)
bgemm2(const uint32_t* __restrict__ A, long sA,
       const uint32_t* __restrict__ B, long sB,
       const float* __restrict__ bias, long sBias,
       uint32_t* __restrict__ C0, long sC0,
       uint32_t* __restrict__ C1, long sC1,
       int M, int Ntot, int N1, int Kd) {
    constexpr int MT = (BN == 128) ? 4 : 2;
    constexpr int B_PLANE = BN * APITCH * 4;
    extern __shared__ uint32_t smem[];
    uint32_t smem_u = (uint32_t)__cvta_generic_to_shared(smem);
    int Kp = Kd >> 1;
    int b = blockIdx.z;
    int bm = blockIdx.y * 128, bn = blockIdx.x * BN;
    int tid = threadIdx.x, warp = tid >> 5, lane = tid & 31;
    int g = lane >> 2, t = lane & 3;
    int wm, wn;
    if (BN == 128) { wm = warp >> 2; wn = warp & 3; }
    else           { wm = warp >> 1; wn = warp & 1; }

    int rowL = tid >> 2, segL = tid & 3;
    int gm0 = bm + rowL;       if (gm0 >= M) gm0 = M - 1;
    int gm1 = bm + rowL + 64;  if (gm1 >= M) gm1 = M - 1;
    const uint32_t* sA0 = A + (long)b * sA + (long)gm0 * Kp + segL * 4;
    const uint32_t* sA1 = A + (long)b * sA + (long)gm1 * Kp + segL * 4;
    const uint32_t* sB0 = B + (long)b * sB + (long)(bn + rowL) * Kp + segL * 4;
    const uint32_t* sB1 = sB0 + (long)64 * Kp;
    uint32_t dA0 = smem_u + (rowL * APITCH + segL * 4) * 4;
    uint32_t dA1 = dA0 + 64 * APITCH * 4;
    uint32_t dB0 = smem_u + B_OFF + (rowL * APITCH + segL * 4) * 4;
    uint32_t dB1 = dB0 + 64 * APITCH * 4;

    int rowA = ((lane >> 3) & 1) * 8 + (lane & 7);
    int segA = (lane >> 4) * 4;
    int rowB = ((lane >> 4) & 1) * 8 + (lane & 7);
    int segB = ((lane >> 3) & 1) * 4;
    uint32_t aOff0 = smem_u + ((wm * (MT * 16) + rowA) * APITCH + segA) * 4;
    uint32_t bOff0 = smem_u + B_OFF + ((wn * 32 + rowB) * APITCH + segB) * 4;
    uint32_t bOff1 = bOff0 + 16 * APITCH * 4;

    auto issue = [&](int kt) {
        uint32_t aD = kt * (uint32_t)A_PLANE;
        uint32_t bD = kt * (uint32_t)B_PLANE;
        cpasync16(dA0 + aD, sA0);
        cpasync16(dA1 + aD, sA1);
        cpasync16(dB0 + bD, sB0);
        if (BN == 128) cpasync16(dB1 + bD, sB1);
        sA0 += 16;
        sA1 += 16;
        sB0 += 16;
        if (BN == 128) sB1 += 16;
        asm volatile("cp.async.commit_group;" ::: "memory");
    };

    float acc[MT][4][4];
#pragma unroll
    for (int i = 0; i < MT; i++)
#pragma unroll
        for (int j = 0; j < 4; j++)
#pragma unroll
            for (int k = 0; k < 4; k++) acc[i][j][k] = 0.f;

    int NT = Kd / 32;
    for (int s = 0; s < 3 && s < NT; s++) issue(s & 3);
    for (int kt = 0; kt < NT; kt++) {
        int buf = kt & 3;
        int rem = NT - kt;
        if (rem >= 3) {
            asm volatile("cp.async.wait_group 2;" ::: "memory");
        } else if (rem == 2) {
            asm volatile("cp.async.wait_group 1;" ::: "memory");
        } else {
            asm volatile("cp.async.wait_group 0;" ::: "memory");
        }
        __syncthreads();
        if (kt + 3 < NT) issue((kt + 3) & 3);
        uint32_t aBase = buf * (uint32_t)A_PLANE;
        uint32_t bBase = buf * (uint32_t)B_PLANE;
#pragma unroll
        for (int ks = 0; ks < 2; ks++) {
            uint32_t ko = ks * 32;
            uint32_t af[MT][4], bf[4][2];
#pragma unroll
            for (int mt = 0; mt < MT; mt++)
                ldsm4(af[mt], aOff0 + mt * (16 * APITCH * 4) + aBase + ko);
            ldsm4(&bf[0][0], bOff0 + bBase + ko);
            ldsm4(&bf[2][0], bOff1 + bBase + ko);
#pragma unroll
            for (int mt = 0; mt < MT; mt++)
#pragma unroll
                for (int nt = 0; nt < 4; nt++) mma_f16(acc[mt][nt], af[mt], bf[nt]);
        }
    }

    int row0 = bm + wm * (MT * 16);
    int col0 = bn + wn * 32;
#pragma unroll
    for (int nt = 0; nt < 4; nt++) {
        int c = col0 + nt * 8 + 2 * t;
        bool out1 = (c >= N1);
        float bx = 0.f, by = 0.f;
        uint32_t* O;
        long pitch;
        int cc;
        if (out1) {
            if (bias) {
                bx = bias[b * sBias + (c - N1)];
                by = bias[b * sBias + (c - N1) + 1];
            }
            O = C1 + (long)b * sC1;
            pitch = (Ntot - N1) >> 1;
            cc = (c - N1) >> 1;
        } else {
            O = C0 + (long)b * sC0;
            pitch = N1 >> 1;
            cc = c >> 1;
        }
#pragma unroll
        for (int mt = 0; mt < MT; mt++) {
            int r = row0 + mt * 16 + g;
            if (r < M)
                O[(long)r * pitch + cc] = pack_f16(acc[mt][nt][0] + bx, acc[mt][nt][1] + by);
            if (r + 8 < M)
                O[(long)(r + 8) * pitch + cc] =
                    pack_f16(acc[mt][nt][2] + bx, acc[mt][nt][3] + by);
        }
    }
}

#define GSMEM128 (NSTAGE * (A_PLANE + 128 * APITCH * 4))  // 81920
#define GSMEM64 (NSTAGE * (A_PLANE + 64 * APITCH * 4))    // 61440

// ---------------- propagation (uint4 gather) ------------------------------------
template <int F, bool RELU>
__global__ void prop_kernel(const uint32_t* __restrict__ H,
                            const uint32_t* __restrict__ R,
                            uint32_t* __restrict__ O) {
    constexpr int LANES = F / 8;
    constexpr int NPB = 256 / LANES;
    constexpr int PITCH = F / 2;
    int lane = threadIdx.x % LANES;
    int local = threadIdx.x / LANES;
    int n = blockIdx.x * NPB + local;
    int k = blockIdx.y;
    if (n >= NN) return;
    long base = (long)k * NN * PITCH;
    const uint32_t* Hk = H + base;
    int e0 = g_rowptr[n], e1 = g_rowptr[n + 1];
    float a[8] = {0.f, 0.f, 0.f, 0.f, 0.f, 0.f, 0.f, 0.f};
#pragma unroll 4
    for (int e = e0; e < e1; e++) {
        int s = g_src[e];
        float w = g_nrm[e];
        uint4 v = *(const uint4*)(Hk + (long)s * PITCH + lane * 4);
        acc8(a, v, w);
    }
    long off = base + (long)n * PITCH + lane * 4;
    add8(a, *(const uint4*)(R + off));
    if (RELU) {
#pragma unroll
        for (int j = 0; j < 8; j++) a[j] = fmaxf(a[j], 0.f);
    }
    uint4 o;
    o.x = pack_f16(a[0], a[1]);
    o.y = pack_f16(a[2], a[3]);
    o.z = pack_f16(a[4], a[5]);
    o.w = pack_f16(a[6], a[7]);
    *(uint4*)(O + off) = o;
}

// ---------------- fused 2nd conv1 prop + mean over stacks -----------------------
__global__ void prop1_mean_kernel(const uint32_t* __restrict__ H,
                                  const uint32_t* __restrict__ R) {
    // F=256: 32 lanes x uint4, 8 nodes per 256-thread block
    int lane = threadIdx.x & 31;
    int local = threadIdx.x >> 5;
    int n = blockIdx.x * 8 + local;
    if (n >= NN) return;
    int e0 = g_rowptr[n], e1 = g_rowptr[n + 1];
    float m[8] = {0.f, 0.f, 0.f, 0.f, 0.f, 0.f, 0.f, 0.f};
#pragma unroll
    for (int k = 0; k < KST; k++) {
        long base = (long)k * NN * KPH;
        const uint32_t* Hk = H + base;
        float a[8] = {0.f, 0.f, 0.f, 0.f, 0.f, 0.f, 0.f, 0.f};
#pragma unroll 4
        for (int e = e0; e < e1; e++) {
            int s = g_src[e];
            float w = g_nrm[e];
            uint4 v = *(const uint4*)(Hk + (long)s * KPH + lane * 4);
            acc8(a, v, w);
        }
        add8(a, *(const uint4*)(R + base + (long)n * KPH + lane * 4));
#pragma unroll
        for (int j = 0; j < 8; j++) m[j] += fmaxf(a[j], 0.f);
    }
    uint4 o;
    o.x = pack_f16(m[0] * (1.f / 3.f), m[1] * (1.f / 3.f));
    o.y = pack_f16(m[2] * (1.f / 3.f), m[3] * (1.f / 3.f));
    o.z = pack_f16(m[4] * (1.f / 3.f), m[5] * (1.f / 3.f));
    o.w = pack_f16(m[6] * (1.f / 3.f), m[7] * (1.f / 3.f));
    *(uint4*)(g_HM + (long)n * KPH + lane * 4) = o;
}

// ---------------- fused 2nd conv2 prop + mean + log_softmax ---------------------
__global__ void prop2_final_kernel(const uint32_t* __restrict__ H,
                                   const uint32_t* __restrict__ R,
                                   float* __restrict__ out) {
    // F=64: 8 lanes x uint4 (32 u32), 32 nodes per 256-thread block
    int lane = threadIdx.x & 7;
    int local = threadIdx.x >> 3;
    int n = blockIdx.x * 32 + local;
    if (n >= NN) return;
    int e0 = g_rowptr[n], e1 = g_rowptr[n + 1];
    float m[8] = {0.f, 0.f, 0.f, 0.f, 0.f, 0.f, 0.f, 0.f};
#pragma unroll
    for (int k = 0; k < KST; k++) {
        long base = (long)k * NN * KPO;
        const uint32_t* Hk = H + base;
        float a[8] = {0.f, 0.f, 0.f, 0.f, 0.f, 0.f, 0.f, 0.f};
#pragma unroll 4
        for (int e = e0; e < e1; e++) {
            int s = g_src[e];
            float w = g_nrm[e];
            uint4 v = *(const uint4*)(Hk + (long)s * KPO + lane * 4);
            acc8(a, v, w);
        }
        add8(a, *(const uint4*)(R + base + (long)n * KPO + lane * 4));
#pragma unroll
        for (int j = 0; j < 8; j++) m[j] += a[j];
    }
#pragma unroll
    for (int j = 0; j < 8; j++) m[j] *= (1.f / 3.f);
    // log_softmax over 64 features (8 lanes x 8 local)
    float mx = m[0];
#pragma unroll
    for (int j = 1; j < 8; j++) mx = fmaxf(mx, m[j]);
#pragma unroll
    for (int d = 4; d; d >>= 1) mx = fmaxf(mx, __shfl_xor_sync(0xffffffffu, mx, d, 8));
    float s = 0.f;
#pragma unroll
    for (int j = 0; j < 8; j++) s += expf(m[j] - mx);
#pragma unroll
    for (int d = 4; d; d >>= 1) s += __shfl_xor_sync(0xffffffffu, s, d, 8);
    float lg = mx + logf(s);
    float* o = out + (long)n * FOUT + lane * 8;
#pragma unroll
    for (int j = 0; j < 8; j++) o[j] = m[j] - lg;
}

// ---------------- launch ---------------------------------------------------------
extern "C" void kernel_launch(void* const* d_in, const int* in_sizes, int n_in,
                              void* d_out, int out_size) {
    const float* x = (const float*)d_in[0];
    const void* ei = d_in[1];
    const float* init_w1 = (const float*)d_in[2];
    const float* w1 = (const float*)d_in[3];
    const float* root_w1 = (const float*)d_in[4];
    const float* bias1 = (const float*)d_in[5];
    const float* init_w2 = (const float*)d_in[6];
    const float* w2 = (const float*)d_in[7];
    const float* root_w2 = (const float*)d_in[8];
    const float* bias2 = (const float*)d_in[9];
    float* out = (float*)d_out;

    static bool attr_set = false;
    if (!attr_set) {
        cudaFuncSetAttribute(bgemm2<128>, cudaFuncAttributeMaxDynamicSharedMemorySize,
                             GSMEM128);
        cudaFuncSetAttribute(bgemm2<64>, cudaFuncAttributeMaxDynamicSharedMemorySize,
                             GSMEM64);
        attr_set = true;
    }

    uint32_t *X, *H0, *H1, *R1, *HM, *G0, *G1, *R2;
    uint32_t *W1C, *W1, *W2C, *W2;
    cudaGetSymbolAddress((void**)&X, g_X);
    cudaGetSymbolAddress((void**)&H0, g_H0);
    cudaGetSymbolAddress((void**)&H1, g_H1);
    cudaGetSymbolAddress((void**)&R1, g_R1);
    cudaGetSymbolAddress((void**)&HM, g_HM);
    cudaGetSymbolAddress((void**)&G0, g_G0);
    cudaGetSymbolAddress((void**)&G1, g_G1);
    cudaGetSymbolAddress((void**)&R2, g_R2);
    cudaGetSymbolAddress((void**)&W1C, g_W1C);
    cudaGetSymbolAddress((void**)&W1, g_W1);
    cudaGetSymbolAddress((void**)&W2C, g_W2C);
    cudaGetSymbolAddress((void**)&W2, g_W2);

    const int MY = (NN + 127) / 128;  // 235

    // 0: fused prep (x/weights fp16 convert, zero counters, dtype sniff)
    prep_kernel<<<(int)((CNT_PREP + 255) / 256), 256>>>(
        x, init_w1, root_w1, w1, init_w2, root_w2, w2, (const int*)ei);
    // 1: fused conv1 GEMM
    dim3 gc1(512 / 128, MY, KST);
    bgemm2<128><<<gc1, 256, GSMEM128>>>(X, 0, W1C, (long)512 * KP1, bias1, FHID,
                                        H0, (long)NN * KPH, R1, (long)NN * KPH,
                                        NN, 512, 256, FIN);
    // 2-5: CSR build
    count_deg_kernel<<<(NE + 255) / 256, 256>>>(ei);
    scan1_kernel<<<SCAN_NBLK, 256>>>();
    scan3_kernel<<<SCAN_NBLK, 256>>>();
    fill_csr_kernel<<<(NE + 255) / 256, 256>>>(ei);

    // conv1 body
    prop_kernel<FHID, true><<<dim3((NN + 7) / 8, KST), 256>>>(H0, R1, H1);
    dim3 gw1(256 / 128, MY, KST);
    bgemm2<128><<<gw1, 256, GSMEM128>>>(H1, (long)NN * KPH, W1, (long)256 * KPH,
                                        nullptr, 0, H0, (long)NN * KPH, nullptr, 0,
                                        NN, 256, 256, FHID);
    prop1_mean_kernel<<<(NN + 7) / 8, 256>>>(H0, R1);

    // conv2
    dim3 gc2(1, MY, KST);
    bgemm2<128><<<gc2, 256, GSMEM128>>>(HM, 0, W2C, (long)128 * KPH, bias2, FOUT,
                                        G0, (long)NN * KPO, R2, (long)NN * KPO,
                                        NN, 128, 64, FHID);
    prop_kernel<FOUT, false><<<dim3((NN + 31) / 32, KST), 256>>>(G0, R2, G1);
    dim3 gw2(1, MY, KST);
    bgemm2<64><<<gw2, 256, GSMEM64>>>(G1, (long)NN * KPO, W2, (long)64 * KPO,
                                      nullptr, 0, G0, (long)NN * KPO, nullptr, 0,
                                      NN, 64, 64, FOUT);
    prop2_final_kernel<<<(NN + 31) / 32, 256>>>(G0, R2, out);
}

// round 15
// speedup vs baseline: 2.5429x; 1.0432x over previous
#include <cuda_runtime.h>
#include <cuda_fp16.h>
#include <math.h>
#include <stdint.h>

#define KST 3
#define NN 30000
#define NE 300000
#define FIN 256
#define FHID 256
#define FOUT 64
#define KP1 (FIN / 2)    // 128
#define KPH (FHID / 2)   // 128
#define KPO (FOUT / 2)   // 32

// ---------------- scratch (device globals) ------------------------------------
__device__ __align__(16) uint32_t g_X[NN * KP1];
__device__ __align__(16) uint32_t g_H0[KST * NN * KPH];
__device__ __align__(16) uint32_t g_H1[KST * NN * KPH];
__device__ __align__(16) uint32_t g_R1[KST * NN * KPH];
__device__ __align__(16) uint32_t g_HM[NN * KPH];
__device__ __align__(16) uint32_t g_G0[KST * NN * KPO];
__device__ __align__(16) uint32_t g_G1[KST * NN * KPO];
__device__ __align__(16) uint32_t g_R2[KST * NN * KPO];
__device__ __align__(16) uint32_t g_W1C[KST * 512 * KP1];
__device__ __align__(16) uint32_t g_W1[KST * 256 * KPH];
__device__ __align__(16) uint32_t g_W2C[KST * 128 * KPH];
__device__ __align__(16) uint32_t g_W2[KST * 64 * KPO];
__device__ float g_dis[NN];
__device__ int g_cnt[NN];
__device__ int g_rowptr[NN + 1];
__device__ int g_cursor[NN];
__device__ int g_src[NE];
__device__ float g_nrm[NE];
__device__ int g_is64;
#define SCAN_NBLK 118
__device__ int g_bsum[SCAN_NBLK + 1];

// ---------------- helpers -----------------------------------------------------
__device__ __forceinline__ uint32_t pack_f16(float a, float b) {
    __half2 h = __floats2half2_rn(a, b);
    return *reinterpret_cast<uint32_t*>(&h);
}

__device__ __forceinline__ float2 h2f2(uint32_t u) {
    __half2 h = *reinterpret_cast<__half2*>(&u);
    return __half22float2(h);
}

__device__ __forceinline__ void mma_f16(float* c, const uint32_t* a, const uint32_t* bb) {
    asm volatile(
        "mma.sync.aligned.m16n8k16.row.col.f32.f16.f16.f32 "
        "{%0,%1,%2,%3}, {%4,%5,%6,%7}, {%8,%9}, {%0,%1,%2,%3};\n"
        : "+f"(c[0]), "+f"(c[1]), "+f"(c[2]), "+f"(c[3])
        : "r"(a[0]), "r"(a[1]), "r"(a[2]), "r"(a[3]), "r"(bb[0]), "r"(bb[1]));
}

__device__ __forceinline__ void ldsm4(uint32_t* r, uint32_t addr) {
    asm volatile("ldmatrix.sync.aligned.m8n8.x4.shared.b16 {%0,%1,%2,%3}, [%4];"
                 : "=r"(r[0]), "=r"(r[1]), "=r"(r[2]), "=r"(r[3])
                 : "r"(addr));
}

__device__ __forceinline__ void cpasync16(uint32_t dst, const uint32_t* src) {
    asm volatile("cp.async.cg.shared.global [%0], [%1], 16;" ::"r"(dst), "l"(src));
}

__device__ __forceinline__ void acc8(float* a, uint4 v, float w) {
    float2 f0 = h2f2(v.x), f1 = h2f2(v.y), f2 = h2f2(v.z), f3 = h2f2(v.w);
    a[0] += w * f0.x; a[1] += w * f0.y;
    a[2] += w * f1.x; a[3] += w * f1.y;
    a[4] += w * f2.x; a[5] += w * f2.y;
    a[6] += w * f3.x; a[7] += w * f3.y;
}

__device__ __forceinline__ void add8(float* a, uint4 v) {
    float2 f0 = h2f2(v.x), f1 = h2f2(v.y), f2 = h2f2(v.z), f3 = h2f2(v.w);
    a[0] += f0.x; a[1] += f0.y;
    a[2] += f1.x; a[3] += f1.y;
    a[4] += f2.x; a[5] += f2.y;
    a[6] += f3.x; a[7] += f3.y;
}

// ---------------- fused prep ---------------------------------------------------
__device__ __forceinline__ void wconv(const float* __restrict__ W, uint32_t* oh,
                                      int Kd, int N, int nOff, int outN, long idx) {
    int Kp = Kd / 2;
    int k = (int)(idx / ((long)N * Kp));
    int rem = (int)(idx % ((long)N * Kp));
    int n = rem / Kp;
    int kp = rem % Kp;
    const float* Wk = W + (long)k * Kd * N;
    float v0 = Wk[(long)(2 * kp) * N + n];
    float v1 = Wk[(long)(2 * kp + 1) * N + n];
    oh[((long)k * outN + nOff + n) * Kp + kp] = pack_f16(v0, v1);
}

#define CNT_X ((long)NN * KP1)
#define CNT_A (KST * 256 * 128)
#define CNT_B (KST * 64 * 128)
#define CNT_C (KST * 64 * 32)
#define CNT_PREP (CNT_X + 3 * CNT_A + 2 * CNT_B + CNT_C + NN)

__global__ void prep_kernel(const float* x, const float* iw1, const float* rw1,
                            const float* w1, const float* iw2, const float* rw2,
                            const float* w2, const int* ei_raw) {
    long id = blockIdx.x * 256L + threadIdx.x;
    if (id == 0) {
        int all_zero = 1;
        for (int j = 0; j < 128; j++)
            if (ei_raw[2 * j + 1] != 0) { all_zero = 0; break; }
        g_is64 = all_zero;
    }
    if (id < CNT_X) {
        float2 v = *(const float2*)(x + 2 * id);
        g_X[id] = pack_f16(v.x, v.y);
        return;
    }
    id -= CNT_X;
    if (id < CNT_A) { wconv(iw1, g_W1C, 256, 256, 0, 512, id); return; }
    id -= CNT_A;
    if (id < CNT_A) { wconv(rw1, g_W1C, 256, 256, 256, 512, id); return; }
    id -= CNT_A;
    if (id < CNT_A) { wconv(w1, g_W1, 256, 256, 0, 256, id); return; }
    id -= CNT_A;
    if (id < CNT_B) { wconv(iw2, g_W2C, 256, 64, 0, 128, id); return; }
    id -= CNT_B;
    if (id < CNT_B) { wconv(rw2, g_W2C, 256, 64, 64, 128, id); return; }
    id -= CNT_B;
    if (id < CNT_C) { wconv(w2, g_W2, 64, 64, 0, 64, id); return; }
    id -= CNT_C;
    if (id < NN) g_cnt[id] = 0;
}

// ---------------- CSR ----------------------------------------------------------
__device__ __forceinline__ int load_idx(const void* ei, long pos) {
    if (g_is64) return (int)((const long long*)ei)[pos];
    return ((const int*)ei)[pos];
}

__global__ void count_deg_kernel(const void* __restrict__ ei) {
    int e = blockIdx.x * blockDim.x + threadIdx.x;
    if (e < NE) {
        int c = load_idx(ei, (long)NE + e);
        if (c >= 0 && c < NN) atomicAdd(&g_cnt[c], 1);
    }
}

__global__ void scan1_kernel() {
    __shared__ int sh[256];
    int blk = blockIdx.x;
    int i = blk * 256 + threadIdx.x;
    int v = (i < NN) ? g_cnt[i] : 0;
    if (i < NN) g_dis[i] = (v > 0) ? rsqrtf((float)v) : 0.0f;
    sh[threadIdx.x] = v;
    __syncthreads();
    for (int d = 1; d < 256; d <<= 1) {
        int t = (threadIdx.x >= (unsigned)d) ? sh[threadIdx.x - d] : 0;
        __syncthreads();
        sh[threadIdx.x] += t;
        __syncthreads();
    }
    int incl = sh[threadIdx.x];
    if (i < NN) g_rowptr[i] = incl - v;
    if (threadIdx.x == 255) g_bsum[blk] = incl;
}

__global__ void scan3_kernel() {
    __shared__ int sh[128];
    int tid = threadIdx.x;
    if (tid < 128) sh[tid] = (tid < SCAN_NBLK) ? g_bsum[tid] : 0;
    __syncthreads();
    for (int d = 1; d < 128; d <<= 1) {
        int t = (tid < 128 && tid >= d) ? sh[tid - d] : 0;
        __syncthreads();
        if (tid < 128) sh[tid] += t;
        __syncthreads();
    }
    int prefix = sh[blockIdx.x] - g_bsum[blockIdx.x];
    int i = blockIdx.x * 256 + tid;
    if (i < NN) {
        int ex = g_rowptr[i] + prefix;
        g_rowptr[i] = ex;
        g_cursor[i] = ex;
    }
    if (blockIdx.x == 0 && tid == 0) g_rowptr[NN] = sh[SCAN_NBLK - 1];
}

__global__ void fill_csr_kernel(const void* __restrict__ ei) {
    int e = blockIdx.x * blockDim.x + threadIdx.x;
    if (e < NE) {
        int r = load_idx(ei, e);
        int c = load_idx(ei, (long)NE + e);
        if (r >= 0 && r < NN && c >= 0 && c < NN) {
            int pos = atomicAdd(&g_cursor[c], 1);
            if (pos >= 0 && pos < NE) {
                g_src[pos] = r;
                g_nrm[pos] = g_dis[r] * g_dis[c];
            }
        }
    }
}

// ---------------- fp16 tensor-core GEMM ----------------------------------------
#define APITCH 20
#define NSTAGE 4
#define A_PLANE 10240
#define B_OFF (NSTAGE * A_PLANE)

template <int BN>
__global__ void __launch_bounds__(256, (BN == 128) ? 2 : 3)
bgemm2(const uint32_t* __restrict__ A,
       const uint32_t* __restrict__ B,
       const float* __restrict__ bias,
       uint32_t* __restrict__ C0,
       uint32_t* __restrict__ C1,
       int M, int Ntot, int N1, int Kd) {
    constexpr int MT = (BN == 128) ? 4 : 2;
    constexpr int B_PLANE = BN * APITCH * 4;
    extern __shared__ uint32_t smem[];
    uint32_t smem_u = (uint32_t)__cvta_generic_to_shared(smem);
    int Kp = Kd >> 1;
    int bm = blockIdx.y * 128, bn = blockIdx.x * BN;
    int tid = threadIdx.x, warp = tid >> 5, lane = tid & 31;
    int g = lane >> 2, t = lane & 3;
    int wm, wn;
    if (BN == 128) { wm = warp >> 2; wn = warp & 3; }
    else           { wm = warp >> 1; wn = warp & 1; }

    int rowL = tid >> 2, segL = tid & 3;
    int gm0 = bm + rowL;       if (gm0 >= M) gm0 = M - 1;
    int gm1 = bm + rowL + 64;  if (gm1 >= M) gm1 = M - 1;
    const uint32_t* sA0 = A + (long)gm0 * Kp + segL * 4;
    const uint32_t* sA1 = A + (long)gm1 * Kp + segL * 4;
    const uint32_t* sB0 = B + (long)(bn + rowL) * Kp + segL * 4;
    const uint32_t* sB1 = sB0 + (long)64 * Kp;
    uint32_t dA0 = smem_u + (rowL * APITCH + segL * 4) * 4;
    uint32_t dA1 = dA0 + 64 * APITCH * 4;
    uint32_t dB0 = smem_u + B_OFF + (rowL * APITCH + segL * 4) * 4;
    uint32_t dB1 = dB0 + 64 * APITCH * 4;

    int rowA = ((lane >> 3) & 1) * 8 + (lane & 7);
    int segA = (lane >> 4) * 4;
    int rowB = ((lane >> 4) & 1) * 8 + (lane & 7);
    int segB = ((lane >> 3) & 1) * 4;
    uint32_t aOff0 = smem_u + ((wm * (MT * 16) + rowA) * APITCH + segA) * 4;
    uint32_t bOff0 = smem_u + B_OFF + ((wn * 32 + rowB) * APITCH + segB) * 4;
    uint32_t bOff1 = bOff0 + 16 * APITCH * 4;

    auto issue = [&](int kt) {
        uint32_t aD = kt * (uint32_t)A_PLANE;
        uint32_t bD = kt * (uint32_t)B_PLANE;
        cpasync16(dA0 + aD, sA0);
        cpasync16(dA1 + aD, sA1);
        cpasync16(dB0 + bD, sB0);
        if (BN == 128) cpasync16(dB1 + bD, sB1);
        sA0 += 16;
        sA1 += 16;
        sB0 += 16;
        if (BN == 128) sB1 += 16;
        asm volatile("cp.async.commit_group;" ::: "memory");
    };

    float acc[MT][4][4];
#pragma unroll
    for (int i = 0; i < MT; i++)
#pragma unroll
        for (int j = 0; j < 4; j++)
#pragma unroll
            for (int k = 0; k < 4; k++) acc[i][j][k] = 0.f;

    int NT = Kd / 32;
    for (int s = 0; s < 3 && s < NT; s++) issue(s & 3);
    for (int kt = 0; kt < NT; kt++) {
        int buf = kt & 3;
        int rem = NT - kt;
        if (rem >= 3) {
            asm volatile("cp.async.wait_group 2;" ::: "memory");
        } else if (rem == 2) {
            asm volatile("cp.async.wait_group 1;" ::: "memory");
        } else {
            asm volatile("cp.async.wait_group 0;" ::: "memory");
        }
        __syncthreads();
        if (kt + 3 < NT) issue((kt + 3) & 3);
        uint32_t aBase = buf * (uint32_t)A_PLANE;
        uint32_t bBase = buf * (uint32_t)B_PLANE;
#pragma unroll
        for (int ks = 0; ks < 2; ks++) {
            uint32_t ko = ks * 32;
            uint32_t af[MT][4], bf[4][2];
#pragma unroll
            for (int mt = 0; mt < MT; mt++)
                ldsm4(af[mt], aOff0 + mt * (16 * APITCH * 4) + aBase + ko);
            ldsm4(&bf[0][0], bOff0 + bBase + ko);
            ldsm4(&bf[2][0], bOff1 + bBase + ko);
#pragma unroll
            for (int mt = 0; mt < MT; mt++)
#pragma unroll
                for (int nt = 0; nt < 4; nt++) mma_f16(acc[mt][nt], af[mt], bf[nt]);
        }
    }

    int row0 = bm + wm * (MT * 16);
    int col0 = bn + wn * 32;
#pragma unroll
    for (int nt = 0; nt < 4; nt++) {
        int c = col0 + nt * 8 + 2 * t;
        bool out1 = (c >= N1);
        float bx = 0.f, by = 0.f;
        uint32_t* O;
        long pitch;
        int cc;
        if (out1) {
            if (bias) {
                bx = bias[c - N1];
                by = bias[c - N1 + 1];
            }
            O = C1;
            pitch = (Ntot - N1) >> 1;
            cc = (c - N1) >> 1;
        } else {
            O = C0;
            pitch = N1 >> 1;
            cc = c >> 1;
        }
#pragma unroll
        for (int mt = 0; mt < MT; mt++) {
            int r = row0 + mt * 16 + g;
            if (r < M)
                O[(long)r * pitch + cc] = pack_f16(acc[mt][nt][0] + bx, acc[mt][nt][1] + by);
            if (r + 8 < M)
                O[(long)(r + 8) * pitch + cc] =
                    pack_f16(acc[mt][nt][2] + bx, acc[mt][nt][3] + by);
        }
    }
}

#define GSMEM128 (NSTAGE * (A_PLANE + 128 * APITCH * 4))  // 81920
#define GSMEM64 (NSTAGE * (A_PLANE + 64 * APITCH * 4))    // 61440

// ---------------- propagation (uint4 gather, single stack) ----------------------
template <int F, bool RELU>
__global__ void prop_kernel(const uint32_t* __restrict__ H,
                            const uint32_t* __restrict__ R,
                            uint32_t* __restrict__ O) {
    constexpr int LANES = F / 8;
    constexpr int NPB = 256 / LANES;
    constexpr int PITCH = F / 2;
    int lane = threadIdx.x % LANES;
    int local = threadIdx.x / LANES;
    int n = blockIdx.x * NPB + local;
    if (n >= NN) return;
    int e0 = g_rowptr[n], e1 = g_rowptr[n + 1];
    float a[8] = {0.f, 0.f, 0.f, 0.f, 0.f, 0.f, 0.f, 0.f};
#pragma unroll 4
    for (int e = e0; e < e1; e++) {
        int s = g_src[e];
        float w = g_nrm[e];
        uint4 v = *(const uint4*)(H + (long)s * PITCH + lane * 4);
        acc8(a, v, w);
    }
    long off = (long)n * PITCH + lane * 4;
    add8(a, *(const uint4*)(R + off));
    if (RELU) {
#pragma unroll
        for (int j = 0; j < 8; j++) a[j] = fmaxf(a[j], 0.f);
    }
    uint4 o;
    o.x = pack_f16(a[0], a[1]);
    o.y = pack_f16(a[2], a[3]);
    o.z = pack_f16(a[4], a[5]);
    o.w = pack_f16(a[6], a[7]);
    *(uint4*)(O + off) = o;
}

// ---------------- fused 2nd conv1 prop + mean over stacks -----------------------
__global__ void prop1_mean_kernel(const uint32_t* __restrict__ H,
                                  const uint32_t* __restrict__ R) {
    int lane = threadIdx.x & 31;
    int local = threadIdx.x >> 5;
    int n = blockIdx.x * 8 + local;
    if (n >= NN) return;
    int e0 = g_rowptr[n], e1 = g_rowptr[n + 1];
    float m[8] = {0.f, 0.f, 0.f, 0.f, 0.f, 0.f, 0.f, 0.f};
#pragma unroll
    for (int k = 0; k < KST; k++) {
        long base = (long)k * NN * KPH;
        const uint32_t* Hk = H + base;
        float a[8] = {0.f, 0.f, 0.f, 0.f, 0.f, 0.f, 0.f, 0.f};
#pragma unroll 4
        for (int e = e0; e < e1; e++) {
            int s = g_src[e];
            float w = g_nrm[e];
            uint4 v = *(const uint4*)(Hk + (long)s * KPH + lane * 4);
            acc8(a, v, w);
        }
        add8(a, *(const uint4*)(R + base + (long)n * KPH + lane * 4));
#pragma unroll
        for (int j = 0; j < 8; j++) m[j] += fmaxf(a[j], 0.f);
    }
    uint4 o;
    o.x = pack_f16(m[0] * (1.f / 3.f), m[1] * (1.f / 3.f));
    o.y = pack_f16(m[2] * (1.f / 3.f), m[3] * (1.f / 3.f));
    o.z = pack_f16(m[4] * (1.f / 3.f), m[5] * (1.f / 3.f));
    o.w = pack_f16(m[6] * (1.f / 3.f), m[7] * (1.f / 3.f));
    *(uint4*)(g_HM + (long)n * KPH + lane * 4) = o;
}

// ---------------- fused 2nd conv2 prop + mean + log_softmax ---------------------
__global__ void prop2_final_kernel(const uint32_t* __restrict__ H,
                                   const uint32_t* __restrict__ R,
                                   float* __restrict__ out) {
    int lane = threadIdx.x & 7;
    int local = threadIdx.x >> 3;
    int n = blockIdx.x * 32 + local;
    if (n >= NN) return;
    int e0 = g_rowptr[n], e1 = g_rowptr[n + 1];
    float m[8] = {0.f, 0.f, 0.f, 0.f, 0.f, 0.f, 0.f, 0.f};
#pragma unroll
    for (int k = 0; k < KST; k++) {
        long base = (long)k * NN * KPO;
        const uint32_t* Hk = H + base;
        float a[8] = {0.f, 0.f, 0.f, 0.f, 0.f, 0.f, 0.f, 0.f};
#pragma unroll 4
        for (int e = e0; e < e1; e++) {
            int s = g_src[e];
            float w = g_nrm[e];
            uint4 v = *(const uint4*)(Hk + (long)s * KPO + lane * 4);
            acc8(a, v, w);
        }
        add8(a, *(const uint4*)(R + base + (long)n * KPO + lane * 4));
#pragma unroll
        for (int j = 0; j < 8; j++) m[j] += a[j];
    }
#pragma unroll
    for (int j = 0; j < 8; j++) m[j] *= (1.f / 3.f);
    float mx = m[0];
#pragma unroll
    for (int j = 1; j < 8; j++) mx = fmaxf(mx, m[j]);
#pragma unroll
    for (int d = 4; d; d >>= 1) mx = fmaxf(mx, __shfl_xor_sync(0xffffffffu, mx, d, 8));
    float s = 0.f;
#pragma unroll
    for (int j = 0; j < 8; j++) s += expf(m[j] - mx);
#pragma unroll
    for (int d = 4; d; d >>= 1) s += __shfl_xor_sync(0xffffffffu, s, d, 8);
    float lg = mx + logf(s);
    float* o = out + (long)n * FOUT + lane * 8;
#pragma unroll
    for (int j = 0; j < 8; j++) o[j] = m[j] - lg;
}

// ---------------- launch ---------------------------------------------------------
extern "C" void kernel_launch(void* const* d_in, const int* in_sizes, int n_in,
                              void* d_out, int out_size) {
    const float* x = (const float*)d_in[0];
    const void* ei = d_in[1];
    const float* init_w1 = (const float*)d_in[2];
    const float* w1 = (const float*)d_in[3];
    const float* root_w1 = (const float*)d_in[4];
    const float* bias1 = (const float*)d_in[5];
    const float* init_w2 = (const float*)d_in[6];
    const float* w2 = (const float*)d_in[7];
    const float* root_w2 = (const float*)d_in[8];
    const float* bias2 = (const float*)d_in[9];
    float* out = (float*)d_out;

    static bool init_done = false;
    static cudaStream_t sB, sC, sD;
    static cudaEvent_t ev0, evCSR, ev1, ev2, evM, ev1b, ev2b;
    if (!init_done) {
        cudaFuncSetAttribute(bgemm2<128>, cudaFuncAttributeMaxDynamicSharedMemorySize,
                             GSMEM128);
        cudaFuncSetAttribute(bgemm2<64>, cudaFuncAttributeMaxDynamicSharedMemorySize,
                             GSMEM64);
        cudaStreamCreateWithFlags(&sB, cudaStreamNonBlocking);
        cudaStreamCreateWithFlags(&sC, cudaStreamNonBlocking);
        cudaStreamCreateWithFlags(&sD, cudaStreamNonBlocking);
        cudaEventCreateWithFlags(&ev0, cudaEventDisableTiming);
        cudaEventCreateWithFlags(&evCSR, cudaEventDisableTiming);
        cudaEventCreateWithFlags(&ev1, cudaEventDisableTiming);
        cudaEventCreateWithFlags(&ev2, cudaEventDisableTiming);
        cudaEventCreateWithFlags(&evM, cudaEventDisableTiming);
        cudaEventCreateWithFlags(&ev1b, cudaEventDisableTiming);
        cudaEventCreateWithFlags(&ev2b, cudaEventDisableTiming);
        init_done = true;
    }

    uint32_t *X, *H0, *H1, *R1, *HM, *G0, *G1, *R2;
    uint32_t *W1C, *W1, *W2C, *W2;
    cudaGetSymbolAddress((void**)&X, g_X);
    cudaGetSymbolAddress((void**)&H0, g_H0);
    cudaGetSymbolAddress((void**)&H1, g_H1);
    cudaGetSymbolAddress((void**)&R1, g_R1);
    cudaGetSymbolAddress((void**)&HM, g_HM);
    cudaGetSymbolAddress((void**)&G0, g_G0);
    cudaGetSymbolAddress((void**)&G1, g_G1);
    cudaGetSymbolAddress((void**)&R2, g_R2);
    cudaGetSymbolAddress((void**)&W1C, g_W1C);
    cudaGetSymbolAddress((void**)&W1, g_W1);
    cudaGetSymbolAddress((void**)&W2C, g_W2C);
    cudaGetSymbolAddress((void**)&W2, g_W2);

    const int MY = (NN + 127) / 128;  // 235
    cudaStream_t stk[3] = {0, sB, sC};

    // prep on origin stream, then fork
    prep_kernel<<<(int)((CNT_PREP + 255) / 256), 256>>>(
        x, init_w1, root_w1, w1, init_w2, root_w2, w2, (const int*)ei);
    cudaEventRecord(ev0, 0);
    cudaStreamWaitEvent(sB, ev0, 0);
    cudaStreamWaitEvent(sC, ev0, 0);
    cudaStreamWaitEvent(sD, ev0, 0);

    // CSR chain on sD
    count_deg_kernel<<<(NE + 255) / 256, 256, 0, sD>>>(ei);
    scan1_kernel<<<SCAN_NBLK, 256, 0, sD>>>();
    scan3_kernel<<<SCAN_NBLK, 256, 0, sD>>>();
    fill_csr_kernel<<<(NE + 255) / 256, 256, 0, sD>>>(ei);
    cudaEventRecord(evCSR, sD);

    // per-stack conv1 chains: conv1c_k -> (wait CSR) -> prop1_k -> gw1_k
    for (int k = 0; k < KST; k++) {
        cudaStream_t s = stk[k];
        long oH = (long)k * NN * KPH;
        bgemm2<128><<<dim3(4, MY), 256, GSMEM128, s>>>(
            X, W1C + (long)k * 512 * KP1, bias1 + k * FHID, H0 + oH, R1 + oH,
            NN, 512, 256, FIN);
        cudaStreamWaitEvent(s, evCSR, 0);
        prop_kernel<FHID, true><<<(NN + 7) / 8, 256, 0, s>>>(H0 + oH, R1 + oH, H1 + oH);
        bgemm2<128><<<dim3(2, MY), 256, GSMEM128, s>>>(
            H1 + oH, W1 + (long)k * 256 * KPH, nullptr, H0 + oH, nullptr,
            NN, 256, 256, FHID);
    }
    cudaEventRecord(ev1, sB);
    cudaEventRecord(ev2, sC);
    cudaStreamWaitEvent(0, ev1, 0);
    cudaStreamWaitEvent(0, ev2, 0);

    // fused prop + mean (all stacks) on origin stream
    prop1_mean_kernel<<<(NN + 7) / 8, 256>>>(H0, R1);
    cudaEventRecord(evM, 0);
    cudaStreamWaitEvent(sB, evM, 0);
    cudaStreamWaitEvent(sC, evM, 0);

    // per-stack conv2 chains: gc2_k -> prop2_k -> gw2_k
    for (int k = 0; k < KST; k++) {
        cudaStream_t s = stk[k];
        long oG = (long)k * NN * KPO;
        bgemm2<128><<<dim3(1, MY), 256, GSMEM128, s>>>(
            HM, W2C + (long)k * 128 * KPH, bias2 + k * FOUT, G0 + oG, R2 + oG,
            NN, 128, 64, FHID);
        prop_kernel<FOUT, false><<<(NN + 31) / 32, 256, 0, s>>>(G0 + oG, R2 + oG, G1 + oG);
        bgemm2<64><<<dim3(1, MY), 256, GSMEM64, s>>>(
            G1 + oG, W2 + (long)k * 64 * KPO, nullptr, G0 + oG, nullptr,
            NN, 64, 64, FOUT);
    }
    cudaEventRecord(ev1b, sB);
    cudaEventRecord(ev2b, sC);
    cudaStreamWaitEvent(0, ev1b, 0);
    cudaStreamWaitEvent(0, ev2b, 0);

    // fused prop + mean + log_softmax (all stacks)
    prop2_final_kernel<<<(NN + 31) / 32, 256>>>(G0, R2, out);
}

// round 16
// speedup vs baseline: 2.7018x; 1.0625x over previous
#include <cuda_runtime.h>
#include <cuda_fp16.h>
#include <math.h>
#include <stdint.h>

#define KST 3
#define NN 30000
#define NE 300000
#define FIN 256
#define FHID 256
#define FOUT 64
#define KP1 (FIN / 2)    // 128
#define KPH (FHID / 2)   // 128
#define KPO (FOUT / 2)   // 32

// ---------------- scratch (device globals) ------------------------------------
__device__ __align__(16) uint32_t g_X[NN * KP1];
__device__ __align__(16) uint32_t g_H0[KST * NN * KPH];
__device__ __align__(16) uint32_t g_H1[KST * NN * KPH];
__device__ __align__(16) uint32_t g_R1[KST * NN * KPH];
__device__ __align__(16) uint32_t g_HM[NN * KPH];
__device__ __align__(16) uint32_t g_G0[KST * NN * KPO];
__device__ __align__(16) uint32_t g_G1[KST * NN * KPO];
__device__ __align__(16) uint32_t g_R2[KST * NN * KPO];
__device__ __align__(16) uint32_t g_W1C[KST * 512 * KP1];
__device__ __align__(16) uint32_t g_W1[KST * 256 * KPH];
__device__ __align__(16) uint32_t g_W2C[KST * 128 * KPH];
__device__ __align__(16) uint32_t g_W2[KST * 64 * KPO];
__device__ float g_dis[NN];
__device__ int g_cnt[NN];
__device__ int g_rowptr[NN + 1];
__device__ int g_cursor[NN];
__device__ int g_src[NE];
__device__ float g_nrm[NE];
__device__ int g_is64;
#define SCAN_NBLK 118
__device__ int g_bsum[SCAN_NBLK + 1];

// ---------------- helpers -----------------------------------------------------
__device__ __forceinline__ uint32_t pack_f16(float a, float b) {
    __half2 h = __floats2half2_rn(a, b);
    return *reinterpret_cast<uint32_t*>(&h);
}

__device__ __forceinline__ float2 h2f2(uint32_t u) {
    __half2 h = *reinterpret_cast<__half2*>(&u);
    return __half22float2(h);
}

__device__ __forceinline__ void mma_f16(float* c, const uint32_t* a, const uint32_t* bb) {
    asm volatile(
        "mma.sync.aligned.m16n8k16.row.col.f32.f16.f16.f32 "
        "{%0,%1,%2,%3}, {%4,%5,%6,%7}, {%8,%9}, {%0,%1,%2,%3};\n"
        : "+f"(c[0]), "+f"(c[1]), "+f"(c[2]), "+f"(c[3])
        : "r"(a[0]), "r"(a[1]), "r"(a[2]), "r"(a[3]), "r"(bb[0]), "r"(bb[1]));
}

__device__ __forceinline__ void ldsm4(uint32_t* r, uint32_t addr) {
    asm volatile("ldmatrix.sync.aligned.m8n8.x4.shared.b16 {%0,%1,%2,%3}, [%4];"
                 : "=r"(r[0]), "=r"(r[1]), "=r"(r[2]), "=r"(r[3])
                 : "r"(addr));
}

__device__ __forceinline__ void cpasync16(uint32_t dst, const uint32_t* src) {
    asm volatile("cp.async.cg.shared.global [%0], [%1], 16;" ::"r"(dst), "l"(src));
}

__device__ __forceinline__ void acc8(float* a, uint4 v, float w) {
    float2 f0 = h2f2(v.x), f1 = h2f2(v.y), f2 = h2f2(v.z), f3 = h2f2(v.w);
    a[0] += w * f0.x; a[1] += w * f0.y;
    a[2] += w * f1.x; a[3] += w * f1.y;
    a[4] += w * f2.x; a[5] += w * f2.y;
    a[6] += w * f3.x; a[7] += w * f3.y;
}

__device__ __forceinline__ void add8(float* a, uint4 v) {
    float2 f0 = h2f2(v.x), f1 = h2f2(v.y), f2 = h2f2(v.z), f3 = h2f2(v.w);
    a[0] += f0.x; a[1] += f0.y;
    a[2] += f1.x; a[3] += f1.y;
    a[4] += f2.x; a[5] += f2.y;
    a[6] += f3.x; a[7] += f3.y;
}

// ---------------- fused prep ---------------------------------------------------
__device__ __forceinline__ void wconv(const float* __restrict__ W, uint32_t* oh,
                                      int Kd, int N, int nOff, int outN, long idx) {
    int Kp = Kd / 2;
    int k = (int)(idx / ((long)N * Kp));
    int rem = (int)(idx % ((long)N * Kp));
    int n = rem / Kp;
    int kp = rem % Kp;
    const float* Wk = W + (long)k * Kd * N;
    float v0 = Wk[(long)(2 * kp) * N + n];
    float v1 = Wk[(long)(2 * kp + 1) * N + n];
    oh[((long)k * outN + nOff + n) * Kp + kp] = pack_f16(v0, v1);
}

#define CNT_X ((long)NN * KP1)
#define CNT_A (KST * 256 * 128)
#define CNT_B (KST * 64 * 128)
#define CNT_C (KST * 64 * 32)
#define CNT_PREP (CNT_X + 3 * CNT_A + 2 * CNT_B + CNT_C + NN)

__global__ void prep_kernel(const float* x, const float* iw1, const float* rw1,
                            const float* w1, const float* iw2, const float* rw2,
                            const float* w2, const int* ei_raw) {
    long id = blockIdx.x * 256L + threadIdx.x;
    if (id == 0) {
        int all_zero = 1;
        for (int j = 0; j < 128; j++)
            if (ei_raw[2 * j + 1] != 0) { all_zero = 0; break; }
        g_is64 = all_zero;
    }
    if (id < CNT_X) {
        float2 v = *(const float2*)(x + 2 * id);
        g_X[id] = pack_f16(v.x, v.y);
        return;
    }
    id -= CNT_X;
    if (id < CNT_A) { wconv(iw1, g_W1C, 256, 256, 0, 512, id); return; }
    id -= CNT_A;
    if (id < CNT_A) { wconv(rw1, g_W1C, 256, 256, 256, 512, id); return; }
    id -= CNT_A;
    if (id < CNT_A) { wconv(w1, g_W1, 256, 256, 0, 256, id); return; }
    id -= CNT_A;
    if (id < CNT_B) { wconv(iw2, g_W2C, 256, 64, 0, 128, id); return; }
    id -= CNT_B;
    if (id < CNT_B) { wconv(rw2, g_W2C, 256, 64, 64, 128, id); return; }
    id -= CNT_B;
    if (id < CNT_C) { wconv(w2, g_W2, 64, 64, 0, 64, id); return; }
    id -= CNT_C;
    if (id < NN) g_cnt[id] = 0;
}

// ---------------- CSR ----------------------------------------------------------
__device__ __forceinline__ int load_idx(const void* ei, long pos) {
    if (g_is64) return (int)((const long long*)ei)[pos];
    return ((const int*)ei)[pos];
}

__global__ void count_deg_kernel(const void* __restrict__ ei) {
    int e = blockIdx.x * blockDim.x + threadIdx.x;
    if (e < NE) {
        int c = load_idx(ei, (long)NE + e);
        if (c >= 0 && c < NN) atomicAdd(&g_cnt[c], 1);
    }
}

__global__ void scan1_kernel() {
    __shared__ int sh[256];
    int blk = blockIdx.x;
    int i = blk * 256 + threadIdx.x;
    int v = (i < NN) ? g_cnt[i] : 0;
    if (i < NN) g_dis[i] = (v > 0) ? rsqrtf((float)v) : 0.0f;
    sh[threadIdx.x] = v;
    __syncthreads();
    for (int d = 1; d < 256; d <<= 1) {
        int t = (threadIdx.x >= (unsigned)d) ? sh[threadIdx.x - d] : 0;
        __syncthreads();
        sh[threadIdx.x] += t;
        __syncthreads();
    }
    int incl = sh[threadIdx.x];
    if (i < NN) g_rowptr[i] = incl - v;
    if (threadIdx.x == 255) g_bsum[blk] = incl;
}

__global__ void scan3_kernel() {
    __shared__ int sh[128];
    int tid = threadIdx.x;
    if (tid < 128) sh[tid] = (tid < SCAN_NBLK) ? g_bsum[tid] : 0;
    __syncthreads();
    for (int d = 1; d < 128; d <<= 1) {
        int t = (tid < 128 && tid >= d) ? sh[tid - d] : 0;
        __syncthreads();
        if (tid < 128) sh[tid] += t;
        __syncthreads();
    }
    int prefix = sh[blockIdx.x] - g_bsum[blockIdx.x];
    int i = blockIdx.x * 256 + tid;
    if (i < NN) {
        int ex = g_rowptr[i] + prefix;
        g_rowptr[i] = ex;
        g_cursor[i] = ex;
    }
    if (blockIdx.x == 0 && tid == 0) g_rowptr[NN] = sh[SCAN_NBLK - 1];
}

__global__ void fill_csr_kernel(const void* __restrict__ ei) {
    int e = blockIdx.x * blockDim.x + threadIdx.x;
    if (e < NE) {
        int r = load_idx(ei, e);
        int c = load_idx(ei, (long)NE + e);
        if (r >= 0 && r < NN && c >= 0 && c < NN) {
            int pos = atomicAdd(&g_cursor[c], 1);
            if (pos >= 0 && pos < NE) {
                g_src[pos] = r;
                g_nrm[pos] = g_dis[r] * g_dis[c];
            }
        }
    }
}

// ---------------- fp16 tensor-core GEMM ----------------------------------------
#define APITCH 20
#define NSTAGE 4
#define A_PLANE 10240
#define B_OFF (NSTAGE * A_PLANE)

template <int BN>
__global__ void __launch_bounds__(256, (BN == 128) ? 2 : 3)
bgemm2(const uint32_t* __restrict__ A,
       const uint32_t* __restrict__ B,
       const float* __restrict__ bias,
       uint32_t* __restrict__ C0,
       uint32_t* __restrict__ C1,
       int M, int Ntot, int N1, int Kd) {
    constexpr int MT = (BN == 128) ? 4 : 2;
    constexpr int B_PLANE = BN * APITCH * 4;
    extern __shared__ uint32_t smem[];
    uint32_t smem_u = (uint32_t)__cvta_generic_to_shared(smem);
    int Kp = Kd >> 1;
    int bm = blockIdx.y * 128, bn = blockIdx.x * BN;
    int tid = threadIdx.x, warp = tid >> 5, lane = tid & 31;
    int g = lane >> 2, t = lane & 3;
    int wm, wn;
    if (BN == 128) { wm = warp >> 2; wn = warp & 3; }
    else           { wm = warp >> 1; wn = warp & 1; }

    int rowL = tid >> 2, segL = tid & 3;
    int gm0 = bm + rowL;       if (gm0 >= M) gm0 = M - 1;
    int gm1 = bm + rowL + 64;  if (gm1 >= M) gm1 = M - 1;
    const uint32_t* sA0 = A + (long)gm0 * Kp + segL * 4;
    const uint32_t* sA1 = A + (long)gm1 * Kp + segL * 4;
    const uint32_t* sB0 = B + (long)(bn + rowL) * Kp + segL * 4;
    const uint32_t* sB1 = sB0 + (long)64 * Kp;
    uint32_t dA0 = smem_u + (rowL * APITCH + segL * 4) * 4;
    uint32_t dA1 = dA0 + 64 * APITCH * 4;
    uint32_t dB0 = smem_u + B_OFF + (rowL * APITCH + segL * 4) * 4;
    uint32_t dB1 = dB0 + 64 * APITCH * 4;

    int rowA = ((lane >> 3) & 1) * 8 + (lane & 7);
    int segA = (lane >> 4) * 4;
    int rowB = ((lane >> 4) & 1) * 8 + (lane & 7);
    int segB = ((lane >> 3) & 1) * 4;
    uint32_t aOff0 = smem_u + ((wm * (MT * 16) + rowA) * APITCH + segA) * 4;
    uint32_t bOff0 = smem_u + B_OFF + ((wn * 32 + rowB) * APITCH + segB) * 4;
    uint32_t bOff1 = bOff0 + 16 * APITCH * 4;

    auto issue = [&](int kt) {
        uint32_t aD = kt * (uint32_t)A_PLANE;
        uint32_t bD = kt * (uint32_t)B_PLANE;
        cpasync16(dA0 + aD, sA0);
        cpasync16(dA1 + aD, sA1);
        cpasync16(dB0 + bD, sB0);
        if (BN == 128) cpasync16(dB1 + bD, sB1);
        sA0 += 16;
        sA1 += 16;
        sB0 += 16;
        if (BN == 128) sB1 += 16;
        asm volatile("cp.async.commit_group;" ::: "memory");
    };

    float acc[MT][4][4];
#pragma unroll
    for (int i = 0; i < MT; i++)
#pragma unroll
        for (int j = 0; j < 4; j++)
#pragma unroll
            for (int k = 0; k < 4; k++) acc[i][j][k] = 0.f;

    int NT = Kd / 32;
    for (int s = 0; s < 3 && s < NT; s++) issue(s & 3);
    for (int kt = 0; kt < NT; kt++) {
        int buf = kt & 3;
        int rem = NT - kt;
        if (rem >= 3) {
            asm volatile("cp.async.wait_group 2;" ::: "memory");
        } else if (rem == 2) {
            asm volatile("cp.async.wait_group 1;" ::: "memory");
        } else {
            asm volatile("cp.async.wait_group 0;" ::: "memory");
        }
        __syncthreads();
        if (kt + 3 < NT) issue((kt + 3) & 3);
        uint32_t aBase = buf * (uint32_t)A_PLANE;
        uint32_t bBase = buf * (uint32_t)B_PLANE;
#pragma unroll
        for (int ks = 0; ks < 2; ks++) {
            uint32_t ko = ks * 32;
            uint32_t af[MT][4], bf[4][2];
#pragma unroll
            for (int mt = 0; mt < MT; mt++)
                ldsm4(af[mt], aOff0 + mt * (16 * APITCH * 4) + aBase + ko);
            ldsm4(&bf[0][0], bOff0 + bBase + ko);
            ldsm4(&bf[2][0], bOff1 + bBase + ko);
#pragma unroll
            for (int mt = 0; mt < MT; mt++)
#pragma unroll
                for (int nt = 0; nt < 4; nt++) mma_f16(acc[mt][nt], af[mt], bf[nt]);
        }
    }

    int row0 = bm + wm * (MT * 16);
    int col0 = bn + wn * 32;
#pragma unroll
    for (int nt = 0; nt < 4; nt++) {
        int c = col0 + nt * 8 + 2 * t;
        bool out1 = (c >= N1);
        float bx = 0.f, by = 0.f;
        uint32_t* O;
        long pitch;
        int cc;
        if (out1) {
            if (bias) {
                bx = bias[c - N1];
                by = bias[c - N1 + 1];
            }
            O = C1;
            pitch = (Ntot - N1) >> 1;
            cc = (c - N1) >> 1;
        } else {
            O = C0;
            pitch = N1 >> 1;
            cc = c >> 1;
        }
#pragma unroll
        for (int mt = 0; mt < MT; mt++) {
            int r = row0 + mt * 16 + g;
            if (r < M)
                O[(long)r * pitch + cc] = pack_f16(acc[mt][nt][0] + bx, acc[mt][nt][1] + by);
            if (r + 8 < M)
                O[(long)(r + 8) * pitch + cc] =
                    pack_f16(acc[mt][nt][2] + bx, acc[mt][nt][3] + by);
        }
    }
}

#define GSMEM128 (NSTAGE * (A_PLANE + 128 * APITCH * 4))  // 81920
#define GSMEM64 (NSTAGE * (A_PLANE + 64 * APITCH * 4))    // 61440

// ---------------- propagation (uint4 gather, 2-edge interleave) -----------------
template <int F, bool RELU>
__global__ void prop_kernel(const uint32_t* __restrict__ H,
                            const uint32_t* __restrict__ R,
                            uint32_t* __restrict__ O) {
    constexpr int LANES = F / 8;
    constexpr int NPB = 256 / LANES;
    constexpr int PITCH = F / 2;
    int lane = threadIdx.x % LANES;
    int local = threadIdx.x / LANES;
    int n = blockIdx.x * NPB + local;
    if (n >= NN) return;
    int e0 = g_rowptr[n], e1 = g_rowptr[n + 1];
    float a[8] = {0.f, 0.f, 0.f, 0.f, 0.f, 0.f, 0.f, 0.f};
    int e = e0;
#pragma unroll 2
    for (; e + 1 < e1; e += 2) {
        int s0 = g_src[e], s1 = g_src[e + 1];
        float w0 = g_nrm[e], w1 = g_nrm[e + 1];
        uint4 v0 = *(const uint4*)(H + (long)s0 * PITCH + lane * 4);
        uint4 v1 = *(const uint4*)(H + (long)s1 * PITCH + lane * 4);
        acc8(a, v0, w0);
        acc8(a, v1, w1);
    }
    if (e < e1) {
        int s = g_src[e];
        float w = g_nrm[e];
        uint4 v = *(const uint4*)(H + (long)s * PITCH + lane * 4);
        acc8(a, v, w);
    }
    long off = (long)n * PITCH + lane * 4;
    add8(a, *(const uint4*)(R + off));
    if (RELU) {
#pragma unroll
        for (int j = 0; j < 8; j++) a[j] = fmaxf(a[j], 0.f);
    }
    uint4 o;
    o.x = pack_f16(a[0], a[1]);
    o.y = pack_f16(a[2], a[3]);
    o.z = pack_f16(a[4], a[5]);
    o.w = pack_f16(a[6], a[7]);
    *(uint4*)(O + off) = o;
}

// ---------------- fused 2nd conv1 prop + mean (edge-outer, 3x MLP) --------------
__global__ void prop1_mean_kernel(const uint32_t* __restrict__ H,
                                  const uint32_t* __restrict__ R) {
    int lane = threadIdx.x & 31;
    int local = threadIdx.x >> 5;
    int n = blockIdx.x * 8 + local;
    if (n >= NN) return;
    int e0 = g_rowptr[n], e1 = g_rowptr[n + 1];
    float a[KST][8];
#pragma unroll
    for (int k = 0; k < KST; k++)
#pragma unroll
        for (int j = 0; j < 8; j++) a[k][j] = 0.f;
#pragma unroll 2
    for (int e = e0; e < e1; e++) {
        int s = g_src[e];
        float w = g_nrm[e];
        long so = (long)s * KPH + lane * 4;
        uint4 v0 = *(const uint4*)(H + so);
        uint4 v1 = *(const uint4*)(H + (long)NN * KPH + so);
        uint4 v2 = *(const uint4*)(H + 2L * NN * KPH + so);
        acc8(a[0], v0, w);
        acc8(a[1], v1, w);
        acc8(a[2], v2, w);
    }
    long ro = (long)n * KPH + lane * 4;
    float m[8] = {0.f, 0.f, 0.f, 0.f, 0.f, 0.f, 0.f, 0.f};
#pragma unroll
    for (int k = 0; k < KST; k++) {
        add8(a[k], *(const uint4*)(R + (long)k * NN * KPH + ro));
#pragma unroll
        for (int j = 0; j < 8; j++) m[j] += fmaxf(a[k][j], 0.f);
    }
    uint4 o;
    o.x = pack_f16(m[0] * (1.f / 3.f), m[1] * (1.f / 3.f));
    o.y = pack_f16(m[2] * (1.f / 3.f), m[3] * (1.f / 3.f));
    o.z = pack_f16(m[4] * (1.f / 3.f), m[5] * (1.f / 3.f));
    o.w = pack_f16(m[6] * (1.f / 3.f), m[7] * (1.f / 3.f));
    *(uint4*)(g_HM + ro) = o;
}

// ---------------- fused 2nd conv2 prop + mean + log_softmax (edge-outer) --------
__global__ void prop2_final_kernel(const uint32_t* __restrict__ H,
                                   const uint32_t* __restrict__ R,
                                   float* __restrict__ out) {
    int lane = threadIdx.x & 7;
    int local = threadIdx.x >> 3;
    int n = blockIdx.x * 32 + local;
    if (n >= NN) return;
    int e0 = g_rowptr[n], e1 = g_rowptr[n + 1];
    float a[KST][8];
#pragma unroll
    for (int k = 0; k < KST; k++)
#pragma unroll
        for (int j = 0; j < 8; j++) a[k][j] = 0.f;
#pragma unroll 2
    for (int e = e0; e < e1; e++) {
        int s = g_src[e];
        float w = g_nrm[e];
        long so = (long)s * KPO + lane * 4;
        uint4 v0 = *(const uint4*)(H + so);
        uint4 v1 = *(const uint4*)(H + (long)NN * KPO + so);
        uint4 v2 = *(const uint4*)(H + 2L * NN * KPO + so);
        acc8(a[0], v0, w);
        acc8(a[1], v1, w);
        acc8(a[2], v2, w);
    }
    long ro = (long)n * KPO + lane * 4;
    float m[8] = {0.f, 0.f, 0.f, 0.f, 0.f, 0.f, 0.f, 0.f};
#pragma unroll
    for (int k = 0; k < KST; k++) {
        add8(a[k], *(const uint4*)(R + (long)k * NN * KPO + ro));
#pragma unroll
        for (int j = 0; j < 8; j++) m[j] += a[k][j];
    }
#pragma unroll
    for (int j = 0; j < 8; j++) m[j] *= (1.f / 3.f);
    float mx = m[0];
#pragma unroll
    for (int j = 1; j < 8; j++) mx = fmaxf(mx, m[j]);
#pragma unroll
    for (int d = 4; d; d >>= 1) mx = fmaxf(mx, __shfl_xor_sync(0xffffffffu, mx, d, 8));
    float s = 0.f;
#pragma unroll
    for (int j = 0; j < 8; j++) s += expf(m[j] - mx);
#pragma unroll
    for (int d = 4; d; d >>= 1) s += __shfl_xor_sync(0xffffffffu, s, d, 8);
    float lg = mx + logf(s);
    float* o = out + (long)n * FOUT + lane * 8;
#pragma unroll
    for (int j = 0; j < 8; j++) o[j] = m[j] - lg;
}

// ---------------- launch ---------------------------------------------------------
extern "C" void kernel_launch(void* const* d_in, const int* in_sizes, int n_in,
                              void* d_out, int out_size) {
    const float* x = (const float*)d_in[0];
    const void* ei = d_in[1];
    const float* init_w1 = (const float*)d_in[2];
    const float* w1 = (const float*)d_in[3];
    const float* root_w1 = (const float*)d_in[4];
    const float* bias1 = (const float*)d_in[5];
    const float* init_w2 = (const float*)d_in[6];
    const float* w2 = (const float*)d_in[7];
    const float* root_w2 = (const float*)d_in[8];
    const float* bias2 = (const float*)d_in[9];
    float* out = (float*)d_out;

    static bool init_done = false;
    static cudaStream_t sB, sC, sD;
    static cudaEvent_t ev0, evCSR, ev1, ev2, evM, ev1b, ev2b;
    if (!init_done) {
        cudaFuncSetAttribute(bgemm2<128>, cudaFuncAttributeMaxDynamicSharedMemorySize,
                             GSMEM128);
        cudaFuncSetAttribute(bgemm2<64>, cudaFuncAttributeMaxDynamicSharedMemorySize,
                             GSMEM64);
        cudaStreamCreateWithFlags(&sB, cudaStreamNonBlocking);
        cudaStreamCreateWithFlags(&sC, cudaStreamNonBlocking);
        cudaStreamCreateWithFlags(&sD, cudaStreamNonBlocking);
        cudaEventCreateWithFlags(&ev0, cudaEventDisableTiming);
        cudaEventCreateWithFlags(&evCSR, cudaEventDisableTiming);
        cudaEventCreateWithFlags(&ev1, cudaEventDisableTiming);
        cudaEventCreateWithFlags(&ev2, cudaEventDisableTiming);
        cudaEventCreateWithFlags(&evM, cudaEventDisableTiming);
        cudaEventCreateWithFlags(&ev1b, cudaEventDisableTiming);
        cudaEventCreateWithFlags(&ev2b, cudaEventDisableTiming);
        init_done = true;
    }

    uint32_t *X, *H0, *H1, *R1, *HM, *G0, *G1, *R2;
    uint32_t *W1C, *W1, *W2C, *W2;
    cudaGetSymbolAddress((void**)&X, g_X);
    cudaGetSymbolAddress((void**)&H0, g_H0);
    cudaGetSymbolAddress((void**)&H1, g_H1);
    cudaGetSymbolAddress((void**)&R1, g_R1);
    cudaGetSymbolAddress((void**)&HM, g_HM);
    cudaGetSymbolAddress((void**)&G0, g_G0);
    cudaGetSymbolAddress((void**)&G1, g_G1);
    cudaGetSymbolAddress((void**)&R2, g_R2);
    cudaGetSymbolAddress((void**)&W1C, g_W1C);
    cudaGetSymbolAddress((void**)&W1, g_W1);
    cudaGetSymbolAddress((void**)&W2C, g_W2C);
    cudaGetSymbolAddress((void**)&W2, g_W2);

    const int MY = (NN + 127) / 128;  // 235
    cudaStream_t stk[3] = {0, sB, sC};

    prep_kernel<<<(int)((CNT_PREP + 255) / 256), 256>>>(
        x, init_w1, root_w1, w1, init_w2, root_w2, w2, (const int*)ei);
    cudaEventRecord(ev0, 0);
    cudaStreamWaitEvent(sB, ev0, 0);
    cudaStreamWaitEvent(sC, ev0, 0);
    cudaStreamWaitEvent(sD, ev0, 0);

    // CSR chain on sD
    count_deg_kernel<<<(NE + 255) / 256, 256, 0, sD>>>(ei);
    scan1_kernel<<<SCAN_NBLK, 256, 0, sD>>>();
    scan3_kernel<<<SCAN_NBLK, 256, 0, sD>>>();
    fill_csr_kernel<<<(NE + 255) / 256, 256, 0, sD>>>(ei);
    cudaEventRecord(evCSR, sD);

    // per-stack conv1 chains
    for (int k = 0; k < KST; k++) {
        cudaStream_t s = stk[k];
        long oH = (long)k * NN * KPH;
        bgemm2<128><<<dim3(4, MY), 256, GSMEM128, s>>>(
            X, W1C + (long)k * 512 * KP1, bias1 + k * FHID, H0 + oH, R1 + oH,
            NN, 512, 256, FIN);
        cudaStreamWaitEvent(s, evCSR, 0);
        prop_kernel<FHID, true><<<(NN + 7) / 8, 256, 0, s>>>(H0 + oH, R1 + oH, H1 + oH);
        bgemm2<128><<<dim3(2, MY), 256, GSMEM128, s>>>(
            H1 + oH, W1 + (long)k * 256 * KPH, nullptr, H0 + oH, nullptr,
            NN, 256, 256, FHID);
    }
    cudaEventRecord(ev1, sB);
    cudaEventRecord(ev2, sC);
    cudaStreamWaitEvent(0, ev1, 0);
    cudaStreamWaitEvent(0, ev2, 0);

    prop1_mean_kernel<<<(NN + 7) / 8, 256>>>(H0, R1);
    cudaEventRecord(evM, 0);
    cudaStreamWaitEvent(sB, evM, 0);
    cudaStreamWaitEvent(sC, evM, 0);

    // per-stack conv2 chains
    for (int k = 0; k < KST; k++) {
        cudaStream_t s = stk[k];
        long oG = (long)k * NN * KPO;
        bgemm2<128><<<dim3(1, MY), 256, GSMEM128, s>>>(
            HM, W2C + (long)k * 128 * KPH, bias2 + k * FOUT, G0 + oG, R2 + oG,
            NN, 128, 64, FHID);
        prop_kernel<FOUT, false><<<(NN + 31) / 32, 256, 0, s>>>(G0 + oG, R2 + oG, G1 + oG);
        bgemm2<64><<<dim3(1, MY), 256, GSMEM64, s>>>(
            G1 + oG, W2 + (long)k * 64 * KPO, nullptr, G0 + oG, nullptr,
            NN, 64, 64, FOUT);
    }
    cudaEventRecord(ev1b, sB);
    cudaEventRecord(ev2b, sC);
    cudaStreamWaitEvent(0, ev1b, 0);
    cudaStreamWaitEvent(0, ev2b, 0);

    prop2_final_kernel<<<(NN + 31) / 32, 256>>>(G0, R2, out);
}